// round 8
// baseline (speedup 1.0000x reference)
#include <cuda_runtime.h>
#include <cstdint>

#define Bb 8
#define Nn 1024
#define Cc 768
#define Hh 12
#define Dd 64
#define BHh 96
#define Mm 8192
#define SCALEF 0.125f
#define EPSF 1e-8f
#define LNEPS 1e-5f

// ---------------- scratch (device globals) ----------------
__device__ float g_q[2][(size_t)BHh*Nn*Dd];
__device__ float g_k[2][(size_t)BHh*Nn*Dd];
__device__ float g_v[2][(size_t)BHh*Nn*Dd];
__device__ float g_ao[2][(size_t)Mm*Cc];
__device__ float g_pr[2][(size_t)Mm*Cc];
__device__ float g_wt[2][(size_t)3*Cc*Cc];    // W_qkv^T
__device__ float g_wpt[2][(size_t)Cc*Cc];     // W_proj^T
__device__ float g_xr[(size_t)Mm*Cc];         // tf32-rounded x

// ---------------- helpers ----------------
__device__ __forceinline__ uint32_t smem_u32(const void* p) {
    uint32_t a;
    asm("{ .reg .u64 t; cvta.to.shared.u64 t, %1; cvt.u32.u64 %0, t; }" : "=r"(a) : "l"(p));
    return a;
}
__device__ __forceinline__ float rna(float x) {
    uint32_t u;
    asm("cvt.rna.tf32.f32 %0, %1;" : "=r"(u) : "f"(x));
    return __uint_as_float(u);
}
__device__ __forceinline__ void ldsm4(uint32_t& d0, uint32_t& d1, uint32_t& d2, uint32_t& d3, uint32_t a) {
    asm volatile("ldmatrix.sync.aligned.m8n8.x4.shared.b16 {%0,%1,%2,%3}, [%4];"
                 : "=r"(d0), "=r"(d1), "=r"(d2), "=r"(d3) : "r"(a));
}
__device__ __forceinline__ void mma8(float* c, uint32_t a0, uint32_t a1, uint32_t a2, uint32_t a3,
                                     uint32_t b0, uint32_t b1) {
    asm volatile("mma.sync.aligned.m16n8k8.row.col.f32.tf32.tf32.f32 "
                 "{%0,%1,%2,%3},{%4,%5,%6,%7},{%8,%9},{%0,%1,%2,%3};"
                 : "+f"(c[0]), "+f"(c[1]), "+f"(c[2]), "+f"(c[3])
                 : "r"(a0), "r"(a1), "r"(a2), "r"(a3), "r"(b0), "r"(b1));
}
#define CPA16(d, s) asm volatile("cp.async.cg.shared.global [%0], [%1], 16;" :: "r"(d), "l"(s))
#define CPA4(d, s)  asm volatile("cp.async.ca.shared.global [%0], [%1], 4;"  :: "r"(d), "l"(s))
#define CPCOMMIT()  asm volatile("cp.async.commit_group;" ::: "memory")
#define CPWAIT(n)   asm volatile("cp.async.wait_group %0;" :: "n"(n) : "memory")

// =============== shared tf32-mma mainloop: C[128x128] = A * B^T, K=768 ======
__device__ __forceinline__ void gemm_main_768(const float* __restrict__ A,
                                              const float* __restrict__ Bt,
                                              int by, int bx, uint32_t smb,
                                              float acc[2][8][4]) {
    const int tid = threadIdx.x, lane = tid & 31, wid = tid >> 5;
    const int wm = wid >> 1, wn = wid & 1;
    uint32_t dA[4], dB[4];
    const float* sA[4];
    const float* sB[4];
#pragma unroll
    for (int j = 0; j < 4; j++) {
        int e = tid + 256 * j;
        int m = e >> 3, kg = e & 7;
        uint32_t sw = (uint32_t)(m * 128 + ((kg * 16) ^ ((m & 7) << 4)));
        dA[j] = smb + sw;
        dB[j] = smb + 32768u + sw;
        sA[j] = A + (size_t)(by + m) * 768 + kg * 4;
        sB[j] = Bt + (size_t)(bx + m) * 768 + kg * 4;
    }
#pragma unroll
    for (int i = 0; i < 2; i++)
#pragma unroll
        for (int n = 0; n < 8; n++)
#pragma unroll
            for (int c = 0; c < 4; c++) acc[i][n][c] = 0.0f;

#pragma unroll
    for (int j = 0; j < 4; j++) { CPA16(dA[j], sA[j]); CPA16(dB[j], sB[j]); }
    CPCOMMIT();

    const int arow0 = wm * 32 + ((lane >> 3) & 1) * 8 + (lane & 7);
    const int brow0 = wn * 64 + ((lane >> 4) & 1) * 8 + (lane & 7);
    const int axr = (lane & 7) << 4;
    const int agsel = lane >> 4, bgsel = (lane >> 3) & 1;

    for (int it = 0; it < 24; ++it) {
        if (it + 1 < 24) {
            int kc = (it + 1) * 32;
            uint32_t ob = ((it + 1) & 1) ? 16384u : 0u;
#pragma unroll
            for (int j = 0; j < 4; j++) { CPA16(dA[j] + ob, sA[j] + kc); CPA16(dB[j] + ob, sB[j] + kc); }
        }
        CPCOMMIT();
        CPWAIT(1);
        __syncthreads();
        uint32_t Ab = smb + ((it & 1) ? 16384u : 0u);
        uint32_t Bbf = smb + 32768u + ((it & 1) ? 16384u : 0u);
#pragma unroll
        for (int ks = 0; ks < 4; ks++) {
            uint32_t a[2][4];
#pragma unroll
            for (int mt = 0; mt < 2; mt++) {
                int r = arow0 + mt * 16;
                ldsm4(a[mt][0], a[mt][1], a[mt][2], a[mt][3],
                      Ab + r * 128 + (((ks * 2 + agsel) * 16) ^ axr));
            }
#pragma unroll
            for (int j2 = 0; j2 < 4; j2++) {
                int r = brow0 + j2 * 16;
                uint32_t b0, b1, b2, b3;
                ldsm4(b0, b1, b2, b3, Bbf + r * 128 + (((ks * 2 + bgsel) * 16) ^ axr));
#pragma unroll
                for (int mt = 0; mt < 2; mt++) {
                    mma8(acc[mt][2 * j2],     a[mt][0], a[mt][1], a[mt][2], a[mt][3], b0, b1);
                    mma8(acc[mt][2 * j2 + 1], a[mt][0], a[mt][1], a[mt][2], a[mt][3], b2, b3);
                }
            }
        }
        __syncthreads();
    }
}

// ================= 1) qkv GEMM (both branches via z) + scatter ==============
__global__ __launch_bounds__(256, 2) void k_qkv_mma(const float* __restrict__ X,
                                                    const float* __restrict__ Wt0,
                                                    const float* __restrict__ Wt1) {
    extern __shared__ char smch[];
    uint32_t smb = smem_u32(smch);
    int br = blockIdx.z;
    const float* Wt = br ? Wt1 : Wt0;
    int bx = blockIdx.x * 128, by = blockIdx.y * 128;
    float acc[2][8][4];
    gemm_main_768(X, Wt, by, bx, smb, acc);

    int lane = threadIdx.x & 31, wid = threadIdx.x >> 5;
    int wm = wid >> 1, wn = wid & 1, g = lane >> 2, tig = lane & 3;
    int colbase = bx + wn * 64;
    int seg = colbase >> 6;
    int three = seg / 12, hseg = seg - three * 12;
    float* base3 = (three == 0) ? g_q[br] : ((three == 1) ? g_k[br] : g_v[br]);
#pragma unroll
    for (int mt = 0; mt < 2; mt++) {
        int m1 = by + wm * 32 + mt * 16 + g;
        int b1 = m1 >> 10, n1 = m1 & 1023;
        float* p1 = base3 + (((size_t)(b1 * 12 + hseg)) * 1024 + n1) * 64 + 2 * tig;
        float* p2 = p1 + (size_t)8 * 64;
#pragma unroll
        for (int nt = 0; nt < 8; nt++) {
            *(float2*)(p1 + nt * 8) = make_float2(rna(acc[mt][nt][0]), rna(acc[mt][nt][1]));
            *(float2*)(p2 + nt * 8) = make_float2(rna(acc[mt][nt][2]), rna(acc[mt][nt][3]));
        }
    }
}

// ================= 2) proj GEMM + bias (both branches via z) ================
__global__ __launch_bounds__(256, 2) void k_proj_mma(const float* __restrict__ Wt0,
                                                     const float* __restrict__ Wt1,
                                                     const float* __restrict__ bias0,
                                                     const float* __restrict__ bias1) {
    extern __shared__ char smch[];
    uint32_t smb = smem_u32(smch);
    int br = blockIdx.z;
    const float* Wt = br ? Wt1 : Wt0;
    const float* bias = br ? bias1 : bias0;
    int bx = blockIdx.x * 128, by = blockIdx.y * 128;
    float acc[2][8][4];
    gemm_main_768(g_ao[br], Wt, by, bx, smb, acc);

    int lane = threadIdx.x & 31, wid = threadIdx.x >> 5;
    int wm = wid >> 1, wn = wid & 1, g = lane >> 2, tig = lane & 3;
    int colbase = bx + wn * 64;
#pragma unroll
    for (int mt = 0; mt < 2; mt++) {
        int m1 = by + wm * 32 + mt * 16 + g;
        float* p1 = g_pr[br] + (size_t)m1 * 768 + colbase + 2 * tig;
        float* p2 = p1 + (size_t)8 * 768;
#pragma unroll
        for (int nt = 0; nt < 8; nt++) {
            float2 bv = *(const float2*)(bias + colbase + nt * 8 + 2 * tig);
            *(float2*)(p1 + nt * 8) = make_float2(acc[mt][nt][0] + bv.x, acc[mt][nt][1] + bv.y);
            *(float2*)(p2 + nt * 8) = make_float2(acc[mt][nt][2] + bv.x, acc[mt][nt][3] + bv.y);
        }
    }
}

// ====== 3) FUSED attention, 64-row q tiles, E aliased onto K buffers ========
// smem: Q0 @0 (16K) Q1 @16384 | K0/E0 @32768 (16K) K1/E1 @49152 |
//       V0 @65536 (17408, 64 d-rows x 272B) V1 @82944  -> total 100352, occ 2
#define ASQ1 16384u
#define ASK0 32768u
#define ASK1 49152u
#define ASV0 65536u
#define ASV1 82944u
#define A_SMEM 100352

__device__ __forceinline__ void issue_kv64(uint32_t smb, uint32_t sko, uint32_t svo,
                                           const float* __restrict__ Kg,
                                           const float* __restrict__ Vg,
                                           int j0, int tid) {
#pragma unroll
    for (int jj = 0; jj < 4; jj++) {
        int e = tid + 256 * jj;
        int n = e >> 4, kg = e & 15;
        uint32_t dst = smb + sko + n * 256 + ((kg * 16) ^ ((n & 7) << 4));
        CPA16(dst, Kg + (size_t)(j0 + n) * 64 + kg * 4);
    }
    int vn = tid & 63, vkq = tid >> 6;   // vkq 0..3
    uint32_t vb = smb + svo + vn * 272;
    const float* vs = Vg + (size_t)j0 * 64 + vn;
#pragma unroll
    for (int jj = 0; jj < 16; jj++) {
        int k = vkq * 16 + jj;
        CPA4(vb + k * 4, vs + (size_t)k * 64);
    }
}

__global__ __launch_bounds__(256, 2) void k_attn(const float* __restrict__ temp_ptr) {
    extern __shared__ char smch[];
    uint32_t smb = smem_u32(smch);
    const int head = blockIdx.y, i0 = blockIdx.x * 64;
    const int tid = threadIdx.x, lane = tid & 31, wid = tid >> 5;
    const int wm = wid >> 1, wn = wid & 1;
    const float* Qg0 = g_q[0] + (size_t)head * 65536;
    const float* Qg1 = g_q[1] + (size_t)head * 65536;
    const float* Kg0 = g_k[0] + (size_t)head * 65536;
    const float* Kg1 = g_k[1] + (size_t)head * 65536;
    const float* Vg0 = g_v[0] + (size_t)head * 65536;
    const float* Vg1 = g_v[1] + (size_t)head * 65536;

    // persistent Q (both branches), group 0
#pragma unroll
    for (int j = 0; j < 8; j++) {
        int e = tid + 256 * j;
        int br = e >> 10, r = e & 1023;
        int n = r >> 4, kg = r & 15;
        uint32_t dst = smb + (uint32_t)(br ? ASQ1 : 0u) + n * 256 + ((kg * 16) ^ ((n & 7) << 4));
        const float* src = (br ? Qg1 : Qg0) + (size_t)(i0 + n) * 64 + kg * 4;
        CPA16(dst, src);
    }
    issue_kv64(smb, ASK0, ASV0, Kg0, Vg0, 0, tid);
    issue_kv64(smb, ASK1, ASV1, Kg1, Vg1, 0, tid);
    CPCOMMIT();

    // fragment indices: warp = (wm: 16-row group of 64, wn: 32-col half)
    const int arow = wm * 16 + ((lane >> 3) & 1) * 8 + (lane & 7);
    const int brow0 = wn * 32 + ((lane >> 4) & 1) * 8 + (lane & 7);
    const int axr = (lane & 7) << 4;
    const int agsel = lane >> 4, bgsel = (lane >> 3) & 1;
    const int g = lane >> 2, tig = lane & 3;
    const int r1 = wm * 16 + g, r2 = r1 + 8;
    const int sw1 = (r1 & 7) << 4, sw2 = (r2 & 7) << 4;
    const int ecol = wn * 128 + (tig & 1) * 8;
    char* e1b0 = smch + ASK0 + r1 * 256 + ecol;
    char* e2b0 = smch + ASK0 + r2 * 256 + ecol;
    char* e1b1 = smch + ASK1 + r1 * 256 + ecol;
    char* e2b1 = smch + ASK1 + r2 * 256 + ecol;
    const int tg2 = tig >> 1;

    float O0[4][4], O1[4][4];
#pragma unroll
    for (int n = 0; n < 4; n++)
#pragma unroll
        for (int c = 0; c < 4; c++) { O0[n][c] = 0.f; O1[n][c] = 0.f; }
    float z0[2] = {0.f, 0.f}, z1[2] = {0.f, 0.f}, dt[2] = {0.f, 0.f};

    for (int jt = 0; jt < 16; jt++) {
        CPWAIT(0);
        __syncthreads();
        // ---------- QK branch 0 ----------
        float acc[4][4];
#pragma unroll
        for (int n = 0; n < 4; n++)
#pragma unroll
            for (int c = 0; c < 4; c++) acc[n][c] = 0.f;
#pragma unroll
        for (int ks = 0; ks < 8; ks++) {
            uint32_t a0, a1, a2, a3;
            ldsm4(a0, a1, a2, a3, smb + arow * 256 + (((ks * 2 + agsel) * 16) ^ axr));
#pragma unroll
            for (int j2 = 0; j2 < 2; j2++) {
                uint32_t b0, b1, b2, b3;
                ldsm4(b0, b1, b2, b3, smb + ASK0 + (brow0 + j2 * 16) * 256 + (((ks * 2 + bgsel) * 16) ^ axr));
                mma8(acc[2 * j2],     a0, a1, a2, a3, b0, b1);
                mma8(acc[2 * j2 + 1], a0, a1, a2, a3, b2, b3);
            }
        }
        __syncthreads();   // all warps done reading K0 -> overwrite with E0
#pragma unroll
        for (int nt = 0; nt < 4; nt++) {
            float ea = rna(__expf(fminf(fmaxf(acc[nt][0] * SCALEF, -20.f), 20.f) - 20.f));
            float eb = rna(__expf(fminf(fmaxf(acc[nt][1] * SCALEF, -20.f), 20.f) - 20.f));
            float ec = rna(__expf(fminf(fmaxf(acc[nt][2] * SCALEF, -20.f), 20.f) - 20.f));
            float ed = rna(__expf(fminf(fmaxf(acc[nt][3] * SCALEF, -20.f), 20.f) - 20.f));
            z0[0] += ea + eb; z0[1] += ec + ed;
            int off = (2 * nt + tg2) * 16;
            *(float2*)(e1b0 + (off ^ sw1)) = make_float2(ea, eb);
            *(float2*)(e2b0 + (off ^ sw2)) = make_float2(ec, ed);
        }
        __syncthreads();   // E0 visible
        // ---------- AV branch 0 + QK branch 1 (independent buffers) ----------
#pragma unroll
        for (int ks = 0; ks < 8; ks++) {
            uint32_t a0, a1, a2, a3;
            ldsm4(a0, a1, a2, a3, smb + ASK0 + arow * 256 + (((ks * 2 + agsel) * 16) ^ axr));
#pragma unroll
            for (int j2 = 0; j2 < 2; j2++) {
                uint32_t b0, b1, b2, b3;
                ldsm4(b0, b1, b2, b3, smb + ASV0 + (brow0 + j2 * 16) * 272 + (ks * 2 + bgsel) * 16);
                mma8(O0[2 * j2],     a0, a1, a2, a3, b0, b1);
                mma8(O0[2 * j2 + 1], a0, a1, a2, a3, b2, b3);
            }
        }
#pragma unroll
        for (int n = 0; n < 4; n++)
#pragma unroll
            for (int c = 0; c < 4; c++) acc[n][c] = 0.f;
#pragma unroll
        for (int ks = 0; ks < 8; ks++) {
            uint32_t a0, a1, a2, a3;
            ldsm4(a0, a1, a2, a3, smb + ASQ1 + arow * 256 + (((ks * 2 + agsel) * 16) ^ axr));
#pragma unroll
            for (int j2 = 0; j2 < 2; j2++) {
                uint32_t b0, b1, b2, b3;
                ldsm4(b0, b1, b2, b3, smb + ASK1 + (brow0 + j2 * 16) * 256 + (((ks * 2 + bgsel) * 16) ^ axr));
                mma8(acc[2 * j2],     a0, a1, a2, a3, b0, b1);
                mma8(acc[2 * j2 + 1], a0, a1, a2, a3, b2, b3);
            }
        }
        __syncthreads();   // all warps done reading K1 -> overwrite with E1
        // ---------- exp branch 1 + overlap dot (reads E0 from K0 buffer) ----
#pragma unroll
        for (int nt = 0; nt < 4; nt++) {
            float ea = rna(__expf(fminf(fmaxf(acc[nt][0] * SCALEF, -20.f), 20.f) - 20.f));
            float eb = rna(__expf(fminf(fmaxf(acc[nt][1] * SCALEF, -20.f), 20.f) - 20.f));
            float ec = rna(__expf(fminf(fmaxf(acc[nt][2] * SCALEF, -20.f), 20.f) - 20.f));
            float ed = rna(__expf(fminf(fmaxf(acc[nt][3] * SCALEF, -20.f), 20.f) - 20.f));
            z1[0] += ea + eb; z1[1] += ec + ed;
            int off = (2 * nt + tg2) * 16;
            float2 p1 = *(float2*)(e1b0 + (off ^ sw1));
            float2 p2 = *(float2*)(e2b0 + (off ^ sw2));
            dt[0] += p1.x * ea + p1.y * eb;
            dt[1] += p2.x * ec + p2.y * ed;
            *(float2*)(e1b1 + (off ^ sw1)) = make_float2(ea, eb);
            *(float2*)(e2b1 + (off ^ sw2)) = make_float2(ec, ed);
        }
        __syncthreads();   // E1 visible
        // ---------- AV branch 1 ----------
#pragma unroll
        for (int ks = 0; ks < 8; ks++) {
            uint32_t a0, a1, a2, a3;
            ldsm4(a0, a1, a2, a3, smb + ASK1 + arow * 256 + (((ks * 2 + agsel) * 16) ^ axr));
#pragma unroll
            for (int j2 = 0; j2 < 2; j2++) {
                uint32_t b0, b1, b2, b3;
                ldsm4(b0, b1, b2, b3, smb + ASV1 + (brow0 + j2 * 16) * 272 + (ks * 2 + bgsel) * 16);
                mma8(O1[2 * j2],     a0, a1, a2, a3, b0, b1);
                mma8(O1[2 * j2 + 1], a0, a1, a2, a3, b2, b3);
            }
        }
        __syncthreads();   // all reads of E1/V done before overwriting loads
        if (jt + 1 < 16) {
            int j0 = (jt + 1) * 64;
            issue_kv64(smb, ASK0, ASV0, Kg0, Vg0, j0, tid);
            issue_kv64(smb, ASK1, ASV1, Kg1, Vg1, j0, tid);
            CPCOMMIT();
        }
    }

    // ---------- epilogue: combine z/dt across wn pairs, constants, scatter ---
#pragma unroll
    for (int h = 0; h < 2; h++) {
        z0[h] += __shfl_xor_sync(0xffffffffu, z0[h], 1); z0[h] += __shfl_xor_sync(0xffffffffu, z0[h], 2);
        z1[h] += __shfl_xor_sync(0xffffffffu, z1[h], 1); z1[h] += __shfl_xor_sync(0xffffffffu, z1[h], 2);
        dt[h] += __shfl_xor_sync(0xffffffffu, dt[h], 1); dt[h] += __shfl_xor_sync(0xffffffffu, dt[h], 2);
    }
    float* zz0 = (float*)(smch + ASV0);   // V0 dead now
    float* zz1 = zz0 + 64;
    float* dd  = zz0 + 128;
    if (wn == 0 && tig == 0) {
        zz0[r1] = z0[0]; zz0[r2] = z0[1];
        zz1[r1] = z1[0]; zz1[r2] = z1[1];
        dd[r1]  = dt[0]; dd[r2]  = dt[1];
    }
    __syncthreads();
    if (wn == 1 && tig == 0) {
        zz0[r1] += z0[0]; zz0[r2] += z0[1];
        zz1[r1] += z1[0]; zz1[r2] += z1[1];
        dd[r1]  += dt[0]; dd[r2]  += dt[1];
    }
    __syncthreads();
    float temp = fminf(fmaxf(*temp_ptr, 0.1f), 5.0f);
    float c0r[2], c1r[2];
#pragma unroll
    for (int h = 0; h < 2; h++) {
        int rr = h ? r2 : r1;
        float a = zz0[rr], b = zz1[rr], d = dd[rr];
        float overlap = d / (a * b) + 2.0f * EPSF + 1024.0f * EPSF * EPSF;
        float mask = 1.0f / (1.0f + __expf(overlap * temp));
        float f = mask / (mask + EPSF);
        c0r[h] = f / a;
        c1r[h] = f / b;
    }
    int bidx = head / 12, hh = head - bidx * 12;
    int n1 = i0 + r1;
    int cb = hh * 64 + wn * 32 + 2 * tig;
    float* p1a = g_ao[0] + ((size_t)(bidx * 1024 + n1)) * 768 + cb;
    float* p2a = g_ao[0] + ((size_t)(bidx * 1024 + n1 + 8)) * 768 + cb;
    float* p1b = g_ao[1] + ((size_t)(bidx * 1024 + n1)) * 768 + cb;
    float* p2b = g_ao[1] + ((size_t)(bidx * 1024 + n1 + 8)) * 768 + cb;
#pragma unroll
    for (int nt = 0; nt < 4; nt++) {
        *(float2*)(p1a + nt * 8) = make_float2(rna(O0[nt][0] * c0r[0]), rna(O0[nt][1] * c0r[0]));
        *(float2*)(p2a + nt * 8) = make_float2(rna(O0[nt][2] * c0r[1]), rna(O0[nt][3] * c0r[1]));
        *(float2*)(p1b + nt * 8) = make_float2(rna(O1[nt][0] * c1r[0]), rna(O1[nt][1] * c1r[0]));
        *(float2*)(p2b + nt * 8) = make_float2(rna(O1[nt][2] * c1r[1]), rna(O1[nt][3] * c1r[1]));
    }
}

// ================= 0a) weight transpose pair (+tf32 round) ==================
__global__ __launch_bounds__(256) void k_tr2(const float* __restrict__ in0,
                                             const float* __restrict__ in1,
                                             float* __restrict__ out0,
                                             float* __restrict__ out1, int R, int C) {
    __shared__ float t[32][33];
    const float* in = blockIdx.z ? in1 : in0;
    float* out = blockIdx.z ? out1 : out0;
    int bx = blockIdx.x * 32, by = blockIdx.y * 32;
    int x = threadIdx.x & 31, y = threadIdx.x >> 5;
#pragma unroll
    for (int j = 0; j < 32; j += 8) t[y + j][x] = in[(size_t)(by + y + j) * C + bx + x];
    __syncthreads();
#pragma unroll
    for (int j = 0; j < 32; j += 8) out[(size_t)(bx + y + j) * R + by + x] = rna(t[x][y + j]);
}

// ================= 0b) round x to tf32 ======================================
__global__ __launch_bounds__(256) void k_rx(const float* __restrict__ x,
                                            float* __restrict__ o) {
    int i = blockIdx.x * 256 + threadIdx.x;
    float4 v = ((const float4*)x)[i];
    v.x = rna(v.x); v.y = rna(v.y); v.z = rna(v.z); v.w = rna(v.w);
    ((float4*)o)[i] = v;
}

// ================= 5) LayerNorm over C=768 (both branches via y) ============
__device__ __forceinline__ float blk_reduce(float v, float* smr) {
    const unsigned full = 0xffffffffu;
#pragma unroll
    for (int o = 16; o > 0; o >>= 1) v += __shfl_xor_sync(full, v, o);
    int warp = threadIdx.x >> 5, lane = threadIdx.x & 31;
    if (lane == 0) smr[warp] = v;
    __syncthreads();
    if (warp == 0) {
        float x = (lane < 8) ? smr[lane] : 0.0f;
#pragma unroll
        for (int o = 4; o > 0; o >>= 1) x += __shfl_xor_sync(full, x, o);
        if (lane == 0) smr[0] = x;
    }
    __syncthreads();
    float r = smr[0];
    __syncthreads();
    return r;
}

__global__ __launch_bounds__(256) void k_ln(const float* __restrict__ g0,
                                            const float* __restrict__ b0,
                                            const float* __restrict__ g1,
                                            const float* __restrict__ b1,
                                            float* __restrict__ out) {
    __shared__ float smr[32];
    int br = blockIdx.y;
    int row = blockIdx.x;
    const float* gam = br ? g1 : g0;
    const float* bet = br ? b1 : b0;
    float* o = out + (size_t)br * Mm * Cc;
    const float* x = g_pr[br] + (size_t)row * Cc;
    int t = threadIdx.x;
    float v[3];
#pragma unroll
    for (int i = 0; i < 3; i++) v[i] = x[t + 256 * i];
    float s = v[0] + v[1] + v[2];
    s = blk_reduce(s, smr);
    float mu = s * (1.0f / (float)Cc);
    float ss = 0.0f;
#pragma unroll
    for (int i = 0; i < 3; i++) { float d = v[i] - mu; ss += d * d; }
    ss = blk_reduce(ss, smr);
    float inv = rsqrtf(ss * (1.0f / (float)Cc) + LNEPS);
#pragma unroll
    for (int i = 0; i < 3; i++) {
        int c = t + 256 * i;
        o[(size_t)row * Cc + c] = (v[i] - mu) * inv * gam[c] + bet[c];
    }
}

// ================= launch ==================================================
extern "C" void kernel_launch(void* const* d_in, const int* in_sizes, int n_in,
                              void* d_out, int out_size) {
    const float* x    = (const float*)d_in[0];
    const float* wq0  = (const float*)d_in[1];
    const float* wq1  = (const float*)d_in[2];
    const float* wp0  = (const float*)d_in[3];
    const float* bp0  = (const float*)d_in[4];
    const float* wp1  = (const float*)d_in[5];
    const float* bp1  = (const float*)d_in[6];
    const float* temp = (const float*)d_in[7];
    const float* g0   = (const float*)d_in[8];
    const float* b0   = (const float*)d_in[9];
    const float* g1   = (const float*)d_in[10];
    const float* b1   = (const float*)d_in[11];
    float* out = (float*)d_out;

    static float* wt0 = nullptr; static float* wt1 = nullptr;
    static float* wpt0 = nullptr; static float* wpt1 = nullptr;
    static float* xr = nullptr;
    if (!wt0) {
        cudaGetSymbolAddress((void**)&wt0, g_wt);
        wt1 = wt0 + (size_t)3 * Cc * Cc;
        cudaGetSymbolAddress((void**)&wpt0, g_wpt);
        wpt1 = wpt0 + (size_t)Cc * Cc;
        cudaGetSymbolAddress((void**)&xr, g_xr);
        cudaFuncSetAttribute(k_qkv_mma, cudaFuncAttributeMaxDynamicSharedMemorySize, 65536);
        cudaFuncSetAttribute(k_proj_mma, cudaFuncAttributeMaxDynamicSharedMemorySize, 65536);
        cudaFuncSetAttribute(k_attn, cudaFuncAttributeMaxDynamicSharedMemorySize, A_SMEM);
    }

    dim3 t256(256);
    k_tr2<<<dim3(72, 24, 2), t256>>>(wq0, wq1, wt0, wt1, 768, 2304);
    k_tr2<<<dim3(24, 24, 2), t256>>>(wp0, wp1, wpt0, wpt1, 768, 768);
    k_rx<<<dim3(6144), t256>>>(x, xr);

    k_qkv_mma<<<dim3(18, 64, 2), t256, 65536>>>(xr, wt0, wt1);
    k_attn<<<dim3(16, BHh), t256, A_SMEM>>>(temp);
    k_proj_mma<<<dim3(6, 64, 2), t256, 65536>>>(wpt0, wpt1, bp0, bp1);
    k_ln<<<dim3(Mm, 2), t256>>>(g0, b0, g1, b1, out);
}

// round 9
// speedup vs baseline: 1.0189x; 1.0189x over previous
#include <cuda_runtime.h>
#include <cstdint>

#define Bb 8
#define Nn 1024
#define Cc 768
#define Hh 12
#define Dd 64
#define BHh 96
#define Mm 8192
#define SCALEF 0.125f
#define EPSF 1e-8f
#define LNEPS 1e-5f

// ---------------- scratch (device globals) ----------------
__device__ float g_q[2][(size_t)BHh*Nn*Dd];
__device__ float g_k[2][(size_t)BHh*Nn*Dd];
__device__ float g_v[2][(size_t)BHh*Nn*Dd];
__device__ float g_ao[2][(size_t)Mm*Cc];
__device__ float g_pr[2][(size_t)Mm*Cc];
__device__ float g_wt[2][(size_t)3*Cc*Cc];    // W_qkv^T
__device__ float g_wpt[2][(size_t)Cc*Cc];     // W_proj^T
__device__ float g_xr[(size_t)Mm*Cc];         // tf32-rounded x

// ---------------- helpers ----------------
__device__ __forceinline__ uint32_t smem_u32(const void* p) {
    uint32_t a;
    asm("{ .reg .u64 t; cvta.to.shared.u64 t, %1; cvt.u32.u64 %0, t; }" : "=r"(a) : "l"(p));
    return a;
}
__device__ __forceinline__ float rna(float x) {
    uint32_t u;
    asm("cvt.rna.tf32.f32 %0, %1;" : "=r"(u) : "f"(x));
    return __uint_as_float(u);
}
__device__ __forceinline__ void ldsm4(uint32_t& d0, uint32_t& d1, uint32_t& d2, uint32_t& d3, uint32_t a) {
    asm volatile("ldmatrix.sync.aligned.m8n8.x4.shared.b16 {%0,%1,%2,%3}, [%4];"
                 : "=r"(d0), "=r"(d1), "=r"(d2), "=r"(d3) : "r"(a));
}
__device__ __forceinline__ void mma8(float* c, uint32_t a0, uint32_t a1, uint32_t a2, uint32_t a3,
                                     uint32_t b0, uint32_t b1) {
    asm volatile("mma.sync.aligned.m16n8k8.row.col.f32.tf32.tf32.f32 "
                 "{%0,%1,%2,%3},{%4,%5,%6,%7},{%8,%9},{%0,%1,%2,%3};"
                 : "+f"(c[0]), "+f"(c[1]), "+f"(c[2]), "+f"(c[3])
                 : "r"(a0), "r"(a1), "r"(a2), "r"(a3), "r"(b0), "r"(b1));
}
#define CPA16(d, s) asm volatile("cp.async.cg.shared.global [%0], [%1], 16;" :: "r"(d), "l"(s))
#define CPA4(d, s)  asm volatile("cp.async.ca.shared.global [%0], [%1], 4;"  :: "r"(d), "l"(s))
#define CPCOMMIT()  asm volatile("cp.async.commit_group;" ::: "memory")
#define CPWAIT(n)   asm volatile("cp.async.wait_group %0;" :: "n"(n) : "memory")

// =============== shared tf32-mma mainloop: C[128x128] = A * B^T, K=768 ======
__device__ __forceinline__ void gemm_main_768(const float* __restrict__ A,
                                              const float* __restrict__ Bt,
                                              int by, int bx, uint32_t smb,
                                              float acc[2][8][4]) {
    const int tid = threadIdx.x, lane = tid & 31, wid = tid >> 5;
    const int wm = wid >> 1, wn = wid & 1;
    uint32_t dA[4], dB[4];
    const float* sA[4];
    const float* sB[4];
#pragma unroll
    for (int j = 0; j < 4; j++) {
        int e = tid + 256 * j;
        int m = e >> 3, kg = e & 7;
        uint32_t sw = (uint32_t)(m * 128 + ((kg * 16) ^ ((m & 7) << 4)));
        dA[j] = smb + sw;
        dB[j] = smb + 32768u + sw;
        sA[j] = A + (size_t)(by + m) * 768 + kg * 4;
        sB[j] = Bt + (size_t)(bx + m) * 768 + kg * 4;
    }
#pragma unroll
    for (int i = 0; i < 2; i++)
#pragma unroll
        for (int n = 0; n < 8; n++)
#pragma unroll
            for (int c = 0; c < 4; c++) acc[i][n][c] = 0.0f;

#pragma unroll
    for (int j = 0; j < 4; j++) { CPA16(dA[j], sA[j]); CPA16(dB[j], sB[j]); }
    CPCOMMIT();

    const int arow0 = wm * 32 + ((lane >> 3) & 1) * 8 + (lane & 7);
    const int brow0 = wn * 64 + ((lane >> 4) & 1) * 8 + (lane & 7);
    const int axr = (lane & 7) << 4;
    const int agsel = lane >> 4, bgsel = (lane >> 3) & 1;

    for (int it = 0; it < 24; ++it) {
        if (it + 1 < 24) {
            int kc = (it + 1) * 32;
            uint32_t ob = ((it + 1) & 1) ? 16384u : 0u;
#pragma unroll
            for (int j = 0; j < 4; j++) { CPA16(dA[j] + ob, sA[j] + kc); CPA16(dB[j] + ob, sB[j] + kc); }
        }
        CPCOMMIT();
        CPWAIT(1);
        __syncthreads();
        uint32_t Ab = smb + ((it & 1) ? 16384u : 0u);
        uint32_t Bbf = smb + 32768u + ((it & 1) ? 16384u : 0u);
#pragma unroll
        for (int ks = 0; ks < 4; ks++) {
            uint32_t a[2][4];
#pragma unroll
            for (int mt = 0; mt < 2; mt++) {
                int r = arow0 + mt * 16;
                ldsm4(a[mt][0], a[mt][1], a[mt][2], a[mt][3],
                      Ab + r * 128 + (((ks * 2 + agsel) * 16) ^ axr));
            }
#pragma unroll
            for (int j2 = 0; j2 < 4; j2++) {
                int r = brow0 + j2 * 16;
                uint32_t b0, b1, b2, b3;
                ldsm4(b0, b1, b2, b3, Bbf + r * 128 + (((ks * 2 + bgsel) * 16) ^ axr));
#pragma unroll
                for (int mt = 0; mt < 2; mt++) {
                    mma8(acc[mt][2 * j2],     a[mt][0], a[mt][1], a[mt][2], a[mt][3], b0, b1);
                    mma8(acc[mt][2 * j2 + 1], a[mt][0], a[mt][1], a[mt][2], a[mt][3], b2, b3);
                }
            }
        }
        __syncthreads();
    }
}

// ================= 1) qkv GEMM (both branches via z) + scatter ==============
__global__ __launch_bounds__(256, 2) void k_qkv_mma(const float* __restrict__ X,
                                                    const float* __restrict__ Wt0,
                                                    const float* __restrict__ Wt1) {
    extern __shared__ char smch[];
    uint32_t smb = smem_u32(smch);
    int br = blockIdx.z;
    const float* Wt = br ? Wt1 : Wt0;
    int bx = blockIdx.x * 128, by = blockIdx.y * 128;
    float acc[2][8][4];
    gemm_main_768(X, Wt, by, bx, smb, acc);

    int lane = threadIdx.x & 31, wid = threadIdx.x >> 5;
    int wm = wid >> 1, wn = wid & 1, g = lane >> 2, tig = lane & 3;
    int colbase = bx + wn * 64;
    int seg = colbase >> 6;
    int three = seg / 12, hseg = seg - three * 12;
    float* base3 = (three == 0) ? g_q[br] : ((three == 1) ? g_k[br] : g_v[br]);
#pragma unroll
    for (int mt = 0; mt < 2; mt++) {
        int m1 = by + wm * 32 + mt * 16 + g;
        int b1 = m1 >> 10, n1 = m1 & 1023;
        float* p1 = base3 + (((size_t)(b1 * 12 + hseg)) * 1024 + n1) * 64 + 2 * tig;
        float* p2 = p1 + (size_t)8 * 64;
#pragma unroll
        for (int nt = 0; nt < 8; nt++) {
            *(float2*)(p1 + nt * 8) = make_float2(rna(acc[mt][nt][0]), rna(acc[mt][nt][1]));
            *(float2*)(p2 + nt * 8) = make_float2(rna(acc[mt][nt][2]), rna(acc[mt][nt][3]));
        }
    }
}

// ================= 2) proj GEMM + bias (both branches via z) ================
__global__ __launch_bounds__(256, 2) void k_proj_mma(const float* __restrict__ Wt0,
                                                     const float* __restrict__ Wt1,
                                                     const float* __restrict__ bias0,
                                                     const float* __restrict__ bias1) {
    extern __shared__ char smch[];
    uint32_t smb = smem_u32(smch);
    int br = blockIdx.z;
    const float* Wt = br ? Wt1 : Wt0;
    const float* bias = br ? bias1 : bias0;
    int bx = blockIdx.x * 128, by = blockIdx.y * 128;
    float acc[2][8][4];
    gemm_main_768(g_ao[br], Wt, by, bx, smb, acc);

    int lane = threadIdx.x & 31, wid = threadIdx.x >> 5;
    int wm = wid >> 1, wn = wid & 1, g = lane >> 2, tig = lane & 3;
    int colbase = bx + wn * 64;
#pragma unroll
    for (int mt = 0; mt < 2; mt++) {
        int m1 = by + wm * 32 + mt * 16 + g;
        float* p1 = g_pr[br] + (size_t)m1 * 768 + colbase + 2 * tig;
        float* p2 = p1 + (size_t)8 * 768;
#pragma unroll
        for (int nt = 0; nt < 8; nt++) {
            float2 bv = *(const float2*)(bias + colbase + nt * 8 + 2 * tig);
            *(float2*)(p1 + nt * 8) = make_float2(acc[mt][nt][0] + bv.x, acc[mt][nt][1] + bv.y);
            *(float2*)(p2 + nt * 8) = make_float2(acc[mt][nt][2] + bv.x, acc[mt][nt][3] + bv.y);
        }
    }
}

// ====== 3) FUSED attention: warp-owns-rows layout, warp-private E staging ===
// Each warp: 16 q-rows x full 64-key tile. Only 2 __syncthreads per jt.
// smem: Q0 @0 (32K) Q1 @32768 | K0[2] @65536 K1[2] @98304 (16K each buf)
//       V0[2] @131072 V1[2] @163840 (16K each buf, swizzled 256B rows)
//       E @196608 (8 warps x 4KB, warp-private)
#define ASQ1 32768u
#define ASK0 65536u
#define ASK1 98304u
#define ASV0 131072u
#define ASV1 163840u
#define ASE  196608u
#define A_SMEM 229376

__device__ __forceinline__ void issue_kv(uint32_t smb, uint32_t sko, uint32_t svo,
                                         const float* __restrict__ Kg,
                                         const float* __restrict__ Vg,
                                         int j0, int tid) {
#pragma unroll
    for (int jj = 0; jj < 4; jj++) {
        int e = tid + 256 * jj;
        int n = e >> 4, kg = e & 15;
        CPA16(smb + sko + n * 256 + ((kg * 16) ^ ((n & 7) << 4)),
              Kg + (size_t)(j0 + n) * 64 + kg * 4);
    }
    int vn = tid & 63, vkq = tid >> 6;     // vn = d index, vkq picks 16 keys
    uint32_t vrow = smb + svo + vn * 256;
    int vsw = (vn & 7) << 4;
    const float* vs = Vg + (size_t)j0 * 64 + vn;
#pragma unroll
    for (int jj = 0; jj < 16; jj++) {
        int k = vkq * 16 + jj;
        CPA4(vrow + ((((k >> 2) * 16) ^ vsw) + (k & 3) * 4), vs + (size_t)k * 64);
    }
}

__global__ __launch_bounds__(256, 1) void k_attn(const float* __restrict__ temp_ptr) {
    extern __shared__ char smch[];
    uint32_t smb = smem_u32(smch);
    const int head = blockIdx.y, i0 = blockIdx.x * 128;
    const int tid = threadIdx.x, lane = tid & 31, wq = tid >> 5;
    const float* Qg0 = g_q[0] + (size_t)head * 65536;
    const float* Qg1 = g_q[1] + (size_t)head * 65536;
    const float* Kg0 = g_k[0] + (size_t)head * 65536;
    const float* Kg1 = g_k[1] + (size_t)head * 65536;
    const float* Vg0 = g_v[0] + (size_t)head * 65536;
    const float* Vg1 = g_v[1] + (size_t)head * 65536;

    // persistent Q (both branches) + first KV tiles: ONE cp.async group
#pragma unroll
    for (int j = 0; j < 16; j++) {
        int e = tid + 256 * j;
        int br = e >> 11, r = e & 2047;
        int n = r >> 4, kg = r & 15;
        uint32_t dst = smb + (uint32_t)(br ? ASQ1 : 0u) + n * 256 + ((kg * 16) ^ ((n & 7) << 4));
        const float* src = (br ? Qg1 : Qg0) + (size_t)(i0 + n) * 64 + kg * 4;
        CPA16(dst, src);
    }
    issue_kv(smb, ASK0, ASV0, Kg0, Vg0, 0, tid);
    issue_kv(smb, ASK1, ASV1, Kg1, Vg1, 0, tid);
    CPCOMMIT();

    // fragment indices
    const int agsel = lane >> 4, bgsel = (lane >> 3) & 1;
    const int ar2 = ((lane >> 3) & 1) * 8 + (lane & 7);      // row within 16
    const int arq = wq * 16 + ar2;                            // Q row
    const int asw = (ar2 & 7) << 4;
    const int kr = ((lane >> 4) & 1) * 8 + (lane & 7);        // B row within 16
    const int ksw = (kr & 7) << 4;
    const int g = lane >> 2, tig = lane & 3;
    const int esw = (g & 7) << 4;
    const int tg2 = tig >> 1;
    char* e1p = smch + ASE + wq * 4096 + g * 256 + (tig & 1) * 8;
    char* e2p = e1p + 8 * 256;
    const uint32_t eAb = smb + ASE + wq * 4096;
    const uint32_t qA0 = smb + arq * 256;
    const uint32_t qA1 = smb + ASQ1 + arq * 256;

    float O0[8][4], O1[8][4];
#pragma unroll
    for (int n = 0; n < 8; n++)
#pragma unroll
        for (int c = 0; c < 4; c++) { O0[n][c] = 0.f; O1[n][c] = 0.f; }
    float z0[2] = {0.f, 0.f}, z1[2] = {0.f, 0.f}, dt[2] = {0.f, 0.f};

    for (int jt = 0; jt < 16; jt++) {
        uint32_t cb = (uint32_t)((jt & 1) * 16384);
        if (jt < 15) {
            uint32_t nb = (uint32_t)(((jt + 1) & 1) * 16384);
            int j0 = (jt + 1) * 64;
            issue_kv(smb, ASK0 + nb, ASV0 + nb, Kg0, Vg0, j0, tid);
            issue_kv(smb, ASK1 + nb, ASV1 + nb, Kg1, Vg1, j0, tid);
            CPCOMMIT();
            CPWAIT(1);
        } else {
            CPWAIT(0);
        }
        __syncthreads();

        // ---------- QK branch 0 ----------
        float acc[8][4];
#pragma unroll
        for (int n = 0; n < 8; n++)
#pragma unroll
            for (int c = 0; c < 4; c++) acc[n][c] = 0.f;
#pragma unroll
        for (int ks = 0; ks < 8; ks++) {
            uint32_t a0, a1, a2, a3;
            ldsm4(a0, a1, a2, a3, qA0 + (((ks * 2 + agsel) * 16) ^ asw));
#pragma unroll
            for (int j2 = 0; j2 < 4; j2++) {
                uint32_t b0, b1, b2, b3;
                ldsm4(b0, b1, b2, b3, smb + ASK0 + cb + (j2 * 16 + kr) * 256 + (((ks * 2 + bgsel) * 16) ^ ksw));
                mma8(acc[2 * j2],     a0, a1, a2, a3, b0, b1);
                mma8(acc[2 * j2 + 1], a0, a1, a2, a3, b2, b3);
            }
        }
        // exp + z0 + stage E (warp-private)
#pragma unroll
        for (int nt = 0; nt < 8; nt++) {
            float ea = rna(__expf(fminf(fmaxf(acc[nt][0] * SCALEF, -20.f), 20.f) - 20.f));
            float eb = rna(__expf(fminf(fmaxf(acc[nt][1] * SCALEF, -20.f), 20.f) - 20.f));
            float ec = rna(__expf(fminf(fmaxf(acc[nt][2] * SCALEF, -20.f), 20.f) - 20.f));
            float ed = rna(__expf(fminf(fmaxf(acc[nt][3] * SCALEF, -20.f), 20.f) - 20.f));
            z0[0] += ea + eb; z0[1] += ec + ed;
            int off = (2 * nt + tg2) * 16;
            *(float2*)(e1p + (off ^ esw)) = make_float2(ea, eb);
            *(float2*)(e2p + (off ^ esw)) = make_float2(ec, ed);
        }
        __syncwarp();
        // ---------- AV branch 0 ----------
#pragma unroll
        for (int ks = 0; ks < 8; ks++) {
            uint32_t a0, a1, a2, a3;
            ldsm4(a0, a1, a2, a3, eAb + ar2 * 256 + (((ks * 2 + agsel) * 16) ^ asw));
#pragma unroll
            for (int j2 = 0; j2 < 4; j2++) {
                uint32_t b0, b1, b2, b3;
                ldsm4(b0, b1, b2, b3, smb + ASV0 + cb + (j2 * 16 + kr) * 256 + (((ks * 2 + bgsel) * 16) ^ ksw));
                mma8(O0[2 * j2],     a0, a1, a2, a3, b0, b1);
                mma8(O0[2 * j2 + 1], a0, a1, a2, a3, b2, b3);
            }
        }
        __syncwarp();
        // ---------- QK branch 1 ----------
#pragma unroll
        for (int n = 0; n < 8; n++)
#pragma unroll
            for (int c = 0; c < 4; c++) acc[n][c] = 0.f;
#pragma unroll
        for (int ks = 0; ks < 8; ks++) {
            uint32_t a0, a1, a2, a3;
            ldsm4(a0, a1, a2, a3, qA1 + (((ks * 2 + agsel) * 16) ^ asw));
#pragma unroll
            for (int j2 = 0; j2 < 4; j2++) {
                uint32_t b0, b1, b2, b3;
                ldsm4(b0, b1, b2, b3, smb + ASK1 + cb + (j2 * 16 + kr) * 256 + (((ks * 2 + bgsel) * 16) ^ ksw));
                mma8(acc[2 * j2],     a0, a1, a2, a3, b0, b1);
                mma8(acc[2 * j2 + 1], a0, a1, a2, a3, b2, b3);
            }
        }
        // exp + z1 + overlap dot (read back own e0) + stage E1
#pragma unroll
        for (int nt = 0; nt < 8; nt++) {
            float ea = rna(__expf(fminf(fmaxf(acc[nt][0] * SCALEF, -20.f), 20.f) - 20.f));
            float eb = rna(__expf(fminf(fmaxf(acc[nt][1] * SCALEF, -20.f), 20.f) - 20.f));
            float ec = rna(__expf(fminf(fmaxf(acc[nt][2] * SCALEF, -20.f), 20.f) - 20.f));
            float ed = rna(__expf(fminf(fmaxf(acc[nt][3] * SCALEF, -20.f), 20.f) - 20.f));
            z1[0] += ea + eb; z1[1] += ec + ed;
            int off = (2 * nt + tg2) * 16;
            float2 p1 = *(float2*)(e1p + (off ^ esw));
            float2 p2 = *(float2*)(e2p + (off ^ esw));
            dt[0] += p1.x * ea + p1.y * eb;
            dt[1] += p2.x * ec + p2.y * ed;
            *(float2*)(e1p + (off ^ esw)) = make_float2(ea, eb);
            *(float2*)(e2p + (off ^ esw)) = make_float2(ec, ed);
        }
        __syncwarp();
        // ---------- AV branch 1 ----------
#pragma unroll
        for (int ks = 0; ks < 8; ks++) {
            uint32_t a0, a1, a2, a3;
            ldsm4(a0, a1, a2, a3, eAb + ar2 * 256 + (((ks * 2 + agsel) * 16) ^ asw));
#pragma unroll
            for (int j2 = 0; j2 < 4; j2++) {
                uint32_t b0, b1, b2, b3;
                ldsm4(b0, b1, b2, b3, smb + ASV1 + cb + (j2 * 16 + kr) * 256 + (((ks * 2 + bgsel) * 16) ^ ksw));
                mma8(O1[2 * j2],     a0, a1, a2, a3, b0, b1);
                mma8(O1[2 * j2 + 1], a0, a1, a2, a3, b2, b3);
            }
        }
        __syncthreads();   // all warps done with this jt's K/V before overwrite
    }

    // ---------- epilogue: quad-reduce z/dt (warp owns whole rows) ----------
#pragma unroll
    for (int h = 0; h < 2; h++) {
        z0[h] += __shfl_xor_sync(0xffffffffu, z0[h], 1); z0[h] += __shfl_xor_sync(0xffffffffu, z0[h], 2);
        z1[h] += __shfl_xor_sync(0xffffffffu, z1[h], 1); z1[h] += __shfl_xor_sync(0xffffffffu, z1[h], 2);
        dt[h] += __shfl_xor_sync(0xffffffffu, dt[h], 1); dt[h] += __shfl_xor_sync(0xffffffffu, dt[h], 2);
    }
    float temp = fminf(fmaxf(*temp_ptr, 0.1f), 5.0f);
    float c0r[2], c1r[2];
#pragma unroll
    for (int h = 0; h < 2; h++) {
        float a = z0[h], b = z1[h], d = dt[h];
        float overlap = d / (a * b) + 2.0f * EPSF + 1024.0f * EPSF * EPSF;
        float mask = 1.0f / (1.0f + __expf(overlap * temp));
        float f = mask / (mask + EPSF);
        c0r[h] = f / a;
        c1r[h] = f / b;
    }
    int bidx = head / 12, hh = head - bidx * 12;
    int n1 = i0 + wq * 16 + g;
    int cb2 = hh * 64 + 2 * tig;
    float* p1a = g_ao[0] + ((size_t)(bidx * 1024 + n1)) * 768 + cb2;
    float* p2a = g_ao[0] + ((size_t)(bidx * 1024 + n1 + 8)) * 768 + cb2;
    float* p1b = g_ao[1] + ((size_t)(bidx * 1024 + n1)) * 768 + cb2;
    float* p2b = g_ao[1] + ((size_t)(bidx * 1024 + n1 + 8)) * 768 + cb2;
#pragma unroll
    for (int nt = 0; nt < 8; nt++) {
        *(float2*)(p1a + nt * 8) = make_float2(rna(O0[nt][0] * c0r[0]), rna(O0[nt][1] * c0r[0]));
        *(float2*)(p2a + nt * 8) = make_float2(rna(O0[nt][2] * c0r[1]), rna(O0[nt][3] * c0r[1]));
        *(float2*)(p1b + nt * 8) = make_float2(rna(O1[nt][0] * c1r[0]), rna(O1[nt][1] * c1r[0]));
        *(float2*)(p2b + nt * 8) = make_float2(rna(O1[nt][2] * c1r[1]), rna(O1[nt][3] * c1r[1]));
    }
}

// ================= 0a) weight transpose pair (+tf32 round) ==================
__global__ __launch_bounds__(256) void k_tr2(const float* __restrict__ in0,
                                             const float* __restrict__ in1,
                                             float* __restrict__ out0,
                                             float* __restrict__ out1, int R, int C) {
    __shared__ float t[32][33];
    const float* in = blockIdx.z ? in1 : in0;
    float* out = blockIdx.z ? out1 : out0;
    int bx = blockIdx.x * 32, by = blockIdx.y * 32;
    int x = threadIdx.x & 31, y = threadIdx.x >> 5;
#pragma unroll
    for (int j = 0; j < 32; j += 8) t[y + j][x] = in[(size_t)(by + y + j) * C + bx + x];
    __syncthreads();
#pragma unroll
    for (int j = 0; j < 32; j += 8) out[(size_t)(bx + y + j) * R + by + x] = rna(t[x][y + j]);
}

// ================= 0b) round x to tf32 ======================================
__global__ __launch_bounds__(256) void k_rx(const float* __restrict__ x,
                                            float* __restrict__ o) {
    int i = blockIdx.x * 256 + threadIdx.x;
    float4 v = ((const float4*)x)[i];
    v.x = rna(v.x); v.y = rna(v.y); v.z = rna(v.z); v.w = rna(v.w);
    ((float4*)o)[i] = v;
}

// ================= 5) LayerNorm over C=768 (both branches via y) ============
__device__ __forceinline__ float blk_reduce(float v, float* smr) {
    const unsigned full = 0xffffffffu;
#pragma unroll
    for (int o = 16; o > 0; o >>= 1) v += __shfl_xor_sync(full, v, o);
    int warp = threadIdx.x >> 5, lane = threadIdx.x & 31;
    if (lane == 0) smr[warp] = v;
    __syncthreads();
    if (warp == 0) {
        float x = (lane < 8) ? smr[lane] : 0.0f;
#pragma unroll
        for (int o = 4; o > 0; o >>= 1) x += __shfl_xor_sync(full, x, o);
        if (lane == 0) smr[0] = x;
    }
    __syncthreads();
    float r = smr[0];
    __syncthreads();
    return r;
}

__global__ __launch_bounds__(256) void k_ln(const float* __restrict__ g0,
                                            const float* __restrict__ b0,
                                            const float* __restrict__ g1,
                                            const float* __restrict__ b1,
                                            float* __restrict__ out) {
    __shared__ float smr[32];
    int br = blockIdx.y;
    int row = blockIdx.x;
    const float* gam = br ? g1 : g0;
    const float* bet = br ? b1 : b0;
    float* o = out + (size_t)br * Mm * Cc;
    const float* x = g_pr[br] + (size_t)row * Cc;
    int t = threadIdx.x;
    float v[3];
#pragma unroll
    for (int i = 0; i < 3; i++) v[i] = x[t + 256 * i];
    float s = v[0] + v[1] + v[2];
    s = blk_reduce(s, smr);
    float mu = s * (1.0f / (float)Cc);
    float ss = 0.0f;
#pragma unroll
    for (int i = 0; i < 3; i++) { float d = v[i] - mu; ss += d * d; }
    ss = blk_reduce(ss, smr);
    float inv = rsqrtf(ss * (1.0f / (float)Cc) + LNEPS);
#pragma unroll
    for (int i = 0; i < 3; i++) {
        int c = t + 256 * i;
        o[(size_t)row * Cc + c] = (v[i] - mu) * inv * gam[c] + bet[c];
    }
}

// ================= launch ==================================================
extern "C" void kernel_launch(void* const* d_in, const int* in_sizes, int n_in,
                              void* d_out, int out_size) {
    const float* x    = (const float*)d_in[0];
    const float* wq0  = (const float*)d_in[1];
    const float* wq1  = (const float*)d_in[2];
    const float* wp0  = (const float*)d_in[3];
    const float* bp0  = (const float*)d_in[4];
    const float* wp1  = (const float*)d_in[5];
    const float* bp1  = (const float*)d_in[6];
    const float* temp = (const float*)d_in[7];
    const float* g0   = (const float*)d_in[8];
    const float* b0   = (const float*)d_in[9];
    const float* g1   = (const float*)d_in[10];
    const float* b1   = (const float*)d_in[11];
    float* out = (float*)d_out;

    static float* wt0 = nullptr; static float* wt1 = nullptr;
    static float* wpt0 = nullptr; static float* wpt1 = nullptr;
    static float* xr = nullptr;
    if (!wt0) {
        cudaGetSymbolAddress((void**)&wt0, g_wt);
        wt1 = wt0 + (size_t)3 * Cc * Cc;
        cudaGetSymbolAddress((void**)&wpt0, g_wpt);
        wpt1 = wpt0 + (size_t)Cc * Cc;
        cudaGetSymbolAddress((void**)&xr, g_xr);
        cudaFuncSetAttribute(k_qkv_mma, cudaFuncAttributeMaxDynamicSharedMemorySize, 65536);
        cudaFuncSetAttribute(k_proj_mma, cudaFuncAttributeMaxDynamicSharedMemorySize, 65536);
        cudaFuncSetAttribute(k_attn, cudaFuncAttributeMaxDynamicSharedMemorySize, A_SMEM);
    }

    dim3 t256(256);
    k_tr2<<<dim3(72, 24, 2), t256>>>(wq0, wq1, wt0, wt1, 768, 2304);
    k_tr2<<<dim3(24, 24, 2), t256>>>(wp0, wp1, wpt0, wpt1, 768, 768);
    k_rx<<<dim3(6144), t256>>>(x, xr);

    k_qkv_mma<<<dim3(18, 64, 2), t256, 65536>>>(xr, wt0, wt1);
    k_attn<<<dim3(8, BHh), t256, A_SMEM>>>(temp);
    k_proj_mma<<<dim3(6, 64, 2), t256, 65536>>>(wpt0, wpt1, bp0, bp1);
    k_ln<<<dim3(Mm, 2), t256>>>(g0, b0, g1, b1, out);
}

// round 10
// speedup vs baseline: 1.0339x; 1.0148x over previous
#include <cuda_runtime.h>
#include <cstdint>

#define Bb 8
#define Nn 1024
#define Cc 768
#define Hh 12
#define Dd 64
#define BHh 96
#define Mm 8192
#define SCALEF 0.125f
#define EPSF 1e-8f
#define LNEPS 1e-5f

// ---------------- scratch (device globals) ----------------
__device__ float g_q[2][(size_t)BHh*Nn*Dd];
__device__ float g_k[2][(size_t)BHh*Nn*Dd];
__device__ float g_v[2][(size_t)BHh*Nn*Dd];
__device__ float g_ao[2][(size_t)Mm*Cc];
__device__ float g_pr[2][(size_t)Mm*Cc];
__device__ float g_wt[2][(size_t)3*Cc*Cc];    // W_qkv^T
__device__ float g_wpt[2][(size_t)Cc*Cc];     // W_proj^T
__device__ float g_xr[(size_t)Mm*Cc];         // tf32-rounded x

// ---------------- helpers ----------------
__device__ __forceinline__ uint32_t smem_u32(const void* p) {
    uint32_t a;
    asm("{ .reg .u64 t; cvta.to.shared.u64 t, %1; cvt.u32.u64 %0, t; }" : "=r"(a) : "l"(p));
    return a;
}
__device__ __forceinline__ float rna(float x) {
    uint32_t u;
    asm("cvt.rna.tf32.f32 %0, %1;" : "=r"(u) : "f"(x));
    return __uint_as_float(u);
}
__device__ __forceinline__ void ldsm4(uint32_t& d0, uint32_t& d1, uint32_t& d2, uint32_t& d3, uint32_t a) {
    asm volatile("ldmatrix.sync.aligned.m8n8.x4.shared.b16 {%0,%1,%2,%3}, [%4];"
                 : "=r"(d0), "=r"(d1), "=r"(d2), "=r"(d3) : "r"(a));
}
__device__ __forceinline__ void mma8(float* c, uint32_t a0, uint32_t a1, uint32_t a2, uint32_t a3,
                                     uint32_t b0, uint32_t b1) {
    asm volatile("mma.sync.aligned.m16n8k8.row.col.f32.tf32.tf32.f32 "
                 "{%0,%1,%2,%3},{%4,%5,%6,%7},{%8,%9},{%0,%1,%2,%3};"
                 : "+f"(c[0]), "+f"(c[1]), "+f"(c[2]), "+f"(c[3])
                 : "r"(a0), "r"(a1), "r"(a2), "r"(a3), "r"(b0), "r"(b1));
}
#define CPA16(d, s) asm volatile("cp.async.cg.shared.global [%0], [%1], 16;" :: "r"(d), "l"(s))
#define CPA4(d, s)  asm volatile("cp.async.ca.shared.global [%0], [%1], 4;"  :: "r"(d), "l"(s))
#define CPCOMMIT()  asm volatile("cp.async.commit_group;" ::: "memory")
#define CPWAIT(n)   asm volatile("cp.async.wait_group %0;" :: "n"(n) : "memory")
#define PAIRBAR(id) asm volatile("bar.sync %0, 64;" :: "r"(id) : "memory")

// =============== shared tf32-mma mainloop: C[128x128] = A * B^T, K=768 ======
__device__ __forceinline__ void gemm_main_768(const float* __restrict__ A,
                                              const float* __restrict__ Bt,
                                              int by, int bx, uint32_t smb,
                                              float acc[2][8][4]) {
    const int tid = threadIdx.x, lane = tid & 31, wid = tid >> 5;
    const int wm = wid >> 1, wn = wid & 1;
    uint32_t dA[4], dB[4];
    const float* sA[4];
    const float* sB[4];
#pragma unroll
    for (int j = 0; j < 4; j++) {
        int e = tid + 256 * j;
        int m = e >> 3, kg = e & 7;
        uint32_t sw = (uint32_t)(m * 128 + ((kg * 16) ^ ((m & 7) << 4)));
        dA[j] = smb + sw;
        dB[j] = smb + 32768u + sw;
        sA[j] = A + (size_t)(by + m) * 768 + kg * 4;
        sB[j] = Bt + (size_t)(bx + m) * 768 + kg * 4;
    }
#pragma unroll
    for (int i = 0; i < 2; i++)
#pragma unroll
        for (int n = 0; n < 8; n++)
#pragma unroll
            for (int c = 0; c < 4; c++) acc[i][n][c] = 0.0f;

#pragma unroll
    for (int j = 0; j < 4; j++) { CPA16(dA[j], sA[j]); CPA16(dB[j], sB[j]); }
    CPCOMMIT();

    const int arow0 = wm * 32 + ((lane >> 3) & 1) * 8 + (lane & 7);
    const int brow0 = wn * 64 + ((lane >> 4) & 1) * 8 + (lane & 7);
    const int axr = (lane & 7) << 4;
    const int agsel = lane >> 4, bgsel = (lane >> 3) & 1;

    for (int it = 0; it < 24; ++it) {
        if (it + 1 < 24) {
            int kc = (it + 1) * 32;
            uint32_t ob = ((it + 1) & 1) ? 16384u : 0u;
#pragma unroll
            for (int j = 0; j < 4; j++) { CPA16(dA[j] + ob, sA[j] + kc); CPA16(dB[j] + ob, sB[j] + kc); }
        }
        CPCOMMIT();
        CPWAIT(1);
        __syncthreads();
        uint32_t Ab = smb + ((it & 1) ? 16384u : 0u);
        uint32_t Bbf = smb + 32768u + ((it & 1) ? 16384u : 0u);
#pragma unroll
        for (int ks = 0; ks < 4; ks++) {
            uint32_t a[2][4];
#pragma unroll
            for (int mt = 0; mt < 2; mt++) {
                int r = arow0 + mt * 16;
                ldsm4(a[mt][0], a[mt][1], a[mt][2], a[mt][3],
                      Ab + r * 128 + (((ks * 2 + agsel) * 16) ^ axr));
            }
#pragma unroll
            for (int j2 = 0; j2 < 4; j2++) {
                int r = brow0 + j2 * 16;
                uint32_t b0, b1, b2, b3;
                ldsm4(b0, b1, b2, b3, Bbf + r * 128 + (((ks * 2 + bgsel) * 16) ^ axr));
#pragma unroll
                for (int mt = 0; mt < 2; mt++) {
                    mma8(acc[mt][2 * j2],     a[mt][0], a[mt][1], a[mt][2], a[mt][3], b0, b1);
                    mma8(acc[mt][2 * j2 + 1], a[mt][0], a[mt][1], a[mt][2], a[mt][3], b2, b3);
                }
            }
        }
        __syncthreads();
    }
}

// ================= 1) qkv GEMM (both branches via z) + scatter ==============
__global__ __launch_bounds__(256, 2) void k_qkv_mma(const float* __restrict__ X,
                                                    const float* __restrict__ Wt0,
                                                    const float* __restrict__ Wt1) {
    extern __shared__ char smch[];
    uint32_t smb = smem_u32(smch);
    int br = blockIdx.z;
    const float* Wt = br ? Wt1 : Wt0;
    int bx = blockIdx.x * 128, by = blockIdx.y * 128;
    float acc[2][8][4];
    gemm_main_768(X, Wt, by, bx, smb, acc);

    int lane = threadIdx.x & 31, wid = threadIdx.x >> 5;
    int wm = wid >> 1, wn = wid & 1, g = lane >> 2, tig = lane & 3;
    int colbase = bx + wn * 64;
    int seg = colbase >> 6;
    int three = seg / 12, hseg = seg - three * 12;
    float* base3 = (three == 0) ? g_q[br] : ((three == 1) ? g_k[br] : g_v[br]);
#pragma unroll
    for (int mt = 0; mt < 2; mt++) {
        int m1 = by + wm * 32 + mt * 16 + g;
        int b1 = m1 >> 10, n1 = m1 & 1023;
        float* p1 = base3 + (((size_t)(b1 * 12 + hseg)) * 1024 + n1) * 64 + 2 * tig;
        float* p2 = p1 + (size_t)8 * 64;
#pragma unroll
        for (int nt = 0; nt < 8; nt++) {
            *(float2*)(p1 + nt * 8) = make_float2(rna(acc[mt][nt][0]), rna(acc[mt][nt][1]));
            *(float2*)(p2 + nt * 8) = make_float2(rna(acc[mt][nt][2]), rna(acc[mt][nt][3]));
        }
    }
}

// ================= 2) proj GEMM + bias (both branches via z) ================
__global__ __launch_bounds__(256, 2) void k_proj_mma(const float* __restrict__ Wt0,
                                                     const float* __restrict__ Wt1,
                                                     const float* __restrict__ bias0,
                                                     const float* __restrict__ bias1) {
    extern __shared__ char smch[];
    uint32_t smb = smem_u32(smch);
    int br = blockIdx.z;
    const float* Wt = br ? Wt1 : Wt0;
    const float* bias = br ? bias1 : bias0;
    int bx = blockIdx.x * 128, by = blockIdx.y * 128;
    float acc[2][8][4];
    gemm_main_768(g_ao[br], Wt, by, bx, smb, acc);

    int lane = threadIdx.x & 31, wid = threadIdx.x >> 5;
    int wm = wid >> 1, wn = wid & 1, g = lane >> 2, tig = lane & 3;
    int colbase = bx + wn * 64;
#pragma unroll
    for (int mt = 0; mt < 2; mt++) {
        int m1 = by + wm * 32 + mt * 16 + g;
        float* p1 = g_pr[br] + (size_t)m1 * 768 + colbase + 2 * tig;
        float* p2 = p1 + (size_t)8 * 768;
#pragma unroll
        for (int nt = 0; nt < 8; nt++) {
            float2 bv = *(const float2*)(bias + colbase + nt * 8 + 2 * tig);
            *(float2*)(p1 + nt * 8) = make_float2(acc[mt][nt][0] + bv.x, acc[mt][nt][1] + bv.y);
            *(float2*)(p2 + nt * 8) = make_float2(acc[mt][nt][2] + bv.x, acc[mt][nt][3] + bv.y);
        }
    }
}

// ====== 3) FUSED attention: 64-row tiles, occ 2, warp pairs, pair barriers ==
// Warp (wm,h): 16 q-rows (wm) x key/d half (h). Pair = {wm, wm+4}.
// smem: Q0 @0 Q1 @16K | K0 @32K K1 @48K | V0 @64K V1 @80K | E @96K  (112KB)
#define ASQ1 16384u
#define ASK0 32768u
#define ASK1 49152u
#define ASV0 65536u
#define ASV1 81920u
#define ASE  98304u
#define A_SMEM 114688

__device__ __forceinline__ void issue_kv(uint32_t smb, uint32_t sko, uint32_t svo,
                                         const float* __restrict__ Kg,
                                         const float* __restrict__ Vg,
                                         int j0, int tid) {
#pragma unroll
    for (int jj = 0; jj < 4; jj++) {
        int e = tid + 256 * jj;
        int n = e >> 4, kg = e & 15;
        CPA16(smb + sko + n * 256 + ((kg * 16) ^ ((n & 7) << 4)),
              Kg + (size_t)(j0 + n) * 64 + kg * 4);
    }
    int vn = tid & 63, vkq = tid >> 6;     // vn = d index, vkq picks 16 keys
    uint32_t vrow = smb + svo + vn * 256;
    int vsw = (vn & 7) << 4;
    const float* vs = Vg + (size_t)j0 * 64 + vn;
#pragma unroll
    for (int jj = 0; jj < 16; jj++) {
        int k = vkq * 16 + jj;
        CPA4(vrow + ((((k >> 2) * 16) ^ vsw) + (k & 3) * 4), vs + (size_t)k * 64);
    }
}

__global__ __launch_bounds__(256, 2) void k_attn(const float* __restrict__ temp_ptr) {
    extern __shared__ char smch[];
    uint32_t smb = smem_u32(smch);
    const int head = blockIdx.y, i0 = blockIdx.x * 64;
    const int tid = threadIdx.x, lane = tid & 31, wid = tid >> 5;
    const int wm = wid & 3, h = wid >> 2;
    const float* Qg0 = g_q[0] + (size_t)head * 65536;
    const float* Qg1 = g_q[1] + (size_t)head * 65536;
    const float* Kg0 = g_k[0] + (size_t)head * 65536;
    const float* Kg1 = g_k[1] + (size_t)head * 65536;
    const float* Vg0 = g_v[0] + (size_t)head * 65536;
    const float* Vg1 = g_v[1] + (size_t)head * 65536;

    // persistent Q (both branches) + first KV tiles: one cp.async group
#pragma unroll
    for (int j = 0; j < 8; j++) {
        int e = tid + 256 * j;
        int br = e >> 10, r = e & 1023;
        int n = r >> 4, kg = r & 15;
        uint32_t dst = smb + (uint32_t)(br ? ASQ1 : 0u) + n * 256 + ((kg * 16) ^ ((n & 7) << 4));
        const float* src = (br ? Qg1 : Qg0) + (size_t)(i0 + n) * 64 + kg * 4;
        CPA16(dst, src);
    }
    issue_kv(smb, ASK0, ASV0, Kg0, Vg0, 0, tid);
    issue_kv(smb, ASK1, ASV1, Kg1, Vg1, 0, tid);
    CPCOMMIT();

    // fragment indices
    const int agsel = lane >> 4, bgsel = (lane >> 3) & 1;
    const int ar2 = ((lane >> 3) & 1) * 8 + (lane & 7);
    const int arq = wm * 16 + ar2;
    const int asw = (ar2 & 7) << 4;
    const int kr = ((lane >> 4) & 1) * 8 + (lane & 7);
    const int ksw = (kr & 7) << 4;
    const int g = lane >> 2, tig = lane & 3;
    const int esw = (g & 7) << 4;
    const int tg2 = tig >> 1;
    char* e1p = smch + ASE + (wm * 16 + g) * 256 + h * 128 + (tig & 1) * 8;
    char* e2p = e1p + 8 * 256;
    const uint32_t eA  = smb + ASE + arq * 256;
    const uint32_t qA0 = smb + arq * 256;
    const uint32_t qA1 = smb + ASQ1 + arq * 256;
    const uint32_t kB0 = smb + ASK0 + (h * 32 + kr) * 256;
    const uint32_t kB1 = smb + ASK1 + (h * 32 + kr) * 256;
    const uint32_t vB0 = smb + ASV0 + (h * 32 + kr) * 256;
    const uint32_t vB1 = smb + ASV1 + (h * 32 + kr) * 256;
    const int barid = wm + 1;

    float O0[4][4], O1[4][4];
#pragma unroll
    for (int n = 0; n < 4; n++)
#pragma unroll
        for (int c = 0; c < 4; c++) { O0[n][c] = 0.f; O1[n][c] = 0.f; }
    float z0[2] = {0.f, 0.f}, z1[2] = {0.f, 0.f}, dt[2] = {0.f, 0.f};

    for (int jt = 0; jt < 16; jt++) {
        CPWAIT(0);
        __syncthreads();

        // ---------- QK branch 0 ----------
        float acc[4][4], e0r[4][4];
#pragma unroll
        for (int n = 0; n < 4; n++)
#pragma unroll
            for (int c = 0; c < 4; c++) acc[n][c] = 0.f;
#pragma unroll
        for (int ks = 0; ks < 8; ks++) {
            uint32_t a0, a1, a2, a3;
            ldsm4(a0, a1, a2, a3, qA0 + (((ks * 2 + agsel) * 16) ^ asw));
#pragma unroll
            for (int j2 = 0; j2 < 2; j2++) {
                uint32_t b0, b1, b2, b3;
                ldsm4(b0, b1, b2, b3, kB0 + j2 * 16 * 256 + (((ks * 2 + bgsel) * 16) ^ ksw));
                mma8(acc[2 * j2],     a0, a1, a2, a3, b0, b1);
                mma8(acc[2 * j2 + 1], a0, a1, a2, a3, b2, b3);
            }
        }
        // exp0: keep in regs + stage to E
#pragma unroll
        for (int nt = 0; nt < 4; nt++) {
            float ea = rna(__expf(fminf(fmaxf(acc[nt][0] * SCALEF, -20.f), 20.f) - 20.f));
            float eb = rna(__expf(fminf(fmaxf(acc[nt][1] * SCALEF, -20.f), 20.f) - 20.f));
            float ec = rna(__expf(fminf(fmaxf(acc[nt][2] * SCALEF, -20.f), 20.f) - 20.f));
            float ed = rna(__expf(fminf(fmaxf(acc[nt][3] * SCALEF, -20.f), 20.f) - 20.f));
            e0r[nt][0] = ea; e0r[nt][1] = eb; e0r[nt][2] = ec; e0r[nt][3] = ed;
            z0[0] += ea + eb; z0[1] += ec + ed;
            int off = ((2 * nt + tg2) * 16) ^ esw;
            *(float2*)(e1p + off) = make_float2(ea, eb);
            *(float2*)(e2p + off) = make_float2(ec, ed);
        }
        PAIRBAR(barid);          // pair's E0 rows complete
        // ---------- AV branch 0 ----------
#pragma unroll
        for (int ks = 0; ks < 8; ks++) {
            uint32_t a0, a1, a2, a3;
            ldsm4(a0, a1, a2, a3, eA + (((ks * 2 + agsel) * 16) ^ asw));
#pragma unroll
            for (int j2 = 0; j2 < 2; j2++) {
                uint32_t b0, b1, b2, b3;
                ldsm4(b0, b1, b2, b3, vB0 + j2 * 16 * 256 + (((ks * 2 + bgsel) * 16) ^ ksw));
                mma8(O0[2 * j2],     a0, a1, a2, a3, b0, b1);
                mma8(O0[2 * j2 + 1], a0, a1, a2, a3, b2, b3);
            }
        }
        // ---------- QK branch 1 ----------
#pragma unroll
        for (int n = 0; n < 4; n++)
#pragma unroll
            for (int c = 0; c < 4; c++) acc[n][c] = 0.f;
#pragma unroll
        for (int ks = 0; ks < 8; ks++) {
            uint32_t a0, a1, a2, a3;
            ldsm4(a0, a1, a2, a3, qA1 + (((ks * 2 + agsel) * 16) ^ asw));
#pragma unroll
            for (int j2 = 0; j2 < 2; j2++) {
                uint32_t b0, b1, b2, b3;
                ldsm4(b0, b1, b2, b3, kB1 + j2 * 16 * 256 + (((ks * 2 + bgsel) * 16) ^ ksw));
                mma8(acc[2 * j2],     a0, a1, a2, a3, b0, b1);
                mma8(acc[2 * j2 + 1], a0, a1, a2, a3, b2, b3);
            }
        }
        PAIRBAR(barid);          // pair finished AV0's E reads
        // exp1 + overlap dot (register e0) + stage E1
#pragma unroll
        for (int nt = 0; nt < 4; nt++) {
            float ea = rna(__expf(fminf(fmaxf(acc[nt][0] * SCALEF, -20.f), 20.f) - 20.f));
            float eb = rna(__expf(fminf(fmaxf(acc[nt][1] * SCALEF, -20.f), 20.f) - 20.f));
            float ec = rna(__expf(fminf(fmaxf(acc[nt][2] * SCALEF, -20.f), 20.f) - 20.f));
            float ed = rna(__expf(fminf(fmaxf(acc[nt][3] * SCALEF, -20.f), 20.f) - 20.f));
            z1[0] += ea + eb; z1[1] += ec + ed;
            dt[0] += e0r[nt][0] * ea + e0r[nt][1] * eb;
            dt[1] += e0r[nt][2] * ec + e0r[nt][3] * ed;
            int off = ((2 * nt + tg2) * 16) ^ esw;
            *(float2*)(e1p + off) = make_float2(ea, eb);
            *(float2*)(e2p + off) = make_float2(ec, ed);
        }
        PAIRBAR(barid);          // pair's E1 rows complete
        // ---------- AV branch 1 ----------
#pragma unroll
        for (int ks = 0; ks < 8; ks++) {
            uint32_t a0, a1, a2, a3;
            ldsm4(a0, a1, a2, a3, eA + (((ks * 2 + agsel) * 16) ^ asw));
#pragma unroll
            for (int j2 = 0; j2 < 2; j2++) {
                uint32_t b0, b1, b2, b3;
                ldsm4(b0, b1, b2, b3, vB1 + j2 * 16 * 256 + (((ks * 2 + bgsel) * 16) ^ ksw));
                mma8(O1[2 * j2],     a0, a1, a2, a3, b0, b1);
                mma8(O1[2 * j2 + 1], a0, a1, a2, a3, b2, b3);
            }
        }
        __syncthreads();         // all warps done with this jt's K/V before overwrite
        if (jt < 15) {
            int j0 = (jt + 1) * 64;
            issue_kv(smb, ASK0, ASV0, Kg0, Vg0, j0, tid);
            issue_kv(smb, ASK1, ASV1, Kg1, Vg1, j0, tid);
            CPCOMMIT();
        }
    }

    // ---------- epilogue: quad-reduce, pair-combine z/dt, constants, store ---
#pragma unroll
    for (int hh2 = 0; hh2 < 2; hh2++) {
        z0[hh2] += __shfl_xor_sync(0xffffffffu, z0[hh2], 1); z0[hh2] += __shfl_xor_sync(0xffffffffu, z0[hh2], 2);
        z1[hh2] += __shfl_xor_sync(0xffffffffu, z1[hh2], 1); z1[hh2] += __shfl_xor_sync(0xffffffffu, z1[hh2], 2);
        dt[hh2] += __shfl_xor_sync(0xffffffffu, dt[hh2], 1); dt[hh2] += __shfl_xor_sync(0xffffffffu, dt[hh2], 2);
    }
    const int r1 = wm * 16 + g, r2 = r1 + 8;
    float* zz0 = (float*)(smch + ASE);   // E dead
    float* zz1 = zz0 + 64;
    float* dd  = zz0 + 128;
    if (h == 0 && tig == 0) {
        zz0[r1] = z0[0]; zz0[r2] = z0[1];
        zz1[r1] = z1[0]; zz1[r2] = z1[1];
        dd[r1]  = dt[0]; dd[r2]  = dt[1];
    }
    __syncthreads();
    if (h == 1 && tig == 0) {
        zz0[r1] += z0[0]; zz0[r2] += z0[1];
        zz1[r1] += z1[0]; zz1[r2] += z1[1];
        dd[r1]  += dt[0]; dd[r2]  += dt[1];
    }
    __syncthreads();
    float temp = fminf(fmaxf(*temp_ptr, 0.1f), 5.0f);
    float c0r[2], c1r[2];
#pragma unroll
    for (int hh2 = 0; hh2 < 2; hh2++) {
        int rr = hh2 ? r2 : r1;
        float a = zz0[rr], b = zz1[rr], d = dd[rr];
        float overlap = d / (a * b) + 2.0f * EPSF + 1024.0f * EPSF * EPSF;
        float mask = 1.0f / (1.0f + __expf(overlap * temp));
        float f = mask / (mask + EPSF);
        c0r[hh2] = f / a;
        c1r[hh2] = f / b;
    }
    int bidx = head / 12, hd = head - bidx * 12;
    int n1 = i0 + r1;
    int cb2 = hd * 64 + h * 32 + 2 * tig;
    float* p1a = g_ao[0] + ((size_t)(bidx * 1024 + n1)) * 768 + cb2;
    float* p2a = g_ao[0] + ((size_t)(bidx * 1024 + n1 + 8)) * 768 + cb2;
    float* p1b = g_ao[1] + ((size_t)(bidx * 1024 + n1)) * 768 + cb2;
    float* p2b = g_ao[1] + ((size_t)(bidx * 1024 + n1 + 8)) * 768 + cb2;
#pragma unroll
    for (int nt = 0; nt < 4; nt++) {
        *(float2*)(p1a + nt * 8) = make_float2(rna(O0[nt][0] * c0r[0]), rna(O0[nt][1] * c0r[0]));
        *(float2*)(p2a + nt * 8) = make_float2(rna(O0[nt][2] * c0r[1]), rna(O0[nt][3] * c0r[1]));
        *(float2*)(p1b + nt * 8) = make_float2(rna(O1[nt][0] * c1r[0]), rna(O1[nt][1] * c1r[0]));
        *(float2*)(p2b + nt * 8) = make_float2(rna(O1[nt][2] * c1r[1]), rna(O1[nt][3] * c1r[1]));
    }
}

// ================= 0a) weight transpose pair (+tf32 round) ==================
__global__ __launch_bounds__(256) void k_tr2(const float* __restrict__ in0,
                                             const float* __restrict__ in1,
                                             float* __restrict__ out0,
                                             float* __restrict__ out1, int R, int C) {
    __shared__ float t[32][33];
    const float* in = blockIdx.z ? in1 : in0;
    float* out = blockIdx.z ? out1 : out0;
    int bx = blockIdx.x * 32, by = blockIdx.y * 32;
    int x = threadIdx.x & 31, y = threadIdx.x >> 5;
#pragma unroll
    for (int j = 0; j < 32; j += 8) t[y + j][x] = in[(size_t)(by + y + j) * C + bx + x];
    __syncthreads();
#pragma unroll
    for (int j = 0; j < 32; j += 8) out[(size_t)(bx + y + j) * R + by + x] = rna(t[x][y + j]);
}

// ================= 0b) round x to tf32 ======================================
__global__ __launch_bounds__(256) void k_rx(const float* __restrict__ x,
                                            float* __restrict__ o) {
    int i = blockIdx.x * 256 + threadIdx.x;
    float4 v = ((const float4*)x)[i];
    v.x = rna(v.x); v.y = rna(v.y); v.z = rna(v.z); v.w = rna(v.w);
    ((float4*)o)[i] = v;
}

// ================= 5) LayerNorm over C=768 (both branches via y) ============
__device__ __forceinline__ float blk_reduce(float v, float* smr) {
    const unsigned full = 0xffffffffu;
#pragma unroll
    for (int o = 16; o > 0; o >>= 1) v += __shfl_xor_sync(full, v, o);
    int warp = threadIdx.x >> 5, lane = threadIdx.x & 31;
    if (lane == 0) smr[warp] = v;
    __syncthreads();
    if (warp == 0) {
        float x = (lane < 8) ? smr[lane] : 0.0f;
#pragma unroll
        for (int o = 4; o > 0; o >>= 1) x += __shfl_xor_sync(full, x, o);
        if (lane == 0) smr[0] = x;
    }
    __syncthreads();
    float r = smr[0];
    __syncthreads();
    return r;
}

__global__ __launch_bounds__(256) void k_ln(const float* __restrict__ g0,
                                            const float* __restrict__ b0,
                                            const float* __restrict__ g1,
                                            const float* __restrict__ b1,
                                            float* __restrict__ out) {
    __shared__ float smr[32];
    int br = blockIdx.y;
    int row = blockIdx.x;
    const float* gam = br ? g1 : g0;
    const float* bet = br ? b1 : b0;
    float* o = out + (size_t)br * Mm * Cc;
    const float* x = g_pr[br] + (size_t)row * Cc;
    int t = threadIdx.x;
    float v[3];
#pragma unroll
    for (int i = 0; i < 3; i++) v[i] = x[t + 256 * i];
    float s = v[0] + v[1] + v[2];
    s = blk_reduce(s, smr);
    float mu = s * (1.0f / (float)Cc);
    float ss = 0.0f;
#pragma unroll
    for (int i = 0; i < 3; i++) { float d = v[i] - mu; ss += d * d; }
    ss = blk_reduce(ss, smr);
    float inv = rsqrtf(ss * (1.0f / (float)Cc) + LNEPS);
#pragma unroll
    for (int i = 0; i < 3; i++) {
        int c = t + 256 * i;
        o[(size_t)row * Cc + c] = (v[i] - mu) * inv * gam[c] + bet[c];
    }
}

// ================= launch ==================================================
extern "C" void kernel_launch(void* const* d_in, const int* in_sizes, int n_in,
                              void* d_out, int out_size) {
    const float* x    = (const float*)d_in[0];
    const float* wq0  = (const float*)d_in[1];
    const float* wq1  = (const float*)d_in[2];
    const float* wp0  = (const float*)d_in[3];
    const float* bp0  = (const float*)d_in[4];
    const float* wp1  = (const float*)d_in[5];
    const float* bp1  = (const float*)d_in[6];
    const float* temp = (const float*)d_in[7];
    const float* g0   = (const float*)d_in[8];
    const float* b0   = (const float*)d_in[9];
    const float* g1   = (const float*)d_in[10];
    const float* b1   = (const float*)d_in[11];
    float* out = (float*)d_out;

    static float* wt0 = nullptr; static float* wt1 = nullptr;
    static float* wpt0 = nullptr; static float* wpt1 = nullptr;
    static float* xr = nullptr;
    if (!wt0) {
        cudaGetSymbolAddress((void**)&wt0, g_wt);
        wt1 = wt0 + (size_t)3 * Cc * Cc;
        cudaGetSymbolAddress((void**)&wpt0, g_wpt);
        wpt1 = wpt0 + (size_t)Cc * Cc;
        cudaGetSymbolAddress((void**)&xr, g_xr);
        cudaFuncSetAttribute(k_qkv_mma, cudaFuncAttributeMaxDynamicSharedMemorySize, 65536);
        cudaFuncSetAttribute(k_proj_mma, cudaFuncAttributeMaxDynamicSharedMemorySize, 65536);
        cudaFuncSetAttribute(k_attn, cudaFuncAttributeMaxDynamicSharedMemorySize, A_SMEM);
    }

    dim3 t256(256);
    k_tr2<<<dim3(72, 24, 2), t256>>>(wq0, wq1, wt0, wt1, 768, 2304);
    k_tr2<<<dim3(24, 24, 2), t256>>>(wp0, wp1, wpt0, wpt1, 768, 768);
    k_rx<<<dim3(6144), t256>>>(x, xr);

    k_qkv_mma<<<dim3(18, 64, 2), t256, 65536>>>(xr, wt0, wt1);
    k_attn<<<dim3(16, BHh), t256, A_SMEM>>>(temp);
    k_proj_mma<<<dim3(6, 64, 2), t256, 65536>>>(wpt0, wpt1, bp0, bp1);
    k_ln<<<dim3(Mm, 2), t256>>>(g0, b0, g1, b1, out);
}

// round 11
// speedup vs baseline: 1.1638x; 1.1256x over previous
#include <cuda_runtime.h>
#include <cstdint>

#define Bb 8
#define Nn 1024
#define Cc 768
#define Hh 12
#define Dd 64
#define BHh 96
#define Mm 8192
#define SCALEF 0.125f
#define EPSF 1e-8f
#define LNEPS 1e-5f

// ---------------- scratch (device globals) ----------------
__device__ float g_q[2][(size_t)BHh*Nn*Dd];
__device__ float g_k[2][(size_t)BHh*Nn*Dd];
__device__ float g_vt[2][(size_t)BHh*Dd*Nn];  // V^T: [head][d][key]
__device__ float g_ao[2][(size_t)Mm*Cc];
__device__ float g_pr[2][(size_t)Mm*Cc];
__device__ float g_wt[2][(size_t)3*Cc*Cc];    // W_qkv^T
__device__ float g_wpt[2][(size_t)Cc*Cc];     // W_proj^T
__device__ float g_xr[(size_t)Mm*Cc];         // tf32-rounded x

// ---------------- helpers ----------------
__device__ __forceinline__ uint32_t smem_u32(const void* p) {
    uint32_t a;
    asm("{ .reg .u64 t; cvta.to.shared.u64 t, %1; cvt.u32.u64 %0, t; }" : "=r"(a) : "l"(p));
    return a;
}
__device__ __forceinline__ float rna(float x) {
    uint32_t u;
    asm("cvt.rna.tf32.f32 %0, %1;" : "=r"(u) : "f"(x));
    return __uint_as_float(u);
}
// exp(clamp(acc*0.125, -20, 20) - 20), all on FMA/ALU pipes (no MUFU)
__device__ __forceinline__ float fexp20(float acc) {
    const float C1 = 0.125f * 1.4426950408889634f;
    const float C2 = 20.0f * 1.4426950408889634f;
    float y = fmaf(acc, C1, -C2);
    y = fmaxf(y, -2.0f * C2);
    y = fminf(y, 0.0f);
    float t = y + 12582912.0f;                       // round-to-nearest int
    int ib = __float_as_int(t) - 0x4B400000;         // = round(y)
    float f = y - (t - 12582912.0f);                 // frac in [-0.5, 0.5]
    float p = 1.3333558146e-3f;
    p = fmaf(p, f, 9.6181291076e-3f);
    p = fmaf(p, f, 5.5504108664e-2f);
    p = fmaf(p, f, 2.4022650696e-1f);
    p = fmaf(p, f, 6.9314718056e-1f);
    p = fmaf(p, f, 1.0f);
    return __int_as_float(__float_as_int(p) + (ib << 23));
}
__device__ __forceinline__ void ldsm4(uint32_t& d0, uint32_t& d1, uint32_t& d2, uint32_t& d3, uint32_t a) {
    asm volatile("ldmatrix.sync.aligned.m8n8.x4.shared.b16 {%0,%1,%2,%3}, [%4];"
                 : "=r"(d0), "=r"(d1), "=r"(d2), "=r"(d3) : "r"(a));
}
__device__ __forceinline__ void mma8(float* c, uint32_t a0, uint32_t a1, uint32_t a2, uint32_t a3,
                                     uint32_t b0, uint32_t b1) {
    asm volatile("mma.sync.aligned.m16n8k8.row.col.f32.tf32.tf32.f32 "
                 "{%0,%1,%2,%3},{%4,%5,%6,%7},{%8,%9},{%0,%1,%2,%3};"
                 : "+f"(c[0]), "+f"(c[1]), "+f"(c[2]), "+f"(c[3])
                 : "r"(a0), "r"(a1), "r"(a2), "r"(a3), "r"(b0), "r"(b1));
}
#define CPA16(d, s) asm volatile("cp.async.cg.shared.global [%0], [%1], 16;" :: "r"(d), "l"(s))
#define CPCOMMIT()  asm volatile("cp.async.commit_group;" ::: "memory")
#define CPWAIT(n)   asm volatile("cp.async.wait_group %0;" :: "n"(n) : "memory")
#define PAIRBAR(id) asm volatile("bar.sync %0, 64;" :: "r"(id) : "memory")

// =============== shared tf32-mma mainloop: C[128x128] = A * B^T, K=768 ======
__device__ __forceinline__ void gemm_main_768(const float* __restrict__ A,
                                              const float* __restrict__ Bt,
                                              int by, int bx, uint32_t smb,
                                              float acc[2][8][4]) {
    const int tid = threadIdx.x, lane = tid & 31, wid = tid >> 5;
    const int wm = wid >> 1, wn = wid & 1;
    uint32_t dA[4], dB[4];
    const float* sA[4];
    const float* sB[4];
#pragma unroll
    for (int j = 0; j < 4; j++) {
        int e = tid + 256 * j;
        int m = e >> 3, kg = e & 7;
        uint32_t sw = (uint32_t)(m * 128 + ((kg * 16) ^ ((m & 7) << 4)));
        dA[j] = smb + sw;
        dB[j] = smb + 32768u + sw;
        sA[j] = A + (size_t)(by + m) * 768 + kg * 4;
        sB[j] = Bt + (size_t)(bx + m) * 768 + kg * 4;
    }
#pragma unroll
    for (int i = 0; i < 2; i++)
#pragma unroll
        for (int n = 0; n < 8; n++)
#pragma unroll
            for (int c = 0; c < 4; c++) acc[i][n][c] = 0.0f;

#pragma unroll
    for (int j = 0; j < 4; j++) { CPA16(dA[j], sA[j]); CPA16(dB[j], sB[j]); }
    CPCOMMIT();

    const int arow0 = wm * 32 + ((lane >> 3) & 1) * 8 + (lane & 7);
    const int brow0 = wn * 64 + ((lane >> 4) & 1) * 8 + (lane & 7);
    const int axr = (lane & 7) << 4;
    const int agsel = lane >> 4, bgsel = (lane >> 3) & 1;

    for (int it = 0; it < 24; ++it) {
        if (it + 1 < 24) {
            int kc = (it + 1) * 32;
            uint32_t ob = ((it + 1) & 1) ? 16384u : 0u;
#pragma unroll
            for (int j = 0; j < 4; j++) { CPA16(dA[j] + ob, sA[j] + kc); CPA16(dB[j] + ob, sB[j] + kc); }
        }
        CPCOMMIT();
        CPWAIT(1);
        __syncthreads();
        uint32_t Ab = smb + ((it & 1) ? 16384u : 0u);
        uint32_t Bbf = smb + 32768u + ((it & 1) ? 16384u : 0u);
#pragma unroll
        for (int ks = 0; ks < 4; ks++) {
            uint32_t a[2][4];
#pragma unroll
            for (int mt = 0; mt < 2; mt++) {
                int r = arow0 + mt * 16;
                ldsm4(a[mt][0], a[mt][1], a[mt][2], a[mt][3],
                      Ab + r * 128 + (((ks * 2 + agsel) * 16) ^ axr));
            }
#pragma unroll
            for (int j2 = 0; j2 < 4; j2++) {
                int r = brow0 + j2 * 16;
                uint32_t b0, b1, b2, b3;
                ldsm4(b0, b1, b2, b3, Bbf + r * 128 + (((ks * 2 + bgsel) * 16) ^ axr));
#pragma unroll
                for (int mt = 0; mt < 2; mt++) {
                    mma8(acc[mt][2 * j2],     a[mt][0], a[mt][1], a[mt][2], a[mt][3], b0, b1);
                    mma8(acc[mt][2 * j2 + 1], a[mt][0], a[mt][1], a[mt][2], a[mt][3], b2, b3);
                }
            }
        }
        __syncthreads();
    }
}

// ================= 1) qkv GEMM (both branches via z) + scatter ==============
__global__ __launch_bounds__(256, 2) void k_qkv_mma(const float* __restrict__ X,
                                                    const float* __restrict__ Wt0,
                                                    const float* __restrict__ Wt1) {
    extern __shared__ char smch[];
    uint32_t smb = smem_u32(smch);
    int br = blockIdx.z;
    const float* Wt = br ? Wt1 : Wt0;
    int bx = blockIdx.x * 128, by = blockIdx.y * 128;
    float acc[2][8][4];
    gemm_main_768(X, Wt, by, bx, smb, acc);

    int lane = threadIdx.x & 31, wid = threadIdx.x >> 5;
    int wm = wid >> 1, wn = wid & 1, g = lane >> 2, tig = lane & 3;
    int colbase = bx + wn * 64;
    int seg = colbase >> 6;
    int three = seg / 12, hseg = seg - three * 12;
    if (three == 2) {
        // V: write transposed [head][d][key]
#pragma unroll
        for (int mt = 0; mt < 2; mt++) {
            int m1 = by + wm * 32 + mt * 16 + g;
            int b1 = m1 >> 10, n1 = m1 & 1023;
            float* vt = g_vt[br] + ((size_t)(b1 * 12 + hseg)) * 65536;
#pragma unroll
            for (int nt = 0; nt < 8; nt++) {
                int d0 = nt * 8 + 2 * tig;
                vt[(size_t)d0 * 1024 + n1]             = rna(acc[mt][nt][0]);
                vt[(size_t)(d0 + 1) * 1024 + n1]       = rna(acc[mt][nt][1]);
                vt[(size_t)d0 * 1024 + n1 + 8]         = rna(acc[mt][nt][2]);
                vt[(size_t)(d0 + 1) * 1024 + n1 + 8]   = rna(acc[mt][nt][3]);
            }
        }
    } else {
        float* base3 = (three == 0) ? g_q[br] : g_k[br];
#pragma unroll
        for (int mt = 0; mt < 2; mt++) {
            int m1 = by + wm * 32 + mt * 16 + g;
            int b1 = m1 >> 10, n1 = m1 & 1023;
            float* p1 = base3 + (((size_t)(b1 * 12 + hseg)) * 1024 + n1) * 64 + 2 * tig;
            float* p2 = p1 + (size_t)8 * 64;
#pragma unroll
            for (int nt = 0; nt < 8; nt++) {
                *(float2*)(p1 + nt * 8) = make_float2(rna(acc[mt][nt][0]), rna(acc[mt][nt][1]));
                *(float2*)(p2 + nt * 8) = make_float2(rna(acc[mt][nt][2]), rna(acc[mt][nt][3]));
            }
        }
    }
}

// ================= 2) proj GEMM + bias (both branches via z) ================
__global__ __launch_bounds__(256, 2) void k_proj_mma(const float* __restrict__ Wt0,
                                                     const float* __restrict__ Wt1,
                                                     const float* __restrict__ bias0,
                                                     const float* __restrict__ bias1) {
    extern __shared__ char smch[];
    uint32_t smb = smem_u32(smch);
    int br = blockIdx.z;
    const float* Wt = br ? Wt1 : Wt0;
    const float* bias = br ? bias1 : bias0;
    int bx = blockIdx.x * 128, by = blockIdx.y * 128;
    float acc[2][8][4];
    gemm_main_768(g_ao[br], Wt, by, bx, smb, acc);

    int lane = threadIdx.x & 31, wid = threadIdx.x >> 5;
    int wm = wid >> 1, wn = wid & 1, g = lane >> 2, tig = lane & 3;
    int colbase = bx + wn * 64;
#pragma unroll
    for (int mt = 0; mt < 2; mt++) {
        int m1 = by + wm * 32 + mt * 16 + g;
        float* p1 = g_pr[br] + (size_t)m1 * 768 + colbase + 2 * tig;
        float* p2 = p1 + (size_t)8 * 768;
#pragma unroll
        for (int nt = 0; nt < 8; nt++) {
            float2 bv = *(const float2*)(bias + colbase + nt * 8 + 2 * tig);
            *(float2*)(p1 + nt * 8) = make_float2(acc[mt][nt][0] + bv.x, acc[mt][nt][1] + bv.y);
            *(float2*)(p2 + nt * 8) = make_float2(acc[mt][nt][2] + bv.x, acc[mt][nt][3] + bv.y);
        }
    }
}

// ====== 3) FUSED attention: 64-row tiles, occ 2, all-CPA16 loads ============
// Warp (wm,h): 16 q-rows (wm) x key/d half (h). Pair = {wm, wm+4}.
// smem: Q0 @0 Q1 @16K | K0 @32K K1 @48K | V0 @64K V1 @80K | E @96K  (112KB)
#define ASQ1 16384u
#define ASK0 32768u
#define ASK1 49152u
#define ASV0 65536u
#define ASV1 81920u
#define ASE  98304u
#define A_SMEM 114688

// K rows = keys (64 x 256B of d); V rows = d (64 x 256B of keys, from g_vt)
__device__ __forceinline__ void issue_kv(uint32_t smb, uint32_t sko, uint32_t svo,
                                         const float* __restrict__ Kg,
                                         const float* __restrict__ Vt,
                                         int j0, int tid) {
#pragma unroll
    for (int jj = 0; jj < 4; jj++) {
        int e = tid + 256 * jj;
        int n = e >> 4, kg = e & 15;
        uint32_t sw = (uint32_t)(n * 256 + ((kg * 16) ^ ((n & 7) << 4)));
        CPA16(smb + sko + sw, Kg + (size_t)(j0 + n) * 64 + kg * 4);
        CPA16(smb + svo + sw, Vt + (size_t)n * 1024 + j0 + kg * 4);
    }
}

__global__ __launch_bounds__(256, 2) void k_attn(const float* __restrict__ temp_ptr) {
    extern __shared__ char smch[];
    uint32_t smb = smem_u32(smch);
    const int head = blockIdx.y, i0 = blockIdx.x * 64;
    const int tid = threadIdx.x, lane = tid & 31, wid = tid >> 5;
    const int wm = wid & 3, h = wid >> 2;
    const float* Qg0 = g_q[0] + (size_t)head * 65536;
    const float* Qg1 = g_q[1] + (size_t)head * 65536;
    const float* Kg0 = g_k[0] + (size_t)head * 65536;
    const float* Kg1 = g_k[1] + (size_t)head * 65536;
    const float* Vt0 = g_vt[0] + (size_t)head * 65536;
    const float* Vt1 = g_vt[1] + (size_t)head * 65536;

    // persistent Q (both branches) + first KV tiles
#pragma unroll
    for (int j = 0; j < 8; j++) {
        int e = tid + 256 * j;
        int br = e >> 10, r = e & 1023;
        int n = r >> 4, kg = r & 15;
        uint32_t dst = smb + (uint32_t)(br ? ASQ1 : 0u) + n * 256 + ((kg * 16) ^ ((n & 7) << 4));
        const float* src = (br ? Qg1 : Qg0) + (size_t)(i0 + n) * 64 + kg * 4;
        CPA16(dst, src);
    }
    issue_kv(smb, ASK0, ASV0, Kg0, Vt0, 0, tid);
    issue_kv(smb, ASK1, ASV1, Kg1, Vt1, 0, tid);
    CPCOMMIT();

    // fragment indices
    const int agsel = lane >> 4, bgsel = (lane >> 3) & 1;
    const int ar2 = ((lane >> 3) & 1) * 8 + (lane & 7);
    const int arq = wm * 16 + ar2;
    const int asw = (ar2 & 7) << 4;
    const int kr = ((lane >> 4) & 1) * 8 + (lane & 7);
    const int ksw = (kr & 7) << 4;
    const int g = lane >> 2, tig = lane & 3;
    const int esw = (g & 7) << 4;
    const int tg2 = tig >> 1;
    char* e1p = smch + ASE + (wm * 16 + g) * 256 + h * 128 + (tig & 1) * 8;
    char* e2p = e1p + 8 * 256;
    const uint32_t eA  = smb + ASE + arq * 256;
    const uint32_t qA0 = smb + arq * 256;
    const uint32_t qA1 = smb + ASQ1 + arq * 256;
    const uint32_t kB0 = smb + ASK0 + (h * 32 + kr) * 256;
    const uint32_t kB1 = smb + ASK1 + (h * 32 + kr) * 256;
    const uint32_t vB0 = smb + ASV0 + (h * 32 + kr) * 256;
    const uint32_t vB1 = smb + ASV1 + (h * 32 + kr) * 256;
    const int barid = wm + 1;

    float O0[4][4], O1[4][4];
#pragma unroll
    for (int n = 0; n < 4; n++)
#pragma unroll
        for (int c = 0; c < 4; c++) { O0[n][c] = 0.f; O1[n][c] = 0.f; }
    float z0[2] = {0.f, 0.f}, z1[2] = {0.f, 0.f}, dt[2] = {0.f, 0.f};

    for (int jt = 0; jt < 16; jt++) {
        CPWAIT(0);
        __syncthreads();

        // ---------- QK branch 0 ----------
        float acc[4][4], e0r[4][4];
#pragma unroll
        for (int n = 0; n < 4; n++)
#pragma unroll
            for (int c = 0; c < 4; c++) acc[n][c] = 0.f;
#pragma unroll
        for (int ks = 0; ks < 8; ks++) {
            uint32_t a0, a1, a2, a3;
            ldsm4(a0, a1, a2, a3, qA0 + (((ks * 2 + agsel) * 16) ^ asw));
#pragma unroll
            for (int j2 = 0; j2 < 2; j2++) {
                uint32_t b0, b1, b2, b3;
                ldsm4(b0, b1, b2, b3, kB0 + j2 * 16 * 256 + (((ks * 2 + bgsel) * 16) ^ ksw));
                mma8(acc[2 * j2],     a0, a1, a2, a3, b0, b1);
                mma8(acc[2 * j2 + 1], a0, a1, a2, a3, b2, b3);
            }
        }
        // exp0 (FMA path): keep in regs + stage to E
#pragma unroll
        for (int nt = 0; nt < 4; nt++) {
            float ea = fexp20(acc[nt][0]);
            float eb = fexp20(acc[nt][1]);
            float ec = fexp20(acc[nt][2]);
            float ed = fexp20(acc[nt][3]);
            e0r[nt][0] = ea; e0r[nt][1] = eb; e0r[nt][2] = ec; e0r[nt][3] = ed;
            z0[0] += ea + eb; z0[1] += ec + ed;
            int off = ((2 * nt + tg2) * 16) ^ esw;
            *(float2*)(e1p + off) = make_float2(ea, eb);
            *(float2*)(e2p + off) = make_float2(ec, ed);
        }
        PAIRBAR(barid);          // pair's E0 rows complete
        // ---------- AV branch 0 ----------
#pragma unroll
        for (int ks = 0; ks < 8; ks++) {
            uint32_t a0, a1, a2, a3;
            ldsm4(a0, a1, a2, a3, eA + (((ks * 2 + agsel) * 16) ^ asw));
#pragma unroll
            for (int j2 = 0; j2 < 2; j2++) {
                uint32_t b0, b1, b2, b3;
                ldsm4(b0, b1, b2, b3, vB0 + j2 * 16 * 256 + (((ks * 2 + bgsel) * 16) ^ ksw));
                mma8(O0[2 * j2],     a0, a1, a2, a3, b0, b1);
                mma8(O0[2 * j2 + 1], a0, a1, a2, a3, b2, b3);
            }
        }
        // ---------- QK branch 1 ----------
#pragma unroll
        for (int n = 0; n < 4; n++)
#pragma unroll
            for (int c = 0; c < 4; c++) acc[n][c] = 0.f;
#pragma unroll
        for (int ks = 0; ks < 8; ks++) {
            uint32_t a0, a1, a2, a3;
            ldsm4(a0, a1, a2, a3, qA1 + (((ks * 2 + agsel) * 16) ^ asw));
#pragma unroll
            for (int j2 = 0; j2 < 2; j2++) {
                uint32_t b0, b1, b2, b3;
                ldsm4(b0, b1, b2, b3, kB1 + j2 * 16 * 256 + (((ks * 2 + bgsel) * 16) ^ ksw));
                mma8(acc[2 * j2],     a0, a1, a2, a3, b0, b1);
                mma8(acc[2 * j2 + 1], a0, a1, a2, a3, b2, b3);
            }
        }
        PAIRBAR(barid);          // pair finished AV0's E reads
        // exp1 + overlap dot (register e0) + stage E1
#pragma unroll
        for (int nt = 0; nt < 4; nt++) {
            float ea = fexp20(acc[nt][0]);
            float eb = fexp20(acc[nt][1]);
            float ec = fexp20(acc[nt][2]);
            float ed = fexp20(acc[nt][3]);
            z1[0] += ea + eb; z1[1] += ec + ed;
            dt[0] += e0r[nt][0] * ea + e0r[nt][1] * eb;
            dt[1] += e0r[nt][2] * ec + e0r[nt][3] * ed;
            int off = ((2 * nt + tg2) * 16) ^ esw;
            *(float2*)(e1p + off) = make_float2(ea, eb);
            *(float2*)(e2p + off) = make_float2(ec, ed);
        }
        PAIRBAR(barid);          // pair's E1 rows complete
        // ---------- AV branch 1 ----------
#pragma unroll
        for (int ks = 0; ks < 8; ks++) {
            uint32_t a0, a1, a2, a3;
            ldsm4(a0, a1, a2, a3, eA + (((ks * 2 + agsel) * 16) ^ asw));
#pragma unroll
            for (int j2 = 0; j2 < 2; j2++) {
                uint32_t b0, b1, b2, b3;
                ldsm4(b0, b1, b2, b3, vB1 + j2 * 16 * 256 + (((ks * 2 + bgsel) * 16) ^ ksw));
                mma8(O1[2 * j2],     a0, a1, a2, a3, b0, b1);
                mma8(O1[2 * j2 + 1], a0, a1, a2, a3, b2, b3);
            }
        }
        __syncthreads();         // all warps done with this jt's K/V before overwrite
        if (jt < 15) {
            int j0 = (jt + 1) * 64;
            issue_kv(smb, ASK0, ASV0, Kg0, Vt0, j0, tid);
            issue_kv(smb, ASK1, ASV1, Kg1, Vt1, j0, tid);
            CPCOMMIT();
        }
    }

    // ---------- epilogue: quad-reduce, pair-combine z/dt, constants, store ---
#pragma unroll
    for (int hh2 = 0; hh2 < 2; hh2++) {
        z0[hh2] += __shfl_xor_sync(0xffffffffu, z0[hh2], 1); z0[hh2] += __shfl_xor_sync(0xffffffffu, z0[hh2], 2);
        z1[hh2] += __shfl_xor_sync(0xffffffffu, z1[hh2], 1); z1[hh2] += __shfl_xor_sync(0xffffffffu, z1[hh2], 2);
        dt[hh2] += __shfl_xor_sync(0xffffffffu, dt[hh2], 1); dt[hh2] += __shfl_xor_sync(0xffffffffu, dt[hh2], 2);
    }
    const int r1 = wm * 16 + g, r2 = r1 + 8;
    float* zz0 = (float*)(smch + ASE);   // E dead
    float* zz1 = zz0 + 64;
    float* dd  = zz0 + 128;
    if (h == 0 && tig == 0) {
        zz0[r1] = z0[0]; zz0[r2] = z0[1];
        zz1[r1] = z1[0]; zz1[r2] = z1[1];
        dd[r1]  = dt[0]; dd[r2]  = dt[1];
    }
    __syncthreads();
    if (h == 1 && tig == 0) {
        zz0[r1] += z0[0]; zz0[r2] += z0[1];
        zz1[r1] += z1[0]; zz1[r2] += z1[1];
        dd[r1]  += dt[0]; dd[r2]  += dt[1];
    }
    __syncthreads();
    float temp = fminf(fmaxf(*temp_ptr, 0.1f), 5.0f);
    float c0r[2], c1r[2];
#pragma unroll
    for (int hh2 = 0; hh2 < 2; hh2++) {
        int rr = hh2 ? r2 : r1;
        float a = zz0[rr], b = zz1[rr], d = dd[rr];
        float overlap = d / (a * b) + 2.0f * EPSF + 1024.0f * EPSF * EPSF;
        float mask = 1.0f / (1.0f + __expf(overlap * temp));
        float f = mask / (mask + EPSF);
        c0r[hh2] = f / a;
        c1r[hh2] = f / b;
    }
    int bidx = head / 12, hd = head - bidx * 12;
    int n1 = i0 + r1;
    int cb2 = hd * 64 + h * 32 + 2 * tig;
    float* p1a = g_ao[0] + ((size_t)(bidx * 1024 + n1)) * 768 + cb2;
    float* p2a = g_ao[0] + ((size_t)(bidx * 1024 + n1 + 8)) * 768 + cb2;
    float* p1b = g_ao[1] + ((size_t)(bidx * 1024 + n1)) * 768 + cb2;
    float* p2b = g_ao[1] + ((size_t)(bidx * 1024 + n1 + 8)) * 768 + cb2;
#pragma unroll
    for (int nt = 0; nt < 4; nt++) {
        *(float2*)(p1a + nt * 8) = make_float2(rna(O0[nt][0] * c0r[0]), rna(O0[nt][1] * c0r[0]));
        *(float2*)(p2a + nt * 8) = make_float2(rna(O0[nt][2] * c0r[1]), rna(O0[nt][3] * c0r[1]));
        *(float2*)(p1b + nt * 8) = make_float2(rna(O1[nt][0] * c1r[0]), rna(O1[nt][1] * c1r[0]));
        *(float2*)(p2b + nt * 8) = make_float2(rna(O1[nt][2] * c1r[1]), rna(O1[nt][3] * c1r[1]));
    }
}

// ================= 0a) weight transpose pair (+tf32 round) ==================
__global__ __launch_bounds__(256) void k_tr2(const float* __restrict__ in0,
                                             const float* __restrict__ in1,
                                             float* __restrict__ out0,
                                             float* __restrict__ out1, int R, int C) {
    __shared__ float t[32][33];
    const float* in = blockIdx.z ? in1 : in0;
    float* out = blockIdx.z ? out1 : out0;
    int bx = blockIdx.x * 32, by = blockIdx.y * 32;
    int x = threadIdx.x & 31, y = threadIdx.x >> 5;
#pragma unroll
    for (int j = 0; j < 32; j += 8) t[y + j][x] = in[(size_t)(by + y + j) * C + bx + x];
    __syncthreads();
#pragma unroll
    for (int j = 0; j < 32; j += 8) out[(size_t)(bx + y + j) * R + by + x] = rna(t[x][y + j]);
}

// ================= 0b) round x to tf32 ======================================
__global__ __launch_bounds__(256) void k_rx(const float* __restrict__ x,
                                            float* __restrict__ o) {
    int i = blockIdx.x * 256 + threadIdx.x;
    float4 v = ((const float4*)x)[i];
    v.x = rna(v.x); v.y = rna(v.y); v.z = rna(v.z); v.w = rna(v.w);
    ((float4*)o)[i] = v;
}

// ================= 5) LayerNorm over C=768 (both branches via y) ============
__device__ __forceinline__ float blk_reduce(float v, float* smr) {
    const unsigned full = 0xffffffffu;
#pragma unroll
    for (int o = 16; o > 0; o >>= 1) v += __shfl_xor_sync(full, v, o);
    int warp = threadIdx.x >> 5, lane = threadIdx.x & 31;
    if (lane == 0) smr[warp] = v;
    __syncthreads();
    if (warp == 0) {
        float x = (lane < 8) ? smr[lane] : 0.0f;
#pragma unroll
        for (int o = 4; o > 0; o >>= 1) x += __shfl_xor_sync(full, x, o);
        if (lane == 0) smr[0] = x;
    }
    __syncthreads();
    float r = smr[0];
    __syncthreads();
    return r;
}

__global__ __launch_bounds__(256) void k_ln(const float* __restrict__ g0,
                                            const float* __restrict__ b0,
                                            const float* __restrict__ g1,
                                            const float* __restrict__ b1,
                                            float* __restrict__ out) {
    __shared__ float smr[32];
    int br = blockIdx.y;
    int row = blockIdx.x;
    const float* gam = br ? g1 : g0;
    const float* bet = br ? b1 : b0;
    float* o = out + (size_t)br * Mm * Cc;
    const float* x = g_pr[br] + (size_t)row * Cc;
    int t = threadIdx.x;
    float v[3];
#pragma unroll
    for (int i = 0; i < 3; i++) v[i] = x[t + 256 * i];
    float s = v[0] + v[1] + v[2];
    s = blk_reduce(s, smr);
    float mu = s * (1.0f / (float)Cc);
    float ss = 0.0f;
#pragma unroll
    for (int i = 0; i < 3; i++) { float d = v[i] - mu; ss += d * d; }
    ss = blk_reduce(ss, smr);
    float inv = rsqrtf(ss * (1.0f / (float)Cc) + LNEPS);
#pragma unroll
    for (int i = 0; i < 3; i++) {
        int c = t + 256 * i;
        o[(size_t)row * Cc + c] = (v[i] - mu) * inv * gam[c] + bet[c];
    }
}

// ================= launch ==================================================
extern "C" void kernel_launch(void* const* d_in, const int* in_sizes, int n_in,
                              void* d_out, int out_size) {
    const float* x    = (const float*)d_in[0];
    const float* wq0  = (const float*)d_in[1];
    const float* wq1  = (const float*)d_in[2];
    const float* wp0  = (const float*)d_in[3];
    const float* bp0  = (const float*)d_in[4];
    const float* wp1  = (const float*)d_in[5];
    const float* bp1  = (const float*)d_in[6];
    const float* temp = (const float*)d_in[7];
    const float* g0   = (const float*)d_in[8];
    const float* b0   = (const float*)d_in[9];
    const float* g1   = (const float*)d_in[10];
    const float* b1   = (const float*)d_in[11];
    float* out = (float*)d_out;

    static float* wt0 = nullptr; static float* wt1 = nullptr;
    static float* wpt0 = nullptr; static float* wpt1 = nullptr;
    static float* xr = nullptr;
    if (!wt0) {
        cudaGetSymbolAddress((void**)&wt0, g_wt);
        wt1 = wt0 + (size_t)3 * Cc * Cc;
        cudaGetSymbolAddress((void**)&wpt0, g_wpt);
        wpt1 = wpt0 + (size_t)Cc * Cc;
        cudaGetSymbolAddress((void**)&xr, g_xr);
        cudaFuncSetAttribute(k_qkv_mma, cudaFuncAttributeMaxDynamicSharedMemorySize, 65536);
        cudaFuncSetAttribute(k_proj_mma, cudaFuncAttributeMaxDynamicSharedMemorySize, 65536);
        cudaFuncSetAttribute(k_attn, cudaFuncAttributeMaxDynamicSharedMemorySize, A_SMEM);
    }

    dim3 t256(256);
    k_tr2<<<dim3(72, 24, 2), t256>>>(wq0, wq1, wt0, wt1, 768, 2304);
    k_tr2<<<dim3(24, 24, 2), t256>>>(wp0, wp1, wpt0, wpt1, 768, 768);
    k_rx<<<dim3(6144), t256>>>(x, xr);

    k_qkv_mma<<<dim3(18, 64, 2), t256, 65536>>>(xr, wt0, wt1);
    k_attn<<<dim3(16, BHh), t256, A_SMEM>>>(temp);
    k_proj_mma<<<dim3(6, 64, 2), t256, 65536>>>(wpt0, wpt1, bp0, bp1);
    k_ln<<<dim3(Mm, 2), t256>>>(g0, b0, g1, b1, out);
}

// round 12
// speedup vs baseline: 1.5680x; 1.3473x over previous
#include <cuda_runtime.h>
#include <cuda_fp16.h>
#include <cstdint>

#define Bb 8
#define Nn 1024
#define Cc 768
#define Hh 12
#define Dd 64
#define BHh 96
#define Mm 8192
#define SCALEF 0.125f
#define EPSF 1e-8f
#define LNEPS 1e-5f

// ---------------- scratch (device globals) ----------------
__device__ __half g_qh[2][(size_t)BHh*Nn*Dd];
__device__ __half g_kh[2][(size_t)BHh*Nn*Dd];
__device__ float  g_vt[2][(size_t)BHh*Dd*Nn];   // V^T fp32: [head][d][key]
__device__ __half g_aoh[2][(size_t)Mm*Cc];
__device__ float  g_pr[2][(size_t)Mm*Cc];
__device__ __half g_wth[2][(size_t)3*Cc*Cc];    // W_qkv^T fp16
__device__ __half g_wpth[2][(size_t)Cc*Cc];     // W_proj^T fp16
__device__ __half g_xrh[(size_t)Mm*Cc];         // fp16 x

// ---------------- helpers ----------------
__device__ __forceinline__ uint32_t smem_u32(const void* p) {
    uint32_t a;
    asm("{ .reg .u64 t; cvta.to.shared.u64 t, %1; cvt.u32.u64 %0, t; }" : "=r"(a) : "l"(p));
    return a;
}
__device__ __forceinline__ float rna(float x) {
    uint32_t u;
    asm("cvt.rna.tf32.f32 %0, %1;" : "=r"(u) : "f"(x));
    return __uint_as_float(u);
}
// exp(clamp(acc*0.125, -20, 20) - 20), all on FMA/ALU pipes (no MUFU)
__device__ __forceinline__ float fexp20(float acc) {
    const float C1 = 0.125f * 1.4426950408889634f;
    const float C2 = 20.0f * 1.4426950408889634f;
    float y = fmaf(acc, C1, -C2);
    y = fmaxf(y, -2.0f * C2);
    y = fminf(y, 0.0f);
    float t = y + 12582912.0f;
    int ib = __float_as_int(t) - 0x4B400000;
    float f = y - (t - 12582912.0f);
    float p = 1.3333558146e-3f;
    p = fmaf(p, f, 9.6181291076e-3f);
    p = fmaf(p, f, 5.5504108664e-2f);
    p = fmaf(p, f, 2.4022650696e-1f);
    p = fmaf(p, f, 6.9314718056e-1f);
    p = fmaf(p, f, 1.0f);
    return __int_as_float(__float_as_int(p) + (ib << 23));
}
__device__ __forceinline__ void ldsm4(uint32_t& d0, uint32_t& d1, uint32_t& d2, uint32_t& d3, uint32_t a) {
    asm volatile("ldmatrix.sync.aligned.m8n8.x4.shared.b16 {%0,%1,%2,%3}, [%4];"
                 : "=r"(d0), "=r"(d1), "=r"(d2), "=r"(d3) : "r"(a));
}
__device__ __forceinline__ void mma8(float* c, uint32_t a0, uint32_t a1, uint32_t a2, uint32_t a3,
                                     uint32_t b0, uint32_t b1) {
    asm volatile("mma.sync.aligned.m16n8k8.row.col.f32.tf32.tf32.f32 "
                 "{%0,%1,%2,%3},{%4,%5,%6,%7},{%8,%9},{%0,%1,%2,%3};"
                 : "+f"(c[0]), "+f"(c[1]), "+f"(c[2]), "+f"(c[3])
                 : "r"(a0), "r"(a1), "r"(a2), "r"(a3), "r"(b0), "r"(b1));
}
__device__ __forceinline__ void mma16(float* c, uint32_t a0, uint32_t a1, uint32_t a2, uint32_t a3,
                                      uint32_t b0, uint32_t b1) {
    asm volatile("mma.sync.aligned.m16n8k16.row.col.f32.f16.f16.f32 "
                 "{%0,%1,%2,%3},{%4,%5,%6,%7},{%8,%9},{%0,%1,%2,%3};"
                 : "+f"(c[0]), "+f"(c[1]), "+f"(c[2]), "+f"(c[3])
                 : "r"(a0), "r"(a1), "r"(a2), "r"(a3), "r"(b0), "r"(b1));
}
#define CPA16(d, s) asm volatile("cp.async.cg.shared.global [%0], [%1], 16;" :: "r"(d), "l"(s))
#define CPCOMMIT()  asm volatile("cp.async.commit_group;" ::: "memory")
#define CPWAIT(n)   asm volatile("cp.async.wait_group %0;" :: "n"(n) : "memory")
#define PAIRBAR(id) asm volatile("bar.sync %0, 64;" :: "r"(id) : "memory")

// ====== shared fp16-mma mainloop: C[128x128] = A * B^T, K=768, k-chunk 64 ===
// smem: As[2] @0,16384 ; Bs[2] @32768,49152 ; rows = 64 halfs = 128B SW128
__device__ __forceinline__ void gemm_h768(const __half* __restrict__ A,
                                          const __half* __restrict__ Bt,
                                          int by, int bx, uint32_t smb,
                                          float acc[2][8][4]) {
    const int tid = threadIdx.x, lane = tid & 31, wid = tid >> 5;
    const int wm = wid >> 1, wn = wid & 1;
    uint32_t dA[4], dB[4];
    const __half* sA[4];
    const __half* sB[4];
#pragma unroll
    for (int j = 0; j < 4; j++) {
        int e = tid + 256 * j;
        int m = e >> 3, kg = e & 7;
        uint32_t sw = (uint32_t)(m * 128 + ((kg * 16) ^ ((m & 7) << 4)));
        dA[j] = smb + sw;
        dB[j] = smb + 32768u + sw;
        sA[j] = A + (size_t)(by + m) * 768 + kg * 8;
        sB[j] = Bt + (size_t)(bx + m) * 768 + kg * 8;
    }
#pragma unroll
    for (int i = 0; i < 2; i++)
#pragma unroll
        for (int n = 0; n < 8; n++)
#pragma unroll
            for (int c = 0; c < 4; c++) acc[i][n][c] = 0.0f;

#pragma unroll
    for (int j = 0; j < 4; j++) { CPA16(dA[j], sA[j]); CPA16(dB[j], sB[j]); }
    CPCOMMIT();

    const int al = lane & 15, seg0 = lane >> 4;
    const int aswz = (al & 7) << 4;

    for (int it = 0; it < 12; ++it) {
        if (it + 1 < 12) {
            int kc = (it + 1) * 64;
            uint32_t ob = ((it + 1) & 1) ? 16384u : 0u;
#pragma unroll
            for (int j = 0; j < 4; j++) { CPA16(dA[j] + ob, sA[j] + kc); CPA16(dB[j] + ob, sB[j] + kc); }
        }
        CPCOMMIT();
        CPWAIT(1);
        __syncthreads();
        uint32_t Ab = smb + ((it & 1) ? 16384u : 0u);
        uint32_t Bbf = smb + 32768u + ((it & 1) ? 16384u : 0u);
#pragma unroll
        for (int kk = 0; kk < 4; kk++) {
            int soff = (2 * kk + seg0) * 16;
            uint32_t a[2][4];
#pragma unroll
            for (int mt = 0; mt < 2; mt++) {
                int r = wm * 32 + mt * 16 + al;
                ldsm4(a[mt][0], a[mt][1], a[mt][2], a[mt][3],
                      Ab + r * 128 + (soff ^ aswz));
            }
#pragma unroll
            for (int j2 = 0; j2 < 4; j2++) {
                int r = wn * 64 + j2 * 16 + al;
                uint32_t b0, b1, b2, b3;
                ldsm4(b0, b1, b2, b3, Bbf + r * 128 + (soff ^ aswz));
#pragma unroll
                for (int mt = 0; mt < 2; mt++) {
                    mma16(acc[mt][2 * j2],     a[mt][0], a[mt][1], a[mt][2], a[mt][3], b0, b2);
                    mma16(acc[mt][2 * j2 + 1], a[mt][0], a[mt][1], a[mt][2], a[mt][3], b1, b3);
                }
            }
        }
        __syncthreads();
    }
}

// ================= 1) qkv GEMM (fp16) + scatter =============================
__global__ __launch_bounds__(256, 2) void k_qkv_mma(const __half* __restrict__ X,
                                                    const __half* __restrict__ Wt0,
                                                    const __half* __restrict__ Wt1) {
    extern __shared__ char smch[];
    uint32_t smb = smem_u32(smch);
    int br = blockIdx.z;
    const __half* Wt = br ? Wt1 : Wt0;
    int bx = blockIdx.x * 128, by = blockIdx.y * 128;
    float acc[2][8][4];
    gemm_h768(X, Wt, by, bx, smb, acc);

    int lane = threadIdx.x & 31, wid = threadIdx.x >> 5;
    int wm = wid >> 1, wn = wid & 1, g = lane >> 2, tig = lane & 3;
    int colbase = bx + wn * 64;
    int seg = colbase >> 6;
    int three = seg / 12, hseg = seg - three * 12;
    if (three == 2) {
        // V: write transposed fp32 [head][d][key]
#pragma unroll
        for (int mt = 0; mt < 2; mt++) {
            int m1 = by + wm * 32 + mt * 16 + g;
            int b1 = m1 >> 10, n1 = m1 & 1023;
            float* vt = g_vt[br] + ((size_t)(b1 * 12 + hseg)) * 65536;
#pragma unroll
            for (int nt = 0; nt < 8; nt++) {
                int d0 = nt * 8 + 2 * tig;
                vt[(size_t)d0 * 1024 + n1]           = rna(acc[mt][nt][0]);
                vt[(size_t)(d0 + 1) * 1024 + n1]     = rna(acc[mt][nt][1]);
                vt[(size_t)d0 * 1024 + n1 + 8]       = rna(acc[mt][nt][2]);
                vt[(size_t)(d0 + 1) * 1024 + n1 + 8] = rna(acc[mt][nt][3]);
            }
        }
    } else {
        __half* base3 = (three == 0) ? g_qh[br] : g_kh[br];
#pragma unroll
        for (int mt = 0; mt < 2; mt++) {
            int m1 = by + wm * 32 + mt * 16 + g;
            int b1 = m1 >> 10, n1 = m1 & 1023;
            __half* p1 = base3 + (((size_t)(b1 * 12 + hseg)) * 1024 + n1) * 64 + 2 * tig;
            __half* p2 = p1 + (size_t)8 * 64;
#pragma unroll
            for (int nt = 0; nt < 8; nt++) {
                *(half2*)(p1 + nt * 8) = __floats2half2_rn(acc[mt][nt][0], acc[mt][nt][1]);
                *(half2*)(p2 + nt * 8) = __floats2half2_rn(acc[mt][nt][2], acc[mt][nt][3]);
            }
        }
    }
}

// ================= 2) proj GEMM (fp16) + bias ================================
__global__ __launch_bounds__(256, 2) void k_proj_mma(const __half* __restrict__ Wt0,
                                                     const __half* __restrict__ Wt1,
                                                     const float* __restrict__ bias0,
                                                     const float* __restrict__ bias1) {
    extern __shared__ char smch[];
    uint32_t smb = smem_u32(smch);
    int br = blockIdx.z;
    const __half* Wt = br ? Wt1 : Wt0;
    const float* bias = br ? bias1 : bias0;
    int bx = blockIdx.x * 128, by = blockIdx.y * 128;
    float acc[2][8][4];
    gemm_h768(g_aoh[br], Wt, by, bx, smb, acc);

    int lane = threadIdx.x & 31, wid = threadIdx.x >> 5;
    int wm = wid >> 1, wn = wid & 1, g = lane >> 2, tig = lane & 3;
    int colbase = bx + wn * 64;
#pragma unroll
    for (int mt = 0; mt < 2; mt++) {
        int m1 = by + wm * 32 + mt * 16 + g;
        float* p1 = g_pr[br] + (size_t)m1 * 768 + colbase + 2 * tig;
        float* p2 = p1 + (size_t)8 * 768;
#pragma unroll
        for (int nt = 0; nt < 8; nt++) {
            float2 bv = *(const float2*)(bias + colbase + nt * 8 + 2 * tig);
            *(float2*)(p1 + nt * 8) = make_float2(acc[mt][nt][0] + bv.x, acc[mt][nt][1] + bv.y);
            *(float2*)(p2 + nt * 8) = make_float2(acc[mt][nt][2] + bv.x, acc[mt][nt][3] + bv.y);
        }
    }
}

// ====== 3) FUSED attention: QK fp16 k16, AV tf32; occ 2 =====================
// smem: Q0 @0 (8K) Q1 @8192 | K0 @16384 (8K) K1 @24576 |
//       V0 @32768 (16K fp32) V1 @49152 | E @65536 (16K fp32)  -> 80KB, occ 2
#define ASQ1 8192u
#define ASK0 16384u
#define ASK1 24576u
#define ASV0 32768u
#define ASV1 49152u
#define ASE  65536u
#define A_SMEM 81920

__device__ __forceinline__ void issue_kv(uint32_t smb, uint32_t sko, uint32_t svo,
                                         const __half* __restrict__ Kg,
                                         const float* __restrict__ Vt,
                                         int j0, int tid) {
    // K: 64 key rows x 128B (64 halfs)
#pragma unroll
    for (int jj = 0; jj < 2; jj++) {
        int e = tid + 256 * jj;
        int n = e >> 3, kg = e & 7;
        CPA16(smb + sko + n * 128 + ((kg * 16) ^ ((n & 7) << 4)),
              Kg + (size_t)(j0 + n) * 64 + kg * 8);
    }
    // V^T: 64 d rows x 256B (64 floats of keys)
#pragma unroll
    for (int jj = 0; jj < 4; jj++) {
        int e = tid + 256 * jj;
        int n = e >> 4, kg = e & 15;
        CPA16(smb + svo + n * 256 + ((kg * 16) ^ ((n & 7) << 4)),
              Vt + (size_t)n * 1024 + j0 + kg * 4);
    }
}

__global__ __launch_bounds__(256, 2) void k_attn(const float* __restrict__ temp_ptr) {
    extern __shared__ char smch[];
    uint32_t smb = smem_u32(smch);
    const int head = blockIdx.y, i0 = blockIdx.x * 64;
    const int tid = threadIdx.x, lane = tid & 31, wid = tid >> 5;
    const int wm = wid & 3, h = wid >> 2;
    const __half* Qh0 = g_qh[0] + (size_t)head * 65536;
    const __half* Qh1 = g_qh[1] + (size_t)head * 65536;
    const __half* Kh0 = g_kh[0] + (size_t)head * 65536;
    const __half* Kh1 = g_kh[1] + (size_t)head * 65536;
    const float* Vt0 = g_vt[0] + (size_t)head * 65536;
    const float* Vt1 = g_vt[1] + (size_t)head * 65536;

    // persistent Q (both branches, fp16 128B rows) + first KV
#pragma unroll
    for (int j = 0; j < 4; j++) {
        int e = tid + 256 * j;
        int br = e >> 9, r = e & 511;
        int n = r >> 3, kg = r & 7;
        uint32_t dst = smb + (uint32_t)(br ? ASQ1 : 0u) + n * 128 + ((kg * 16) ^ ((n & 7) << 4));
        const __half* src = (br ? Qh1 : Qh0) + (size_t)(i0 + n) * 64 + kg * 8;
        CPA16(dst, src);
    }
    issue_kv(smb, ASK0, ASV0, Kh0, Vt0, 0, tid);
    issue_kv(smb, ASK1, ASV1, Kh1, Vt1, 0, tid);
    CPCOMMIT();

    // fp16 QK fragment indices
    const int al = lane & 15, seg0 = lane >> 4;
    const int aswz = (al & 7) << 4;
    const uint32_t qA0 = smb + (wm * 16 + al) * 128;
    const uint32_t qA1 = smb + ASQ1 + (wm * 16 + al) * 128;
    const uint32_t kB0 = smb + ASK0 + (h * 32 + al) * 128;
    const uint32_t kB1 = smb + ASK1 + (h * 32 + al) * 128;
    // tf32 AV fragment indices (same as R11)
    const int agsel = lane >> 4, bgsel = (lane >> 3) & 1;
    const int ar2 = ((lane >> 3) & 1) * 8 + (lane & 7);
    const int arq = wm * 16 + ar2;
    const int asw = (ar2 & 7) << 4;
    const int kr = ((lane >> 4) & 1) * 8 + (lane & 7);
    const int ksw = (kr & 7) << 4;
    const int g = lane >> 2, tig = lane & 3;
    const int esw = (g & 7) << 4;
    const int tg2 = tig >> 1;
    char* e1p = smch + ASE + (wm * 16 + g) * 256 + h * 128 + (tig & 1) * 8;
    char* e2p = e1p + 8 * 256;
    const uint32_t eA  = smb + ASE + arq * 256;
    const uint32_t vB0 = smb + ASV0 + (h * 32 + kr) * 256;
    const uint32_t vB1 = smb + ASV1 + (h * 32 + kr) * 256;
    const int barid = wm + 1;

    float O0[4][4], O1[4][4];
#pragma unroll
    for (int n = 0; n < 4; n++)
#pragma unroll
        for (int c = 0; c < 4; c++) { O0[n][c] = 0.f; O1[n][c] = 0.f; }
    float z0[2] = {0.f, 0.f}, z1[2] = {0.f, 0.f}, dt[2] = {0.f, 0.f};

    for (int jt = 0; jt < 16; jt++) {
        CPWAIT(0);
        __syncthreads();

        // ---------- QK branch 0 (fp16 k16) ----------
        float acc[4][4], e0r[4][4];
#pragma unroll
        for (int n = 0; n < 4; n++)
#pragma unroll
            for (int c = 0; c < 4; c++) acc[n][c] = 0.f;
#pragma unroll
        for (int kk = 0; kk < 4; kk++) {
            int soff = ((2 * kk + seg0) * 16) ^ aswz;
            uint32_t a0, a1, a2, a3;
            ldsm4(a0, a1, a2, a3, qA0 + soff);
#pragma unroll
            for (int j2 = 0; j2 < 2; j2++) {
                uint32_t b0, b1, b2, b3;
                ldsm4(b0, b1, b2, b3, kB0 + j2 * 16 * 128 + soff);
                mma16(acc[2 * j2],     a0, a1, a2, a3, b0, b2);
                mma16(acc[2 * j2 + 1], a0, a1, a2, a3, b1, b3);
            }
        }
        // exp0: regs + stage to E
#pragma unroll
        for (int nt = 0; nt < 4; nt++) {
            float ea = fexp20(acc[nt][0]);
            float eb = fexp20(acc[nt][1]);
            float ec = fexp20(acc[nt][2]);
            float ed = fexp20(acc[nt][3]);
            e0r[nt][0] = ea; e0r[nt][1] = eb; e0r[nt][2] = ec; e0r[nt][3] = ed;
            z0[0] += ea + eb; z0[1] += ec + ed;
            int off = ((2 * nt + tg2) * 16) ^ esw;
            *(float2*)(e1p + off) = make_float2(ea, eb);
            *(float2*)(e2p + off) = make_float2(ec, ed);
        }
        PAIRBAR(barid);
        // ---------- AV branch 0 (tf32) ----------
#pragma unroll
        for (int ks = 0; ks < 8; ks++) {
            uint32_t a0, a1, a2, a3;
            ldsm4(a0, a1, a2, a3, eA + (((ks * 2 + agsel) * 16) ^ asw));
#pragma unroll
            for (int j2 = 0; j2 < 2; j2++) {
                uint32_t b0, b1, b2, b3;
                ldsm4(b0, b1, b2, b3, vB0 + j2 * 16 * 256 + (((ks * 2 + bgsel) * 16) ^ ksw));
                mma8(O0[2 * j2],     a0, a1, a2, a3, b0, b1);
                mma8(O0[2 * j2 + 1], a0, a1, a2, a3, b2, b3);
            }
        }
        // ---------- QK branch 1 (fp16) ----------
#pragma unroll
        for (int n = 0; n < 4; n++)
#pragma unroll
            for (int c = 0; c < 4; c++) acc[n][c] = 0.f;
#pragma unroll
        for (int kk = 0; kk < 4; kk++) {
            int soff = ((2 * kk + seg0) * 16) ^ aswz;
            uint32_t a0, a1, a2, a3;
            ldsm4(a0, a1, a2, a3, qA1 + soff);
#pragma unroll
            for (int j2 = 0; j2 < 2; j2++) {
                uint32_t b0, b1, b2, b3;
                ldsm4(b0, b1, b2, b3, kB1 + j2 * 16 * 128 + soff);
                mma16(acc[2 * j2],     a0, a1, a2, a3, b0, b2);
                mma16(acc[2 * j2 + 1], a0, a1, a2, a3, b1, b3);
            }
        }
        PAIRBAR(barid);          // pair finished AV0's E reads
        // exp1 + overlap dot (register e0) + stage E1
#pragma unroll
        for (int nt = 0; nt < 4; nt++) {
            float ea = fexp20(acc[nt][0]);
            float eb = fexp20(acc[nt][1]);
            float ec = fexp20(acc[nt][2]);
            float ed = fexp20(acc[nt][3]);
            z1[0] += ea + eb; z1[1] += ec + ed;
            dt[0] += e0r[nt][0] * ea + e0r[nt][1] * eb;
            dt[1] += e0r[nt][2] * ec + e0r[nt][3] * ed;
            int off = ((2 * nt + tg2) * 16) ^ esw;
            *(float2*)(e1p + off) = make_float2(ea, eb);
            *(float2*)(e2p + off) = make_float2(ec, ed);
        }
        PAIRBAR(barid);
        // ---------- AV branch 1 (tf32) ----------
#pragma unroll
        for (int ks = 0; ks < 8; ks++) {
            uint32_t a0, a1, a2, a3;
            ldsm4(a0, a1, a2, a3, eA + (((ks * 2 + agsel) * 16) ^ asw));
#pragma unroll
            for (int j2 = 0; j2 < 2; j2++) {
                uint32_t b0, b1, b2, b3;
                ldsm4(b0, b1, b2, b3, vB1 + j2 * 16 * 256 + (((ks * 2 + bgsel) * 16) ^ ksw));
                mma8(O1[2 * j2],     a0, a1, a2, a3, b0, b1);
                mma8(O1[2 * j2 + 1], a0, a1, a2, a3, b2, b3);
            }
        }
        __syncthreads();
        if (jt < 15) {
            int j0 = (jt + 1) * 64;
            issue_kv(smb, ASK0, ASV0, Kh0, Vt0, j0, tid);
            issue_kv(smb, ASK1, ASV1, Kh1, Vt1, j0, tid);
            CPCOMMIT();
        }
    }

    // ---------- epilogue ----------
#pragma unroll
    for (int hh2 = 0; hh2 < 2; hh2++) {
        z0[hh2] += __shfl_xor_sync(0xffffffffu, z0[hh2], 1); z0[hh2] += __shfl_xor_sync(0xffffffffu, z0[hh2], 2);
        z1[hh2] += __shfl_xor_sync(0xffffffffu, z1[hh2], 1); z1[hh2] += __shfl_xor_sync(0xffffffffu, z1[hh2], 2);
        dt[hh2] += __shfl_xor_sync(0xffffffffu, dt[hh2], 1); dt[hh2] += __shfl_xor_sync(0xffffffffu, dt[hh2], 2);
    }
    const int r1 = wm * 16 + g, r2 = r1 + 8;
    float* zz0 = (float*)(smch + ASE);   // E dead
    float* zz1 = zz0 + 64;
    float* dd  = zz0 + 128;
    if (h == 0 && tig == 0) {
        zz0[r1] = z0[0]; zz0[r2] = z0[1];
        zz1[r1] = z1[0]; zz1[r2] = z1[1];
        dd[r1]  = dt[0]; dd[r2]  = dt[1];
    }
    __syncthreads();
    if (h == 1 && tig == 0) {
        zz0[r1] += z0[0]; zz0[r2] += z0[1];
        zz1[r1] += z1[0]; zz1[r2] += z1[1];
        dd[r1]  += dt[0]; dd[r2]  += dt[1];
    }
    __syncthreads();
    float temp = fminf(fmaxf(*temp_ptr, 0.1f), 5.0f);
    float c0r[2], c1r[2];
#pragma unroll
    for (int hh2 = 0; hh2 < 2; hh2++) {
        int rr = hh2 ? r2 : r1;
        float a = zz0[rr], b = zz1[rr], d = dd[rr];
        float overlap = d / (a * b) + 2.0f * EPSF + 1024.0f * EPSF * EPSF;
        float mask = 1.0f / (1.0f + __expf(overlap * temp));
        float f = mask / (mask + EPSF);
        c0r[hh2] = f / a;
        c1r[hh2] = f / b;
    }
    int bidx = head / 12, hd = head - bidx * 12;
    int n1 = i0 + r1;
    int cb2 = hd * 64 + h * 32 + 2 * tig;
    __half* p1a = g_aoh[0] + ((size_t)(bidx * 1024 + n1)) * 768 + cb2;
    __half* p2a = g_aoh[0] + ((size_t)(bidx * 1024 + n1 + 8)) * 768 + cb2;
    __half* p1b = g_aoh[1] + ((size_t)(bidx * 1024 + n1)) * 768 + cb2;
    __half* p2b = g_aoh[1] + ((size_t)(bidx * 1024 + n1 + 8)) * 768 + cb2;
#pragma unroll
    for (int nt = 0; nt < 4; nt++) {
        *(half2*)(p1a + nt * 8) = __floats2half2_rn(O0[nt][0] * c0r[0], O0[nt][1] * c0r[0]);
        *(half2*)(p2a + nt * 8) = __floats2half2_rn(O0[nt][2] * c0r[1], O0[nt][3] * c0r[1]);
        *(half2*)(p1b + nt * 8) = __floats2half2_rn(O1[nt][0] * c1r[0], O1[nt][1] * c1r[0]);
        *(half2*)(p2b + nt * 8) = __floats2half2_rn(O1[nt][2] * c1r[1], O1[nt][3] * c1r[1]);
    }
}

// ================= 0a) weight transpose pair -> fp16 ========================
__global__ __launch_bounds__(256) void k_tr2h(const float* __restrict__ in0,
                                              const float* __restrict__ in1,
                                              __half* __restrict__ out0,
                                              __half* __restrict__ out1, int R, int C) {
    __shared__ float t[32][33];
    const float* in = blockIdx.z ? in1 : in0;
    __half* out = blockIdx.z ? out1 : out0;
    int bx = blockIdx.x * 32, by = blockIdx.y * 32;
    int x = threadIdx.x & 31, y = threadIdx.x >> 5;
#pragma unroll
    for (int j = 0; j < 32; j += 8) t[y + j][x] = in[(size_t)(by + y + j) * C + bx + x];
    __syncthreads();
#pragma unroll
    for (int j = 0; j < 32; j += 8) out[(size_t)(bx + y + j) * R + by + x] = __float2half_rn(t[x][y + j]);
}

// ================= 0b) x -> fp16 ============================================
__global__ __launch_bounds__(256) void k_rxh(const float* __restrict__ x,
                                             __half* __restrict__ o) {
    int i = blockIdx.x * 256 + threadIdx.x;
    float4 v = ((const float4*)x)[i];
    ((half2*)o)[2 * i]     = __floats2half2_rn(v.x, v.y);
    ((half2*)o)[2 * i + 1] = __floats2half2_rn(v.z, v.w);
}

// ================= 5) LayerNorm over C=768 (both branches via y) ============
__device__ __forceinline__ float blk_reduce(float v, float* smr) {
    const unsigned full = 0xffffffffu;
#pragma unroll
    for (int o = 16; o > 0; o >>= 1) v += __shfl_xor_sync(full, v, o);
    int warp = threadIdx.x >> 5, lane = threadIdx.x & 31;
    if (lane == 0) smr[warp] = v;
    __syncthreads();
    if (warp == 0) {
        float x = (lane < 8) ? smr[lane] : 0.0f;
#pragma unroll
        for (int o = 4; o > 0; o >>= 1) x += __shfl_xor_sync(full, x, o);
        if (lane == 0) smr[0] = x;
    }
    __syncthreads();
    float r = smr[0];
    __syncthreads();
    return r;
}

__global__ __launch_bounds__(256) void k_ln(const float* __restrict__ g0,
                                            const float* __restrict__ b0,
                                            const float* __restrict__ g1,
                                            const float* __restrict__ b1,
                                            float* __restrict__ out) {
    __shared__ float smr[32];
    int br = blockIdx.y;
    int row = blockIdx.x;
    const float* gam = br ? g1 : g0;
    const float* bet = br ? b1 : b0;
    float* o = out + (size_t)br * Mm * Cc;
    const float* x = g_pr[br] + (size_t)row * Cc;
    int t = threadIdx.x;
    float v[3];
#pragma unroll
    for (int i = 0; i < 3; i++) v[i] = x[t + 256 * i];
    float s = v[0] + v[1] + v[2];
    s = blk_reduce(s, smr);
    float mu = s * (1.0f / (float)Cc);
    float ss = 0.0f;
#pragma unroll
    for (int i = 0; i < 3; i++) { float d = v[i] - mu; ss += d * d; }
    ss = blk_reduce(ss, smr);
    float inv = rsqrtf(ss * (1.0f / (float)Cc) + LNEPS);
#pragma unroll
    for (int i = 0; i < 3; i++) {
        int c = t + 256 * i;
        o[(size_t)row * Cc + c] = (v[i] - mu) * inv * gam[c] + bet[c];
    }
}

// ================= launch ==================================================
extern "C" void kernel_launch(void* const* d_in, const int* in_sizes, int n_in,
                              void* d_out, int out_size) {
    const float* x    = (const float*)d_in[0];
    const float* wq0  = (const float*)d_in[1];
    const float* wq1  = (const float*)d_in[2];
    const float* wp0  = (const float*)d_in[3];
    const float* bp0  = (const float*)d_in[4];
    const float* wp1  = (const float*)d_in[5];
    const float* bp1  = (const float*)d_in[6];
    const float* temp = (const float*)d_in[7];
    const float* g0   = (const float*)d_in[8];
    const float* b0   = (const float*)d_in[9];
    const float* g1   = (const float*)d_in[10];
    const float* b1   = (const float*)d_in[11];
    float* out = (float*)d_out;

    static __half* wt0 = nullptr; static __half* wt1 = nullptr;
    static __half* wpt0 = nullptr; static __half* wpt1 = nullptr;
    static __half* xr = nullptr;
    if (!wt0) {
        cudaGetSymbolAddress((void**)&wt0, g_wth);
        wt1 = wt0 + (size_t)3 * Cc * Cc;
        cudaGetSymbolAddress((void**)&wpt0, g_wpth);
        wpt1 = wpt0 + (size_t)Cc * Cc;
        cudaGetSymbolAddress((void**)&xr, g_xrh);
        cudaFuncSetAttribute(k_qkv_mma, cudaFuncAttributeMaxDynamicSharedMemorySize, 65536);
        cudaFuncSetAttribute(k_proj_mma, cudaFuncAttributeMaxDynamicSharedMemorySize, 65536);
        cudaFuncSetAttribute(k_attn, cudaFuncAttributeMaxDynamicSharedMemorySize, A_SMEM);
    }

    dim3 t256(256);
    k_tr2h<<<dim3(72, 24, 2), t256>>>(wq0, wq1, wt0, wt1, 768, 2304);
    k_tr2h<<<dim3(24, 24, 2), t256>>>(wp0, wp1, wpt0, wpt1, 768, 768);
    k_rxh<<<dim3(6144), t256>>>(x, xr);

    k_qkv_mma<<<dim3(18, 64, 2), t256, 65536>>>(xr, wt0, wt1);
    k_attn<<<dim3(16, BHh), t256, A_SMEM>>>(temp);
    k_proj_mma<<<dim3(6, 64, 2), t256, 65536>>>(wpt0, wpt1, bp0, bp1);
    k_ln<<<dim3(Mm, 2), t256>>>(g0, b0, g1, b1, out);
}

// round 14
// speedup vs baseline: 1.8707x; 1.1931x over previous
#include <cuda_runtime.h>
#include <cuda_fp16.h>
#include <cstdint>

#define Bb 8
#define Nn 1024
#define Cc 768
#define Hh 12
#define Dd 64
#define BHh 96
#define Mm 8192
#define SCALEF 0.125f
#define EPSF 1e-8f
#define LNEPS 1e-5f

// ---------------- scratch (device globals) ----------------
__device__ __half g_qh[2][(size_t)BHh*Nn*Dd];
__device__ __half g_kh[2][(size_t)BHh*Nn*Dd];
__device__ __half g_vth[2][(size_t)BHh*Dd*Nn];  // V^T fp16: [head][d][key]
__device__ __half g_aoh[2][(size_t)Mm*Cc];
__device__ float  g_pr[2][(size_t)Mm*Cc];
__device__ __half g_wth[2][(size_t)3*Cc*Cc];
__device__ __half g_wpth[2][(size_t)Cc*Cc];
__device__ __half g_xrh[(size_t)Mm*Cc];

// ---------------- helpers ----------------
__device__ __forceinline__ uint32_t smem_u32(const void* p) {
    uint32_t a;
    asm("{ .reg .u64 t; cvta.to.shared.u64 t, %1; cvt.u32.u64 %0, t; }" : "=r"(a) : "l"(p));
    return a;
}
// exp(clamp(acc*0.125, -20, 20) - 8), FMA/ALU pipes only. Range [e^-28, e^12].
__device__ __forceinline__ float fexp8(float acc) {
    const float L2E = 1.4426950408889634f;
    const float C1 = 0.125f * L2E;
    float y = fmaf(acc, C1, -8.0f * L2E);
    y = fmaxf(y, -28.0f * L2E);
    y = fminf(y, 12.0f * L2E);
    float t = y + 12582912.0f;
    int ib = __float_as_int(t) - 0x4B400000;
    float f = y - (t - 12582912.0f);
    float p = 1.3333558146e-3f;
    p = fmaf(p, f, 9.6181291076e-3f);
    p = fmaf(p, f, 5.5504108664e-2f);
    p = fmaf(p, f, 2.4022650696e-1f);
    p = fmaf(p, f, 6.9314718056e-1f);
    p = fmaf(p, f, 1.0f);
    return __int_as_float(__float_as_int(p) + (ib << 23));
}
__device__ __forceinline__ uint32_t pack_h2(float lo, float hi) {
    // clamp to avoid fp16 inf if data ever reached the +20 clip
    half2 h = __floats2half2_rn(fminf(lo, 60000.f), fminf(hi, 60000.f));
    return *(uint32_t*)&h;
}
__device__ __forceinline__ void ldsm4(uint32_t& d0, uint32_t& d1, uint32_t& d2, uint32_t& d3, uint32_t a) {
    asm volatile("ldmatrix.sync.aligned.m8n8.x4.shared.b16 {%0,%1,%2,%3}, [%4];"
                 : "=r"(d0), "=r"(d1), "=r"(d2), "=r"(d3) : "r"(a));
}
__device__ __forceinline__ void mma16(float* c, uint32_t a0, uint32_t a1, uint32_t a2, uint32_t a3,
                                      uint32_t b0, uint32_t b1) {
    asm volatile("mma.sync.aligned.m16n8k16.row.col.f32.f16.f16.f32 "
                 "{%0,%1,%2,%3},{%4,%5,%6,%7},{%8,%9},{%0,%1,%2,%3};"
                 : "+f"(c[0]), "+f"(c[1]), "+f"(c[2]), "+f"(c[3])
                 : "r"(a0), "r"(a1), "r"(a2), "r"(a3), "r"(b0), "r"(b1));
}
#define CPA16(d, s) asm volatile("cp.async.cg.shared.global [%0], [%1], 16;" :: "r"(d), "l"(s))
#define CPCOMMIT()  asm volatile("cp.async.commit_group;" ::: "memory")
#define CPWAIT(n)   asm volatile("cp.async.wait_group %0;" :: "n"(n) : "memory")
#define PAIRBAR(id) asm volatile("bar.sync %0, 64;" :: "r"(id) : "memory")

// ====== shared fp16-mma mainloop: C[128x128] = A * B^T, K=768, k-chunk 64 ===
__device__ __forceinline__ void gemm_h768(const __half* __restrict__ A,
                                          const __half* __restrict__ Bt,
                                          int by, int bx, uint32_t smb,
                                          float acc[2][8][4]) {
    const int tid = threadIdx.x, lane = tid & 31, wid = tid >> 5;
    const int wm = wid >> 1, wn = wid & 1;
    uint32_t dA[4], dB[4];
    const __half* sA[4];
    const __half* sB[4];
#pragma unroll
    for (int j = 0; j < 4; j++) {
        int e = tid + 256 * j;
        int m = e >> 3, kg = e & 7;
        uint32_t sw = (uint32_t)(m * 128 + ((kg * 16) ^ ((m & 7) << 4)));
        dA[j] = smb + sw;
        dB[j] = smb + 32768u + sw;
        sA[j] = A + (size_t)(by + m) * 768 + kg * 8;
        sB[j] = Bt + (size_t)(bx + m) * 768 + kg * 8;
    }
#pragma unroll
    for (int i = 0; i < 2; i++)
#pragma unroll
        for (int n = 0; n < 8; n++)
#pragma unroll
            for (int c = 0; c < 4; c++) acc[i][n][c] = 0.0f;

#pragma unroll
    for (int j = 0; j < 4; j++) { CPA16(dA[j], sA[j]); CPA16(dB[j], sB[j]); }
    CPCOMMIT();

    const int al = lane & 15, seg0 = lane >> 4;
    const int aswz = (al & 7) << 4;

    for (int it = 0; it < 12; ++it) {
        if (it + 1 < 12) {
            int kc = (it + 1) * 64;
            uint32_t ob = ((it + 1) & 1) ? 16384u : 0u;
#pragma unroll
            for (int j = 0; j < 4; j++) { CPA16(dA[j] + ob, sA[j] + kc); CPA16(dB[j] + ob, sB[j] + kc); }
        }
        CPCOMMIT();
        CPWAIT(1);
        __syncthreads();
        uint32_t Ab = smb + ((it & 1) ? 16384u : 0u);
        uint32_t Bbf = smb + 32768u + ((it & 1) ? 16384u : 0u);
#pragma unroll
        for (int kk = 0; kk < 4; kk++) {
            int soff = (2 * kk + seg0) * 16;
            uint32_t a[2][4];
#pragma unroll
            for (int mt = 0; mt < 2; mt++) {
                int r = wm * 32 + mt * 16 + al;
                ldsm4(a[mt][0], a[mt][1], a[mt][2], a[mt][3],
                      Ab + r * 128 + (soff ^ aswz));
            }
#pragma unroll
            for (int j2 = 0; j2 < 4; j2++) {
                int r = wn * 64 + j2 * 16 + al;
                uint32_t b0, b1, b2, b3;
                ldsm4(b0, b1, b2, b3, Bbf + r * 128 + (soff ^ aswz));
#pragma unroll
                for (int mt = 0; mt < 2; mt++) {
                    mma16(acc[mt][2 * j2],     a[mt][0], a[mt][1], a[mt][2], a[mt][3], b0, b2);
                    mma16(acc[mt][2 * j2 + 1], a[mt][0], a[mt][1], a[mt][2], a[mt][3], b1, b3);
                }
            }
        }
        __syncthreads();
    }
}

// ================= 1) qkv GEMM (fp16) + scatter =============================
__global__ __launch_bounds__(256, 2) void k_qkv_mma(const __half* __restrict__ X,
                                                    const __half* __restrict__ Wt0,
                                                    const __half* __restrict__ Wt1) {
    extern __shared__ char smch[];
    uint32_t smb = smem_u32(smch);
    int br = blockIdx.z;
    const __half* Wt = br ? Wt1 : Wt0;
    int bx = blockIdx.x * 128, by = blockIdx.y * 128;
    float acc[2][8][4];
    gemm_h768(X, Wt, by, bx, smb, acc);

    int lane = threadIdx.x & 31, wid = threadIdx.x >> 5;
    int wm = wid >> 1, wn = wid & 1, g = lane >> 2, tig = lane & 3;
    int colbase = bx + wn * 64;
    int seg = colbase >> 6;
    int three = seg / 12, hseg = seg - three * 12;
    if (three == 2) {
        // V: write transposed fp16 [head][d][key]
#pragma unroll
        for (int mt = 0; mt < 2; mt++) {
            int m1 = by + wm * 32 + mt * 16 + g;
            int b1 = m1 >> 10, n1 = m1 & 1023;
            __half* vt = g_vth[br] + ((size_t)(b1 * 12 + hseg)) * 65536;
#pragma unroll
            for (int nt = 0; nt < 8; nt++) {
                int d0 = nt * 8 + 2 * tig;
                vt[(size_t)d0 * 1024 + n1]           = __float2half_rn(acc[mt][nt][0]);
                vt[(size_t)(d0 + 1) * 1024 + n1]     = __float2half_rn(acc[mt][nt][1]);
                vt[(size_t)d0 * 1024 + n1 + 8]       = __float2half_rn(acc[mt][nt][2]);
                vt[(size_t)(d0 + 1) * 1024 + n1 + 8] = __float2half_rn(acc[mt][nt][3]);
            }
        }
    } else {
        __half* base3 = (three == 0) ? g_qh[br] : g_kh[br];
#pragma unroll
        for (int mt = 0; mt < 2; mt++) {
            int m1 = by + wm * 32 + mt * 16 + g;
            int b1 = m1 >> 10, n1 = m1 & 1023;
            __half* p1 = base3 + (((size_t)(b1 * 12 + hseg)) * 1024 + n1) * 64 + 2 * tig;
            __half* p2 = p1 + (size_t)8 * 64;
#pragma unroll
            for (int nt = 0; nt < 8; nt++) {
                *(half2*)(p1 + nt * 8) = __floats2half2_rn(acc[mt][nt][0], acc[mt][nt][1]);
                *(half2*)(p2 + nt * 8) = __floats2half2_rn(acc[mt][nt][2], acc[mt][nt][3]);
            }
        }
    }
}

// ================= 2) proj GEMM (fp16) + bias ================================
__global__ __launch_bounds__(256, 2) void k_proj_mma(const __half* __restrict__ Wt0,
                                                     const __half* __restrict__ Wt1,
                                                     const float* __restrict__ bias0,
                                                     const float* __restrict__ bias1) {
    extern __shared__ char smch[];
    uint32_t smb = smem_u32(smch);
    int br = blockIdx.z;
    const __half* Wt = br ? Wt1 : Wt0;
    const float* bias = br ? bias1 : bias0;
    int bx = blockIdx.x * 128, by = blockIdx.y * 128;
    float acc[2][8][4];
    gemm_h768(g_aoh[br], Wt, by, bx, smb, acc);

    int lane = threadIdx.x & 31, wid = threadIdx.x >> 5;
    int wm = wid >> 1, wn = wid & 1, g = lane >> 2, tig = lane & 3;
    int colbase = bx + wn * 64;
#pragma unroll
    for (int mt = 0; mt < 2; mt++) {
        int m1 = by + wm * 32 + mt * 16 + g;
        float* p1 = g_pr[br] + (size_t)m1 * 768 + colbase + 2 * tig;
        float* p2 = p1 + (size_t)8 * 768;
#pragma unroll
        for (int nt = 0; nt < 8; nt++) {
            float2 bv = *(const float2*)(bias + colbase + nt * 8 + 2 * tig);
            *(float2*)(p1 + nt * 8) = make_float2(acc[mt][nt][0] + bv.x, acc[mt][nt][1] + bv.y);
            *(float2*)(p2 + nt * 8) = make_float2(acc[mt][nt][2] + bv.x, acc[mt][nt][3] + bv.y);
        }
    }
}

// ====== 3) FUSED attention: QK+AV fp16, double-buffered KV, occ 2 ===========
// smem: Q0 @0 (8K) Q1 @8192 | K0[2] @16384 K1[2] @32768 (8K/buf) |
//       V0[2] @49152 V1[2] @65536 (8K/buf fp16) | E @81920 (8K fp16) -> 88KB
#define ASQ1 8192u
#define ASK0 16384u
#define ASK1 32768u
#define ASV0 49152u
#define ASV1 65536u
#define ASE  81920u
#define A_SMEM 90112

__device__ __forceinline__ void issue_kv(uint32_t smb, uint32_t sko, uint32_t svo,
                                         const __half* __restrict__ Kg,
                                         const __half* __restrict__ Vt,
                                         int j0, int tid) {
#pragma unroll
    for (int jj = 0; jj < 2; jj++) {
        int e = tid + 256 * jj;
        int n = e >> 3, kg = e & 7;
        uint32_t sw = (uint32_t)(n * 128 + ((kg * 16) ^ ((n & 7) << 4)));
        CPA16(smb + sko + sw, Kg + (size_t)(j0 + n) * 64 + kg * 8);
        CPA16(smb + svo + sw, Vt + (size_t)n * 1024 + j0 + kg * 8);
    }
}

__global__ __launch_bounds__(256, 2) void k_attn(const float* __restrict__ temp_ptr) {
    extern __shared__ char smch[];
    uint32_t smb = smem_u32(smch);
    const int head = blockIdx.y, i0 = blockIdx.x * 64;
    const int tid = threadIdx.x, lane = tid & 31, wid = tid >> 5;
    const int wm = wid & 3, h = wid >> 2;
    const __half* Qh0 = g_qh[0] + (size_t)head * 65536;
    const __half* Qh1 = g_qh[1] + (size_t)head * 65536;
    const __half* Kh0 = g_kh[0] + (size_t)head * 65536;
    const __half* Kh1 = g_kh[1] + (size_t)head * 65536;
    const __half* Vt0 = g_vth[0] + (size_t)head * 65536;
    const __half* Vt1 = g_vth[1] + (size_t)head * 65536;

    // Q (both branches) + KV(jt=0) -> group 0; KV(jt=1) -> group 1
#pragma unroll
    for (int j = 0; j < 4; j++) {
        int e = tid + 256 * j;
        int br = e >> 9, r = e & 511;
        int n = r >> 3, kg = r & 7;
        uint32_t dst = smb + (uint32_t)(br ? ASQ1 : 0u) + n * 128 + ((kg * 16) ^ ((n & 7) << 4));
        const __half* src = (br ? Qh1 : Qh0) + (size_t)(i0 + n) * 64 + kg * 8;
        CPA16(dst, src);
    }
    issue_kv(smb, ASK0, ASV0, Kh0, Vt0, 0, tid);
    issue_kv(smb, ASK1, ASV1, Kh1, Vt1, 0, tid);
    CPCOMMIT();
    issue_kv(smb, ASK0 + 8192u, ASV0 + 8192u, Kh0, Vt0, 64, tid);
    issue_kv(smb, ASK1 + 8192u, ASV1 + 8192u, Kh1, Vt1, 64, tid);
    CPCOMMIT();

    const int al = lane & 15, seg0 = lane >> 4;
    const int aswz = (al & 7) << 4;
    const uint32_t qA0 = smb + (wm * 16 + al) * 128;
    const uint32_t qA1 = smb + ASQ1 + (wm * 16 + al) * 128;
    const uint32_t eAr = smb + ASE + (wm * 16 + al) * 128;
    const int g = lane >> 2, tig = lane & 3;
    const int esw = (g & 7) << 4;
    char* erow1 = smch + ASE + (wm * 16 + g) * 128;
    char* erow2 = erow1 + 8 * 128;
    const int ebase = h * 64 + tig * 4;
    const int barid = wm + 1;

    float O0[4][4], O1[4][4];
#pragma unroll
    for (int n = 0; n < 4; n++)
#pragma unroll
        for (int c = 0; c < 4; c++) { O0[n][c] = 0.f; O1[n][c] = 0.f; }
    float z0[2] = {0.f, 0.f}, z1[2] = {0.f, 0.f}, dt[2] = {0.f, 0.f};

    for (int jt = 0; jt < 16; jt++) {
        if (jt < 15) { CPWAIT(1); } else { CPWAIT(0); }
        __syncthreads();
        uint32_t cb = (uint32_t)((jt & 1) * 8192);
        const uint32_t kB0 = smb + ASK0 + cb + (h * 32 + al) * 128;
        const uint32_t kB1 = smb + ASK1 + cb + (h * 32 + al) * 128;
        const uint32_t vB0 = smb + ASV0 + cb + (h * 32 + al) * 128;
        const uint32_t vB1 = smb + ASV1 + cb + (h * 32 + al) * 128;

        // ---------- QK branch 0 ----------
        float acc[4][4], e0r[4][4];
#pragma unroll
        for (int n = 0; n < 4; n++)
#pragma unroll
            for (int c = 0; c < 4; c++) acc[n][c] = 0.f;
#pragma unroll
        for (int kk = 0; kk < 4; kk++) {
            int soff = ((2 * kk + seg0) * 16) ^ aswz;
            uint32_t a0, a1, a2, a3;
            ldsm4(a0, a1, a2, a3, qA0 + soff);
#pragma unroll
            for (int j2 = 0; j2 < 2; j2++) {
                uint32_t b0, b1, b2, b3;
                ldsm4(b0, b1, b2, b3, kB0 + j2 * 16 * 128 + soff);
                mma16(acc[2 * j2],     a0, a1, a2, a3, b0, b2);
                mma16(acc[2 * j2 + 1], a0, a1, a2, a3, b1, b3);
            }
        }
        // exp0: regs + stage to E (fp16)
#pragma unroll
        for (int nt = 0; nt < 4; nt++) {
            float ea = fexp8(acc[nt][0]);
            float eb = fexp8(acc[nt][1]);
            float ec = fexp8(acc[nt][2]);
            float ed = fexp8(acc[nt][3]);
            e0r[nt][0] = ea; e0r[nt][1] = eb; e0r[nt][2] = ec; e0r[nt][3] = ed;
            z0[0] += ea + eb; z0[1] += ec + ed;
            int off = (ebase + nt * 16) ^ esw;
            *(uint32_t*)(erow1 + off) = pack_h2(ea, eb);
            *(uint32_t*)(erow2 + off) = pack_h2(ec, ed);
        }
        PAIRBAR(barid);
        // ---------- AV branch 0 (fp16) ----------
#pragma unroll
        for (int kk = 0; kk < 4; kk++) {
            int soff = ((2 * kk + seg0) * 16) ^ aswz;
            uint32_t a0, a1, a2, a3;
            ldsm4(a0, a1, a2, a3, eAr + soff);
#pragma unroll
            for (int j2 = 0; j2 < 2; j2++) {
                uint32_t b0, b1, b2, b3;
                ldsm4(b0, b1, b2, b3, vB0 + j2 * 16 * 128 + soff);
                mma16(O0[2 * j2],     a0, a1, a2, a3, b0, b2);
                mma16(O0[2 * j2 + 1], a0, a1, a2, a3, b1, b3);
            }
        }
        // ---------- QK branch 1 ----------
#pragma unroll
        for (int n = 0; n < 4; n++)
#pragma unroll
            for (int c = 0; c < 4; c++) acc[n][c] = 0.f;
#pragma unroll
        for (int kk = 0; kk < 4; kk++) {
            int soff = ((2 * kk + seg0) * 16) ^ aswz;
            uint32_t a0, a1, a2, a3;
            ldsm4(a0, a1, a2, a3, qA1 + soff);
#pragma unroll
            for (int j2 = 0; j2 < 2; j2++) {
                uint32_t b0, b1, b2, b3;
                ldsm4(b0, b1, b2, b3, kB1 + j2 * 16 * 128 + soff);
                mma16(acc[2 * j2],     a0, a1, a2, a3, b0, b2);
                mma16(acc[2 * j2 + 1], a0, a1, a2, a3, b1, b3);
            }
        }
        PAIRBAR(barid);          // pair finished AV0's E reads
        // exp1 + overlap dot (fp32 regs) + stage E1
#pragma unroll
        for (int nt = 0; nt < 4; nt++) {
            float ea = fexp8(acc[nt][0]);
            float eb = fexp8(acc[nt][1]);
            float ec = fexp8(acc[nt][2]);
            float ed = fexp8(acc[nt][3]);
            z1[0] += ea + eb; z1[1] += ec + ed;
            dt[0] += e0r[nt][0] * ea + e0r[nt][1] * eb;
            dt[1] += e0r[nt][2] * ec + e0r[nt][3] * ed;
            int off = (ebase + nt * 16) ^ esw;
            *(uint32_t*)(erow1 + off) = pack_h2(ea, eb);
            *(uint32_t*)(erow2 + off) = pack_h2(ec, ed);
        }
        PAIRBAR(barid);
        // ---------- AV branch 1 (fp16) ----------
#pragma unroll
        for (int kk = 0; kk < 4; kk++) {
            int soff = ((2 * kk + seg0) * 16) ^ aswz;
            uint32_t a0, a1, a2, a3;
            ldsm4(a0, a1, a2, a3, eAr + soff);
#pragma unroll
            for (int j2 = 0; j2 < 2; j2++) {
                uint32_t b0, b1, b2, b3;
                ldsm4(b0, b1, b2, b3, vB1 + j2 * 16 * 128 + soff);
                mma16(O1[2 * j2],     a0, a1, a2, a3, b0, b2);
                mma16(O1[2 * j2 + 1], a0, a1, a2, a3, b1, b3);
            }
        }
        __syncthreads();
        if (jt + 2 < 16) {
            int j0 = (jt + 2) * 64;
            issue_kv(smb, ASK0 + cb, ASV0 + cb, Kh0, Vt0, j0, tid);
            issue_kv(smb, ASK1 + cb, ASV1 + cb, Kh1, Vt1, j0, tid);
            CPCOMMIT();
        }
    }

    // ---------- epilogue ----------
#pragma unroll
    for (int hh2 = 0; hh2 < 2; hh2++) {
        z0[hh2] += __shfl_xor_sync(0xffffffffu, z0[hh2], 1); z0[hh2] += __shfl_xor_sync(0xffffffffu, z0[hh2], 2);
        z1[hh2] += __shfl_xor_sync(0xffffffffu, z1[hh2], 1); z1[hh2] += __shfl_xor_sync(0xffffffffu, z1[hh2], 2);
        dt[hh2] += __shfl_xor_sync(0xffffffffu, dt[hh2], 1); dt[hh2] += __shfl_xor_sync(0xffffffffu, dt[hh2], 2);
    }
    const int r1 = wm * 16 + g, r2 = r1 + 8;
    float* zz0 = (float*)(smch + ASE);   // E dead
    float* zz1 = zz0 + 64;
    float* dd  = zz0 + 128;
    if (h == 0 && tig == 0) {
        zz0[r1] = z0[0]; zz0[r2] = z0[1];
        zz1[r1] = z1[0]; zz1[r2] = z1[1];
        dd[r1]  = dt[0]; dd[r2]  = dt[1];
    }
    __syncthreads();
    if (h == 1 && tig == 0) {
        zz0[r1] += z0[0]; zz0[r2] += z0[1];
        zz1[r1] += z1[0]; zz1[r2] += z1[1];
        dd[r1]  += dt[0]; dd[r2]  += dt[1];
    }
    __syncthreads();
    float temp = fminf(fmaxf(*temp_ptr, 0.1f), 5.0f);
    float c0r[2], c1r[2];
#pragma unroll
    for (int hh2 = 0; hh2 < 2; hh2++) {
        int rr = hh2 ? r2 : r1;
        float a = zz0[rr], b = zz1[rr], d = dd[rr];
        // shift-invariant: dt/(z0*z1) = sum(e^{s0+s1}) / (sum e^{s0} * sum e^{s1}) * ... exact
        float overlap = d / (a * b) + 2.0f * EPSF + 1024.0f * EPSF * EPSF;
        float mask = 1.0f / (1.0f + __expf(overlap * temp));
        float f = mask / (mask + EPSF);
        c0r[hh2] = f / a;
        c1r[hh2] = f / b;
    }
    int bidx = head / 12, hd = head - bidx * 12;
    int n1 = i0 + r1;
    int cb2 = hd * 64 + h * 32 + 2 * tig;
    __half* p1a = g_aoh[0] + ((size_t)(bidx * 1024 + n1)) * 768 + cb2;
    __half* p2a = g_aoh[0] + ((size_t)(bidx * 1024 + n1 + 8)) * 768 + cb2;
    __half* p1b = g_aoh[1] + ((size_t)(bidx * 1024 + n1)) * 768 + cb2;
    __half* p2b = g_aoh[1] + ((size_t)(bidx * 1024 + n1 + 8)) * 768 + cb2;
#pragma unroll
    for (int nt = 0; nt < 4; nt++) {
        *(half2*)(p1a + nt * 8) = __floats2half2_rn(O0[nt][0] * c0r[0], O0[nt][1] * c0r[0]);
        *(half2*)(p2a + nt * 8) = __floats2half2_rn(O0[nt][2] * c0r[1], O0[nt][3] * c0r[1]);
        *(half2*)(p1b + nt * 8) = __floats2half2_rn(O1[nt][0] * c1r[0], O1[nt][1] * c1r[0]);
        *(half2*)(p2b + nt * 8) = __floats2half2_rn(O1[nt][2] * c1r[1], O1[nt][3] * c1r[1]);
    }
}

// ================= 0a) weight transpose pair -> fp16 ========================
__global__ __launch_bounds__(256) void k_tr2h(const float* __restrict__ in0,
                                              const float* __restrict__ in1,
                                              __half* __restrict__ out0,
                                              __half* __restrict__ out1, int R, int C) {
    __shared__ float t[32][33];
    const float* in = blockIdx.z ? in1 : in0;
    __half* out = blockIdx.z ? out1 : out0;
    int bx = blockIdx.x * 32, by = blockIdx.y * 32;
    int x = threadIdx.x & 31, y = threadIdx.x >> 5;
#pragma unroll
    for (int j = 0; j < 32; j += 8) t[y + j][x] = in[(size_t)(by + y + j) * C + bx + x];
    __syncthreads();
#pragma unroll
    for (int j = 0; j < 32; j += 8) out[(size_t)(bx + y + j) * R + by + x] = __float2half_rn(t[x][y + j]);
}

// ================= 0b) x -> fp16 ============================================
__global__ __launch_bounds__(256) void k_rxh(const float* __restrict__ x,
                                             __half* __restrict__ o) {
    int i = blockIdx.x * 256 + threadIdx.x;
    float4 v = ((const float4*)x)[i];
    ((half2*)o)[2 * i]     = __floats2half2_rn(v.x, v.y);
    ((half2*)o)[2 * i + 1] = __floats2half2_rn(v.z, v.w);
}

// ================= 5) LayerNorm over C=768 (both branches via y) ============
__device__ __forceinline__ float blk_reduce(float v, float* smr) {
    const unsigned full = 0xffffffffu;
#pragma unroll
    for (int o = 16; o > 0; o >>= 1) v += __shfl_xor_sync(full, v, o);
    int warp = threadIdx.x >> 5, lane = threadIdx.x & 31;
    if (lane == 0) smr[warp] = v;
    __syncthreads();
    if (warp == 0) {
        float x = (lane < 8) ? smr[lane] : 0.0f;
#pragma unroll
        for (int o = 4; o > 0; o >>= 1) x += __shfl_xor_sync(full, x, o);
        if (lane == 0) smr[0] = x;
    }
    __syncthreads();
    float r = smr[0];
    __syncthreads();
    return r;
}

__global__ __launch_bounds__(256) void k_ln(const float* __restrict__ g0,
                                            const float* __restrict__ b0,
                                            const float* __restrict__ g1,
                                            const float* __restrict__ b1,
                                            float* __restrict__ out) {
    __shared__ float smr[32];
    int br = blockIdx.y;
    int row = blockIdx.x;
    const float* gam = br ? g1 : g0;
    const float* bet = br ? b1 : b0;
    float* o = out + (size_t)br * Mm * Cc;
    const float* x = g_pr[br] + (size_t)row * Cc;
    int t = threadIdx.x;
    float v[3];
#pragma unroll
    for (int i = 0; i < 3; i++) v[i] = x[t + 256 * i];
    float s = v[0] + v[1] + v[2];
    s = blk_reduce(s, smr);
    float mu = s * (1.0f / (float)Cc);
    float ss = 0.0f;
#pragma unroll
    for (int i = 0; i < 3; i++) { float d = v[i] - mu; ss += d * d; }
    ss = blk_reduce(ss, smr);
    float inv = rsqrtf(ss * (1.0f / (float)Cc) + LNEPS);
#pragma unroll
    for (int i = 0; i < 3; i++) {
        int c = t + 256 * i;
        o[(size_t)row * Cc + c] = (v[i] - mu) * inv * gam[c] + bet[c];
    }
}

// ================= launch ==================================================
extern "C" void kernel_launch(void* const* d_in, const int* in_sizes, int n_in,
                              void* d_out, int out_size) {
    const float* x    = (const float*)d_in[0];
    const float* wq0  = (const float*)d_in[1];
    const float* wq1  = (const float*)d_in[2];
    const float* wp0  = (const float*)d_in[3];
    const float* bp0  = (const float*)d_in[4];
    const float* wp1  = (const float*)d_in[5];
    const float* bp1  = (const float*)d_in[6];
    const float* temp = (const float*)d_in[7];
    const float* g0   = (const float*)d_in[8];
    const float* b0   = (const float*)d_in[9];
    const float* g1   = (const float*)d_in[10];
    const float* b1   = (const float*)d_in[11];
    float* out = (float*)d_out;

    static __half* wt0 = nullptr; static __half* wt1 = nullptr;
    static __half* wpt0 = nullptr; static __half* wpt1 = nullptr;
    static __half* xr = nullptr;
    if (!wt0) {
        cudaGetSymbolAddress((void**)&wt0, g_wth);
        wt1 = wt0 + (size_t)3 * Cc * Cc;
        cudaGetSymbolAddress((void**)&wpt0, g_wpth);
        wpt1 = wpt0 + (size_t)Cc * Cc;
        cudaGetSymbolAddress((void**)&xr, g_xrh);
        cudaFuncSetAttribute(k_qkv_mma, cudaFuncAttributeMaxDynamicSharedMemorySize, 65536);
        cudaFuncSetAttribute(k_proj_mma, cudaFuncAttributeMaxDynamicSharedMemorySize, 65536);
        cudaFuncSetAttribute(k_attn, cudaFuncAttributeMaxDynamicSharedMemorySize, A_SMEM);
    }

    dim3 t256(256);
    k_tr2h<<<dim3(72, 24, 2), t256>>>(wq0, wq1, wt0, wt1, 768, 2304);
    k_tr2h<<<dim3(24, 24, 2), t256>>>(wp0, wp1, wpt0, wpt1, 768, 768);
    k_rxh<<<dim3(6144), t256>>>(x, xr);

    k_qkv_mma<<<dim3(18, 64, 2), t256, 65536>>>(xr, wt0, wt1);
    k_attn<<<dim3(16, BHh), t256, A_SMEM>>>(temp);
    k_proj_mma<<<dim3(6, 64, 2), t256, 65536>>>(wpt0, wpt1, bp0, bp1);
    k_ln<<<dim3(Mm, 2), t256>>>(g0, b0, g1, b1, out);
}

// round 15
// speedup vs baseline: 1.9031x; 1.0173x over previous
#include <cuda_runtime.h>
#include <cuda_fp16.h>
#include <cstdint>

#define Bb 8
#define Nn 1024
#define Cc 768
#define Hh 12
#define Dd 64
#define BHh 96
#define Mm 8192
#define SCALEF 0.125f
#define EPSF 1e-8f
#define LNEPS 1e-5f

// ---------------- scratch (device globals) ----------------
__device__ __half g_qh[2][(size_t)BHh*Nn*Dd];
__device__ __half g_kh[2][(size_t)BHh*Nn*Dd];
__device__ __half g_vth[2][(size_t)BHh*Dd*Nn];  // V^T fp16: [head][d][key]
__device__ __half g_aoh[2][(size_t)Mm*Cc];
__device__ float  g_pr[2][(size_t)Mm*Cc];
__device__ __half g_wth[2][(size_t)3*Cc*Cc];
__device__ __half g_wpth[2][(size_t)Cc*Cc];
__device__ __half g_xrh[(size_t)Mm*Cc];

// ---------------- helpers ----------------
__device__ __forceinline__ uint32_t smem_u32(const void* p) {
    uint32_t a;
    asm("{ .reg .u64 t; cvta.to.shared.u64 t, %1; cvt.u32.u64 %0, t; }" : "=r"(a) : "l"(p));
    return a;
}
// exp(clamp(acc*0.125, -20, 20) - 8), FMA/ALU pipes only. Range [e^-28, e^12].
__device__ __forceinline__ float fexp8(float acc) {
    const float L2E = 1.4426950408889634f;
    const float C1 = 0.125f * L2E;
    float y = fmaf(acc, C1, -8.0f * L2E);
    y = fmaxf(y, -28.0f * L2E);
    y = fminf(y, 12.0f * L2E);
    float t = y + 12582912.0f;
    int ib = __float_as_int(t) - 0x4B400000;
    float f = y - (t - 12582912.0f);
    float p = 1.3333558146e-3f;
    p = fmaf(p, f, 9.6181291076e-3f);
    p = fmaf(p, f, 5.5504108664e-2f);
    p = fmaf(p, f, 2.4022650696e-1f);
    p = fmaf(p, f, 6.9314718056e-1f);
    p = fmaf(p, f, 1.0f);
    return __int_as_float(__float_as_int(p) + (ib << 23));
}
__device__ __forceinline__ uint32_t pack_h2(float lo, float hi) {
    half2 h = __floats2half2_rn(fminf(lo, 60000.f), fminf(hi, 60000.f));
    return *(uint32_t*)&h;
}
__device__ __forceinline__ void ldsm4(uint32_t& d0, uint32_t& d1, uint32_t& d2, uint32_t& d3, uint32_t a) {
    asm volatile("ldmatrix.sync.aligned.m8n8.x4.shared.b16 {%0,%1,%2,%3}, [%4];"
                 : "=r"(d0), "=r"(d1), "=r"(d2), "=r"(d3) : "r"(a));
}
__device__ __forceinline__ void mma16(float* c, uint32_t a0, uint32_t a1, uint32_t a2, uint32_t a3,
                                      uint32_t b0, uint32_t b1) {
    asm volatile("mma.sync.aligned.m16n8k16.row.col.f32.f16.f16.f32 "
                 "{%0,%1,%2,%3},{%4,%5,%6,%7},{%8,%9},{%0,%1,%2,%3};"
                 : "+f"(c[0]), "+f"(c[1]), "+f"(c[2]), "+f"(c[3])
                 : "r"(a0), "r"(a1), "r"(a2), "r"(a3), "r"(b0), "r"(b1));
}
#define CPA16(d, s) asm volatile("cp.async.cg.shared.global [%0], [%1], 16;" :: "r"(d), "l"(s))
#define CPCOMMIT()  asm volatile("cp.async.commit_group;" ::: "memory")
#define CPWAIT(n)   asm volatile("cp.async.wait_group %0;" :: "n"(n) : "memory")

// ====== shared fp16-mma mainloop: C[128x128] = A * B^T, K=768, k-chunk 64 ===
__device__ __forceinline__ void gemm_h768(const __half* __restrict__ A,
                                          const __half* __restrict__ Bt,
                                          int by, int bx, uint32_t smb,
                                          float acc[2][8][4]) {
    const int tid = threadIdx.x, lane = tid & 31, wid = tid >> 5;
    const int wm = wid >> 1, wn = wid & 1;
    uint32_t dA[4], dB[4];
    const __half* sA[4];
    const __half* sB[4];
#pragma unroll
    for (int j = 0; j < 4; j++) {
        int e = tid + 256 * j;
        int m = e >> 3, kg = e & 7;
        uint32_t sw = (uint32_t)(m * 128 + ((kg * 16) ^ ((m & 7) << 4)));
        dA[j] = smb + sw;
        dB[j] = smb + 32768u + sw;
        sA[j] = A + (size_t)(by + m) * 768 + kg * 8;
        sB[j] = Bt + (size_t)(bx + m) * 768 + kg * 8;
    }
#pragma unroll
    for (int i = 0; i < 2; i++)
#pragma unroll
        for (int n = 0; n < 8; n++)
#pragma unroll
            for (int c = 0; c < 4; c++) acc[i][n][c] = 0.0f;

#pragma unroll
    for (int j = 0; j < 4; j++) { CPA16(dA[j], sA[j]); CPA16(dB[j], sB[j]); }
    CPCOMMIT();

    const int al = lane & 15, seg0 = lane >> 4;
    const int aswz = (al & 7) << 4;

    for (int it = 0; it < 12; ++it) {
        if (it + 1 < 12) {
            int kc = (it + 1) * 64;
            uint32_t ob = ((it + 1) & 1) ? 16384u : 0u;
#pragma unroll
            for (int j = 0; j < 4; j++) { CPA16(dA[j] + ob, sA[j] + kc); CPA16(dB[j] + ob, sB[j] + kc); }
        }
        CPCOMMIT();
        CPWAIT(1);
        __syncthreads();
        uint32_t Ab = smb + ((it & 1) ? 16384u : 0u);
        uint32_t Bbf = smb + 32768u + ((it & 1) ? 16384u : 0u);
#pragma unroll
        for (int kk = 0; kk < 4; kk++) {
            int soff = (2 * kk + seg0) * 16;
            uint32_t a[2][4];
#pragma unroll
            for (int mt = 0; mt < 2; mt++) {
                int r = wm * 32 + mt * 16 + al;
                ldsm4(a[mt][0], a[mt][1], a[mt][2], a[mt][3],
                      Ab + r * 128 + (soff ^ aswz));
            }
#pragma unroll
            for (int j2 = 0; j2 < 4; j2++) {
                int r = wn * 64 + j2 * 16 + al;
                uint32_t b0, b1, b2, b3;
                ldsm4(b0, b1, b2, b3, Bbf + r * 128 + (soff ^ aswz));
#pragma unroll
                for (int mt = 0; mt < 2; mt++) {
                    mma16(acc[mt][2 * j2],     a[mt][0], a[mt][1], a[mt][2], a[mt][3], b0, b2);
                    mma16(acc[mt][2 * j2 + 1], a[mt][0], a[mt][1], a[mt][2], a[mt][3], b1, b3);
                }
            }
        }
        __syncthreads();
    }
}

// ================= 1) qkv GEMM (fp16) + scatter =============================
__global__ __launch_bounds__(256, 2) void k_qkv_mma(const __half* __restrict__ X,
                                                    const __half* __restrict__ Wt0,
                                                    const __half* __restrict__ Wt1) {
    extern __shared__ char smch[];
    uint32_t smb = smem_u32(smch);
    int br = blockIdx.z;
    const __half* Wt = br ? Wt1 : Wt0;
    int bx = blockIdx.x * 128, by = blockIdx.y * 128;
    float acc[2][8][4];
    gemm_h768(X, Wt, by, bx, smb, acc);

    int lane = threadIdx.x & 31, wid = threadIdx.x >> 5;
    int wm = wid >> 1, wn = wid & 1, g = lane >> 2, tig = lane & 3;
    int colbase = bx + wn * 64;
    int seg = colbase >> 6;
    int three = seg / 12, hseg = seg - three * 12;
    if (three == 2) {
#pragma unroll
        for (int mt = 0; mt < 2; mt++) {
            int m1 = by + wm * 32 + mt * 16 + g;
            int b1 = m1 >> 10, n1 = m1 & 1023;
            __half* vt = g_vth[br] + ((size_t)(b1 * 12 + hseg)) * 65536;
#pragma unroll
            for (int nt = 0; nt < 8; nt++) {
                int d0 = nt * 8 + 2 * tig;
                vt[(size_t)d0 * 1024 + n1]           = __float2half_rn(acc[mt][nt][0]);
                vt[(size_t)(d0 + 1) * 1024 + n1]     = __float2half_rn(acc[mt][nt][1]);
                vt[(size_t)d0 * 1024 + n1 + 8]       = __float2half_rn(acc[mt][nt][2]);
                vt[(size_t)(d0 + 1) * 1024 + n1 + 8] = __float2half_rn(acc[mt][nt][3]);
            }
        }
    } else {
        __half* base3 = (three == 0) ? g_qh[br] : g_kh[br];
#pragma unroll
        for (int mt = 0; mt < 2; mt++) {
            int m1 = by + wm * 32 + mt * 16 + g;
            int b1 = m1 >> 10, n1 = m1 & 1023;
            __half* p1 = base3 + (((size_t)(b1 * 12 + hseg)) * 1024 + n1) * 64 + 2 * tig;
            __half* p2 = p1 + (size_t)8 * 64;
#pragma unroll
            for (int nt = 0; nt < 8; nt++) {
                *(half2*)(p1 + nt * 8) = __floats2half2_rn(acc[mt][nt][0], acc[mt][nt][1]);
                *(half2*)(p2 + nt * 8) = __floats2half2_rn(acc[mt][nt][2], acc[mt][nt][3]);
            }
        }
    }
}

// ================= 2) proj GEMM (fp16) + bias ================================
__global__ __launch_bounds__(256, 2) void k_proj_mma(const __half* __restrict__ Wt0,
                                                     const __half* __restrict__ Wt1,
                                                     const float* __restrict__ bias0,
                                                     const float* __restrict__ bias1) {
    extern __shared__ char smch[];
    uint32_t smb = smem_u32(smch);
    int br = blockIdx.z;
    const __half* Wt = br ? Wt1 : Wt0;
    const float* bias = br ? bias1 : bias0;
    int bx = blockIdx.x * 128, by = blockIdx.y * 128;
    float acc[2][8][4];
    gemm_h768(g_aoh[br], Wt, by, bx, smb, acc);

    int lane = threadIdx.x & 31, wid = threadIdx.x >> 5;
    int wm = wid >> 1, wn = wid & 1, g = lane >> 2, tig = lane & 3;
    int colbase = bx + wn * 64;
#pragma unroll
    for (int mt = 0; mt < 2; mt++) {
        int m1 = by + wm * 32 + mt * 16 + g;
        float* p1 = g_pr[br] + (size_t)m1 * 768 + colbase + 2 * tig;
        float* p2 = p1 + (size_t)8 * 768;
#pragma unroll
        for (int nt = 0; nt < 8; nt++) {
            float2 bv = *(const float2*)(bias + colbase + nt * 8 + 2 * tig);
            *(float2*)(p1 + nt * 8) = make_float2(acc[mt][nt][0] + bv.x, acc[mt][nt][1] + bv.y);
            *(float2*)(p2 + nt * 8) = make_float2(acc[mt][nt][2] + bv.x, acc[mt][nt][3] + bv.y);
        }
    }
}

// ====== 3) FUSED attention: E stays in registers (C->A identity), k-split AV =
// Warp (wm,h): QK for 16 rows x keys [h*32, h*32+32); AV partial O[16x64] over
// those keys; pair {h=0,1} sums O once in the epilogue. No per-jt pair barriers.
// smem: Q0 @0 (8K) Q1 @8192 | K0[2] @16384 K1[2] @32768 | V0[2] @49152 V1[2] @65536
#define ASQ1 8192u
#define ASK0 16384u
#define ASK1 32768u
#define ASV0 49152u
#define ASV1 65536u
#define A_SMEM 81920

__device__ __forceinline__ void issue_kv(uint32_t smb, uint32_t sko, uint32_t svo,
                                         const __half* __restrict__ Kg,
                                         const __half* __restrict__ Vt,
                                         int j0, int tid) {
#pragma unroll
    for (int jj = 0; jj < 2; jj++) {
        int e = tid + 256 * jj;
        int n = e >> 3, kg = e & 7;
        uint32_t sw = (uint32_t)(n * 128 + ((kg * 16) ^ ((n & 7) << 4)));
        CPA16(smb + sko + sw, Kg + (size_t)(j0 + n) * 64 + kg * 8);
        CPA16(smb + svo + sw, Vt + (size_t)n * 1024 + j0 + kg * 8);
    }
}

__global__ __launch_bounds__(256, 2) void k_attn(const float* __restrict__ temp_ptr) {
    extern __shared__ char smch[];
    uint32_t smb = smem_u32(smch);
    const int head = blockIdx.y, i0 = blockIdx.x * 64;
    const int tid = threadIdx.x, lane = tid & 31, wid = tid >> 5;
    const int wm = wid & 3, h = wid >> 2;
    const __half* Qh0 = g_qh[0] + (size_t)head * 65536;
    const __half* Qh1 = g_qh[1] + (size_t)head * 65536;
    const __half* Kh0 = g_kh[0] + (size_t)head * 65536;
    const __half* Kh1 = g_kh[1] + (size_t)head * 65536;
    const __half* Vt0 = g_vth[0] + (size_t)head * 65536;
    const __half* Vt1 = g_vth[1] + (size_t)head * 65536;

#pragma unroll
    for (int j = 0; j < 4; j++) {
        int e = tid + 256 * j;
        int br = e >> 9, r = e & 511;
        int n = r >> 3, kg = r & 7;
        uint32_t dst = smb + (uint32_t)(br ? ASQ1 : 0u) + n * 128 + ((kg * 16) ^ ((n & 7) << 4));
        const __half* src = (br ? Qh1 : Qh0) + (size_t)(i0 + n) * 64 + kg * 8;
        CPA16(dst, src);
    }
    issue_kv(smb, ASK0, ASV0, Kh0, Vt0, 0, tid);
    issue_kv(smb, ASK1, ASV1, Kh1, Vt1, 0, tid);
    CPCOMMIT();
    issue_kv(smb, ASK0 + 8192u, ASV0 + 8192u, Kh0, Vt0, 64, tid);
    issue_kv(smb, ASK1 + 8192u, ASV1 + 8192u, Kh1, Vt1, 64, tid);
    CPCOMMIT();

    const int al = lane & 15, seg0 = lane >> 4;
    const int aswz = (al & 7) << 4;
    const uint32_t qA0 = smb + (wm * 16 + al) * 128;
    const uint32_t qA1 = smb + ASQ1 + (wm * 16 + al) * 128;
    const int g = lane >> 2, tig = lane & 3;

    float O0[8][4], O1[8][4];
#pragma unroll
    for (int n = 0; n < 8; n++)
#pragma unroll
        for (int c = 0; c < 4; c++) { O0[n][c] = 0.f; O1[n][c] = 0.f; }
    float z0[2] = {0.f, 0.f}, z1[2] = {0.f, 0.f}, dt[2] = {0.f, 0.f};

    for (int jt = 0; jt < 16; jt++) {
        if (jt < 15) { CPWAIT(1); } else { CPWAIT(0); }
        __syncthreads();
        uint32_t cb = (uint32_t)((jt & 1) * 8192);
        const uint32_t kB0 = smb + ASK0 + cb + (h * 32 + al) * 128;
        const uint32_t kB1 = smb + ASK1 + cb + (h * 32 + al) * 128;
        const uint32_t vB0 = smb + ASV0 + cb;
        const uint32_t vB1 = smb + ASV1 + cb;

        // ---------- QK branch 0 ----------
        float acc[4][4];
#pragma unroll
        for (int n = 0; n < 4; n++)
#pragma unroll
            for (int c = 0; c < 4; c++) acc[n][c] = 0.f;
#pragma unroll
        for (int kk = 0; kk < 4; kk++) {
            int soff = ((2 * kk + seg0) * 16) ^ aswz;
            uint32_t a0, a1, a2, a3;
            ldsm4(a0, a1, a2, a3, qA0 + soff);
#pragma unroll
            for (int j2 = 0; j2 < 2; j2++) {
                uint32_t b0, b1, b2, b3;
                ldsm4(b0, b1, b2, b3, kB0 + j2 * 16 * 128 + soff);
                mma16(acc[2 * j2],     a0, a1, a2, a3, b0, b2);
                mma16(acc[2 * j2 + 1], a0, a1, a2, a3, b1, b3);
            }
        }
        // exp0 -> register A fragments (C->A layout identity)
        uint32_t ea0[2][4];
#pragma unroll
        for (int u = 0; u < 2; u++) {
            float e00 = fexp8(acc[2 * u][0]),     e01 = fexp8(acc[2 * u][1]);
            float e02 = fexp8(acc[2 * u][2]),     e03 = fexp8(acc[2 * u][3]);
            float e10 = fexp8(acc[2 * u + 1][0]), e11 = fexp8(acc[2 * u + 1][1]);
            float e12 = fexp8(acc[2 * u + 1][2]), e13 = fexp8(acc[2 * u + 1][3]);
            z0[0] += e00 + e01 + e10 + e11;
            z0[1] += e02 + e03 + e12 + e13;
            ea0[u][0] = pack_h2(e00, e01);
            ea0[u][1] = pack_h2(e02, e03);
            ea0[u][2] = pack_h2(e10, e11);
            ea0[u][3] = pack_h2(e12, e13);
        }
        // ---------- AV branch 0 (partial over this warp's 32 keys) ----------
#pragma unroll
        for (int u = 0; u < 2; u++) {
            int koff = h * 64 + u * 32;
#pragma unroll
            for (int j2 = 0; j2 < 4; j2++) {
                uint32_t b0, b1, b2, b3;
                ldsm4(b0, b1, b2, b3, vB0 + (j2 * 16 + al) * 128 + (((koff + seg0 * 16)) ^ aswz));
                mma16(O0[2 * j2],     ea0[u][0], ea0[u][1], ea0[u][2], ea0[u][3], b0, b2);
                mma16(O0[2 * j2 + 1], ea0[u][0], ea0[u][1], ea0[u][2], ea0[u][3], b1, b3);
            }
        }
        // ---------- QK branch 1 ----------
#pragma unroll
        for (int n = 0; n < 4; n++)
#pragma unroll
            for (int c = 0; c < 4; c++) acc[n][c] = 0.f;
#pragma unroll
        for (int kk = 0; kk < 4; kk++) {
            int soff = ((2 * kk + seg0) * 16) ^ aswz;
            uint32_t a0, a1, a2, a3;
            ldsm4(a0, a1, a2, a3, qA1 + soff);
#pragma unroll
            for (int j2 = 0; j2 < 2; j2++) {
                uint32_t b0, b1, b2, b3;
                ldsm4(b0, b1, b2, b3, kB1 + j2 * 16 * 128 + soff);
                mma16(acc[2 * j2],     a0, a1, a2, a3, b0, b2);
                mma16(acc[2 * j2 + 1], a0, a1, a2, a3, b1, b3);
            }
        }
        // exp1 + overlap dot (unpack ea0 -> fp32) + A fragments
        uint32_t ea1[2][4];
#pragma unroll
        for (int u = 0; u < 2; u++) {
            float e00 = fexp8(acc[2 * u][0]),     e01 = fexp8(acc[2 * u][1]);
            float e02 = fexp8(acc[2 * u][2]),     e03 = fexp8(acc[2 * u][3]);
            float e10 = fexp8(acc[2 * u + 1][0]), e11 = fexp8(acc[2 * u + 1][1]);
            float e12 = fexp8(acc[2 * u + 1][2]), e13 = fexp8(acc[2 * u + 1][3]);
            z1[0] += e00 + e01 + e10 + e11;
            z1[1] += e02 + e03 + e12 + e13;
            float2 q0 = __half22float2(*(half2*)&ea0[u][0]);
            float2 q1 = __half22float2(*(half2*)&ea0[u][1]);
            float2 q2 = __half22float2(*(half2*)&ea0[u][2]);
            float2 q3 = __half22float2(*(half2*)&ea0[u][3]);
            dt[0] += q0.x * e00 + q0.y * e01 + q2.x * e10 + q2.y * e11;
            dt[1] += q1.x * e02 + q1.y * e03 + q3.x * e12 + q3.y * e13;
            ea1[u][0] = pack_h2(e00, e01);
            ea1[u][1] = pack_h2(e02, e03);
            ea1[u][2] = pack_h2(e10, e11);
            ea1[u][3] = pack_h2(e12, e13);
        }
        // ---------- AV branch 1 ----------
#pragma unroll
        for (int u = 0; u < 2; u++) {
            int koff = h * 64 + u * 32;
#pragma unroll
            for (int j2 = 0; j2 < 4; j2++) {
                uint32_t b0, b1, b2, b3;
                ldsm4(b0, b1, b2, b3, vB1 + (j2 * 16 + al) * 128 + (((koff + seg0 * 16)) ^ aswz));
                mma16(O1[2 * j2],     ea1[u][0], ea1[u][1], ea1[u][2], ea1[u][3], b0, b2);
                mma16(O1[2 * j2 + 1], ea1[u][0], ea1[u][1], ea1[u][2], ea1[u][3], b1, b3);
            }
        }
        __syncthreads();
        if (jt + 2 < 16) {
            int j0 = (jt + 2) * 64;
            issue_kv(smb, ASK0 + cb, ASV0 + cb, Kh0, Vt0, j0, tid);
            issue_kv(smb, ASK1 + cb, ASV1 + cb, Kh1, Vt1, j0, tid);
            CPCOMMIT();
        }
    }

    // ---------- epilogue: quad-reduce, pair-combine z/dt + O, store ----------
#pragma unroll
    for (int hh2 = 0; hh2 < 2; hh2++) {
        z0[hh2] += __shfl_xor_sync(0xffffffffu, z0[hh2], 1); z0[hh2] += __shfl_xor_sync(0xffffffffu, z0[hh2], 2);
        z1[hh2] += __shfl_xor_sync(0xffffffffu, z1[hh2], 1); z1[hh2] += __shfl_xor_sync(0xffffffffu, z1[hh2], 2);
        dt[hh2] += __shfl_xor_sync(0xffffffffu, dt[hh2], 1); dt[hh2] += __shfl_xor_sync(0xffffffffu, dt[hh2], 2);
    }
    const int r1 = wm * 16 + g, r2 = r1 + 8;
    float* stage = (float*)smch;                 // 16KB O staging (Q dead)
    float* zz0 = (float*)(smch + 16384);         // K area dead
    float* zz1 = zz0 + 64;
    float* dd  = zz0 + 128;
    if (h == 0 && tig == 0) {
        zz0[r1] = z0[0]; zz0[r2] = z0[1];
        zz1[r1] = z1[0]; zz1[r2] = z1[1];
        dd[r1]  = dt[0]; dd[r2]  = dt[1];
    }
    float* sp = stage + wm * 1024;
    if (h == 0) {
#pragma unroll
        for (int nt = 0; nt < 8; nt++) {
            int dcol = nt * 8 + 2 * tig;
            sp[g * 64 + dcol]           = O0[nt][0];
            sp[g * 64 + dcol + 1]       = O0[nt][1];
            sp[(g + 8) * 64 + dcol]     = O0[nt][2];
            sp[(g + 8) * 64 + dcol + 1] = O0[nt][3];
        }
    }
    __syncthreads();
    float temp = fminf(fmaxf(*temp_ptr, 0.1f), 5.0f);
    int bidx = head / 12, hd = head - bidx * 12;
    int n1 = i0 + r1;
    float c0r[2], c1r[2];
    if (h == 1) {
#pragma unroll
        for (int hh2 = 0; hh2 < 2; hh2++) {
            int rr = hh2 ? r2 : r1;
            float a = zz0[rr] + z0[hh2];
            float b = zz1[rr] + z1[hh2];
            float d = dd[rr] + dt[hh2];
            float overlap = d / (a * b) + 2.0f * EPSF + 1024.0f * EPSF * EPSF;
            float mask = 1.0f / (1.0f + __expf(overlap * temp));
            float f = mask / (mask + EPSF);
            c0r[hh2] = f / a;
            c1r[hh2] = f / b;
        }
        __half* p1a = g_aoh[0] + ((size_t)(bidx * 1024 + n1)) * 768 + hd * 64 + 2 * tig;
        __half* p2a = g_aoh[0] + ((size_t)(bidx * 1024 + n1 + 8)) * 768 + hd * 64 + 2 * tig;
#pragma unroll
        for (int nt = 0; nt < 8; nt++) {
            int dcol = nt * 8 + 2 * tig;
            float o0 = O0[nt][0] + sp[g * 64 + dcol];
            float o1 = O0[nt][1] + sp[g * 64 + dcol + 1];
            float o2 = O0[nt][2] + sp[(g + 8) * 64 + dcol];
            float o3 = O0[nt][3] + sp[(g + 8) * 64 + dcol + 1];
            *(half2*)(p1a + nt * 8) = __floats2half2_rn(o0 * c0r[0], o1 * c0r[0]);
            *(half2*)(p2a + nt * 8) = __floats2half2_rn(o2 * c0r[1], o3 * c0r[1]);
        }
    }
    __syncthreads();
    if (h == 0) {
#pragma unroll
        for (int nt = 0; nt < 8; nt++) {
            int dcol = nt * 8 + 2 * tig;
            sp[g * 64 + dcol]           = O1[nt][0];
            sp[g * 64 + dcol + 1]       = O1[nt][1];
            sp[(g + 8) * 64 + dcol]     = O1[nt][2];
            sp[(g + 8) * 64 + dcol + 1] = O1[nt][3];
        }
    }
    __syncthreads();
    if (h == 1) {
        __half* p1b = g_aoh[1] + ((size_t)(bidx * 1024 + n1)) * 768 + hd * 64 + 2 * tig;
        __half* p2b = g_aoh[1] + ((size_t)(bidx * 1024 + n1 + 8)) * 768 + hd * 64 + 2 * tig;
#pragma unroll
        for (int nt = 0; nt < 8; nt++) {
            int dcol = nt * 8 + 2 * tig;
            float o0 = O1[nt][0] + sp[g * 64 + dcol];
            float o1 = O1[nt][1] + sp[g * 64 + dcol + 1];
            float o2 = O1[nt][2] + sp[(g + 8) * 64 + dcol];
            float o3 = O1[nt][3] + sp[(g + 8) * 64 + dcol + 1];
            *(half2*)(p1b + nt * 8) = __floats2half2_rn(o0 * c1r[0], o1 * c1r[0]);
            *(half2*)(p2b + nt * 8) = __floats2half2_rn(o2 * c1r[1], o3 * c1r[1]);
        }
    }
}

// ================= 0a) weight transpose pair -> fp16 ========================
__global__ __launch_bounds__(256) void k_tr2h(const float* __restrict__ in0,
                                              const float* __restrict__ in1,
                                              __half* __restrict__ out0,
                                              __half* __restrict__ out1, int R, int C) {
    __shared__ float t[32][33];
    const float* in = blockIdx.z ? in1 : in0;
    __half* out = blockIdx.z ? out1 : out0;
    int bx = blockIdx.x * 32, by = blockIdx.y * 32;
    int x = threadIdx.x & 31, y = threadIdx.x >> 5;
#pragma unroll
    for (int j = 0; j < 32; j += 8) t[y + j][x] = in[(size_t)(by + y + j) * C + bx + x];
    __syncthreads();
#pragma unroll
    for (int j = 0; j < 32; j += 8) out[(size_t)(bx + y + j) * R + by + x] = __float2half_rn(t[x][y + j]);
}

// ================= 0b) x -> fp16 ============================================
__global__ __launch_bounds__(256) void k_rxh(const float* __restrict__ x,
                                             __half* __restrict__ o) {
    int i = blockIdx.x * 256 + threadIdx.x;
    float4 v = ((const float4*)x)[i];
    ((half2*)o)[2 * i]     = __floats2half2_rn(v.x, v.y);
    ((half2*)o)[2 * i + 1] = __floats2half2_rn(v.z, v.w);
}

// ================= 5) LayerNorm over C=768 (both branches via y) ============
__device__ __forceinline__ float blk_reduce(float v, float* smr) {
    const unsigned full = 0xffffffffu;
#pragma unroll
    for (int o = 16; o > 0; o >>= 1) v += __shfl_xor_sync(full, v, o);
    int warp = threadIdx.x >> 5, lane = threadIdx.x & 31;
    if (lane == 0) smr[warp] = v;
    __syncthreads();
    if (warp == 0) {
        float x = (lane < 8) ? smr[lane] : 0.0f;
#pragma unroll
        for (int o = 4; o > 0; o >>= 1) x += __shfl_xor_sync(full, x, o);
        if (lane == 0) smr[0] = x;
    }
    __syncthreads();
    float r = smr[0];
    __syncthreads();
    return r;
}

__global__ __launch_bounds__(256) void k_ln(const float* __restrict__ g0,
                                            const float* __restrict__ b0,
                                            const float* __restrict__ g1,
                                            const float* __restrict__ b1,
                                            float* __restrict__ out) {
    __shared__ float smr[32];
    int br = blockIdx.y;
    int row = blockIdx.x;
    const float* gam = br ? g1 : g0;
    const float* bet = br ? b1 : b0;
    float* o = out + (size_t)br * Mm * Cc;
    const float* x = g_pr[br] + (size_t)row * Cc;
    int t = threadIdx.x;
    float v[3];
#pragma unroll
    for (int i = 0; i < 3; i++) v[i] = x[t + 256 * i];
    float s = v[0] + v[1] + v[2];
    s = blk_reduce(s, smr);
    float mu = s * (1.0f / (float)Cc);
    float ss = 0.0f;
#pragma unroll
    for (int i = 0; i < 3; i++) { float d = v[i] - mu; ss += d * d; }
    ss = blk_reduce(ss, smr);
    float inv = rsqrtf(ss * (1.0f / (float)Cc) + LNEPS);
#pragma unroll
    for (int i = 0; i < 3; i++) {
        int c = t + 256 * i;
        o[(size_t)row * Cc + c] = (v[i] - mu) * inv * gam[c] + bet[c];
    }
}

// ================= launch ==================================================
extern "C" void kernel_launch(void* const* d_in, const int* in_sizes, int n_in,
                              void* d_out, int out_size) {
    const float* x    = (const float*)d_in[0];
    const float* wq0  = (const float*)d_in[1];
    const float* wq1  = (const float*)d_in[2];
    const float* wp0  = (const float*)d_in[3];
    const float* bp0  = (const float*)d_in[4];
    const float* wp1  = (const float*)d_in[5];
    const float* bp1  = (const float*)d_in[6];
    const float* temp = (const float*)d_in[7];
    const float* g0   = (const float*)d_in[8];
    const float* b0   = (const float*)d_in[9];
    const float* g1   = (const float*)d_in[10];
    const float* b1   = (const float*)d_in[11];
    float* out = (float*)d_out;

    static __half* wt0 = nullptr; static __half* wt1 = nullptr;
    static __half* wpt0 = nullptr; static __half* wpt1 = nullptr;
    static __half* xr = nullptr;
    if (!wt0) {
        cudaGetSymbolAddress((void**)&wt0, g_wth);
        wt1 = wt0 + (size_t)3 * Cc * Cc;
        cudaGetSymbolAddress((void**)&wpt0, g_wpth);
        wpt1 = wpt0 + (size_t)Cc * Cc;
        cudaGetSymbolAddress((void**)&xr, g_xrh);
        cudaFuncSetAttribute(k_qkv_mma, cudaFuncAttributeMaxDynamicSharedMemorySize, 65536);
        cudaFuncSetAttribute(k_proj_mma, cudaFuncAttributeMaxDynamicSharedMemorySize, 65536);
        cudaFuncSetAttribute(k_attn, cudaFuncAttributeMaxDynamicSharedMemorySize, A_SMEM);
    }

    dim3 t256(256);
    k_tr2h<<<dim3(72, 24, 2), t256>>>(wq0, wq1, wt0, wt1, 768, 2304);
    k_tr2h<<<dim3(24, 24, 2), t256>>>(wp0, wp1, wpt0, wpt1, 768, 768);
    k_rxh<<<dim3(6144), t256>>>(x, xr);

    k_qkv_mma<<<dim3(18, 64, 2), t256, 65536>>>(xr, wt0, wt1);
    k_attn<<<dim3(16, BHh), t256, A_SMEM>>>(temp);
    k_proj_mma<<<dim3(6, 64, 2), t256, 65536>>>(wpt0, wpt1, bp0, bp1);
    k_ln<<<dim3(Mm, 2), t256>>>(g0, b0, g1, b1, out);
}